// round 1
// baseline (speedup 1.0000x reference)
#include <cuda_runtime.h>
#include <math.h>

#define N_TOK 4096
#define D     320
#define HEADS 8
#define DH    40
#define CTX_N 77
#define CTX_D 768
#define FFI   1280
#define GROUPS 32

// ---------------- scratch (__device__ globals; no allocations allowed) ----------------
__device__ float g_h   [N_TOK * D];
__device__ float g_h2  [N_TOK * D];
__device__ float g_ln  [N_TOK * D];
__device__ float g_q   [N_TOK * D];
__device__ float g_k   [N_TOK * D];
__device__ float g_v   [N_TOK * D];
__device__ float g_attn[N_TOK * D];
__device__ float g_ffh [N_TOK * 2 * FFI];
__device__ float g_ffg [N_TOK * FFI];
__device__ float g_kc  [CTX_N * D];
__device__ float g_vc  [CTX_N * D];
__device__ float g_wT  [D * D];
__device__ float g_mu  [GROUPS];
__device__ float g_rs  [GROUPS];

// ---------------- GroupNorm stats: one block per group (contiguous 10*4096 floats) ----
__global__ void gn_stats_kernel(const float* __restrict__ x) {
    int g = blockIdx.x;
    const float* p = x + g * (10 * N_TOK);
    float s = 0.f, s2 = 0.f;
    for (int i = threadIdx.x; i < 10 * N_TOK; i += 256) {
        float v = p[i];
        s += v; s2 += v * v;
    }
    __shared__ float sh1[8], sh2[8];
    int lane = threadIdx.x & 31, w = threadIdx.x >> 5;
    #pragma unroll
    for (int o = 16; o; o >>= 1) {
        s  += __shfl_xor_sync(0xffffffffu, s,  o);
        s2 += __shfl_xor_sync(0xffffffffu, s2, o);
    }
    if (lane == 0) { sh1[w] = s; sh2[w] = s2; }
    __syncthreads();
    if (threadIdx.x == 0) {
        s = 0.f; s2 = 0.f;
        #pragma unroll
        for (int i = 0; i < 8; i++) { s += sh1[i]; s2 += sh2[i]; }
        float m   = s  * (1.f / (10 * N_TOK));
        float var = s2 * (1.f / (10 * N_TOK)) - m * m;
        g_mu[g] = m;
        g_rs[g] = rsqrtf(var + 1e-6f);
    }
}

// ---------------- GN apply + transpose [C, P] -> [P, C] (token-major) ----------------
__global__ void gn_apply_t_kernel(const float* __restrict__ x,
                                  const float* __restrict__ w,
                                  const float* __restrict__ b,
                                  float* __restrict__ out) {
    __shared__ float t[32][33];
    int p0 = blockIdx.x * 32, c0 = blockIdx.y * 32;
    int c = c0 + threadIdx.y, p = p0 + threadIdx.x;
    int g = c / 10;
    float v = (x[c * N_TOK + p] - g_mu[g]) * g_rs[g] * w[c] + b[c];
    t[threadIdx.y][threadIdx.x] = v;
    __syncthreads();
    out[(p0 + threadIdx.y) * D + c0 + threadIdx.x] = t[threadIdx.x][threadIdx.y];
}

// ---------------- LayerNorm over rows of 320, one 128-thread block per row -----------
__global__ void layernorm_kernel(const float* __restrict__ in,
                                 const float* __restrict__ w,
                                 const float* __restrict__ b,
                                 float* __restrict__ out) {
    int row = blockIdx.x;
    const float* p = in + row * D;
    int t = threadIdx.x;
    float a0 = p[t], a1 = p[t + 128];
    float a2 = (t < 64) ? p[t + 256] : 0.f;
    float s  = a0 + a1 + a2;
    float s2 = a0 * a0 + a1 * a1 + a2 * a2;
    __shared__ float sh1[4], sh2[4];
    __shared__ float mr[2];
    int lane = t & 31, wp = t >> 5;
    #pragma unroll
    for (int o = 16; o; o >>= 1) {
        s  += __shfl_xor_sync(0xffffffffu, s,  o);
        s2 += __shfl_xor_sync(0xffffffffu, s2, o);
    }
    if (lane == 0) { sh1[wp] = s; sh2[wp] = s2; }
    __syncthreads();
    if (t == 0) {
        s = sh1[0] + sh1[1] + sh1[2] + sh1[3];
        s2 = sh2[0] + sh2[1] + sh2[2] + sh2[3];
        float m = s * (1.f / D);
        float var = s2 * (1.f / D) - m * m;
        mr[0] = m; mr[1] = rsqrtf(var + 1e-5f);
    }
    __syncthreads();
    float m = mr[0], r = mr[1];
    float* o = out + row * D;
    o[t]       = (a0 - m) * r * w[t]       + b[t];
    o[t + 128] = (a1 - m) * r * w[t + 128] + b[t + 128];
    if (t < 64)
        o[t + 256] = (a2 - m) * r * w[t + 256] + b[t + 256];
}

// ---------------- 320x320 transpose (for [out,in] conv weights) ----------------------
__global__ void transpose320_kernel(const float* __restrict__ in, float* __restrict__ out) {
    __shared__ float t[32][33];
    int x0 = blockIdx.x * 32, y0 = blockIdx.y * 32;
    t[threadIdx.y][threadIdx.x] = in[(y0 + threadIdx.y) * D + x0 + threadIdx.x];
    __syncthreads();
    out[(x0 + threadIdx.y) * D + y0 + threadIdx.x] = t[threadIdx.x][threadIdx.y];
}

// ---------------- fp32 tiled GEMM: C[M,N] = A[M,K] @ B[K,N] (+bias)(+epilogue) -------
// EPI 0: C = AB + bias
// EPI 1: C = AB + bias + R   (R same [M,N] layout)
// EPI 2: C[n*M+m] = AB + bias[n] + R[n*M+m]   (transposed store + residual, for pout)
template <int EPI>
__global__ void __launch_bounds__(256) gemm_kernel(
    const float* __restrict__ A, const float* __restrict__ B,
    const float* __restrict__ bias, const float* __restrict__ R,
    float* __restrict__ C, int M, int N, int K)
{
    __shared__ __align__(16) float As[16][68];
    __shared__ __align__(16) float Bs[16][64];
    int bm = blockIdx.y * 64, bn = blockIdx.x * 64;
    int tid = threadIdx.x;
    int tx = tid & 15, ty = tid >> 4;

    float acc[4][4];
    #pragma unroll
    for (int i = 0; i < 4; i++)
        #pragma unroll
        for (int j = 0; j < 4; j++) acc[i][j] = 0.f;

    int amr = tid >> 2;             // 0..63 (m within tile)
    int akc = (tid & 3) * 4;        // 0,4,8,12 (k within tile)
    int bkr = tid >> 4;             // 0..15 (k within tile)
    int bnc = (tid & 15) * 4;       // n within tile
    bool avalid = (bm + amr) < M;
    const float* Aptr = A + (size_t)(bm + amr) * K + akc;
    const float* Bptr = B + (size_t)bkr * N + bn + bnc;

    for (int k0 = 0; k0 < K; k0 += 16) {
        float4 av = avalid ? *(const float4*)Aptr : make_float4(0.f, 0.f, 0.f, 0.f);
        float4 bv = *(const float4*)Bptr;
        As[akc + 0][amr] = av.x;
        As[akc + 1][amr] = av.y;
        As[akc + 2][amr] = av.z;
        As[akc + 3][amr] = av.w;
        *(float4*)&Bs[bkr][bnc] = bv;
        __syncthreads();
        #pragma unroll
        for (int kk = 0; kk < 16; kk++) {
            float4 a = *(const float4*)&As[kk][ty * 4];
            float4 b = *(const float4*)&Bs[kk][tx * 4];
            acc[0][0] += a.x * b.x; acc[0][1] += a.x * b.y; acc[0][2] += a.x * b.z; acc[0][3] += a.x * b.w;
            acc[1][0] += a.y * b.x; acc[1][1] += a.y * b.y; acc[1][2] += a.y * b.z; acc[1][3] += a.y * b.w;
            acc[2][0] += a.z * b.x; acc[2][1] += a.z * b.y; acc[2][2] += a.z * b.z; acc[2][3] += a.z * b.w;
            acc[3][0] += a.w * b.x; acc[3][1] += a.w * b.y; acc[3][2] += a.w * b.z; acc[3][3] += a.w * b.w;
        }
        __syncthreads();
        Aptr += 16;
        Bptr += (size_t)16 * N;
    }

    #pragma unroll
    for (int i = 0; i < 4; i++) {
        int m = bm + ty * 4 + i;
        if (m >= M) continue;
        #pragma unroll
        for (int j = 0; j < 4; j++) {
            int n = bn + tx * 4 + j;
            float v = acc[i][j];
            if (bias) v += bias[n];
            if (EPI == 1) v += R[(size_t)m * N + n];
            if (EPI == 2) {
                C[(size_t)n * M + m] = v + R[(size_t)n * M + m];
            } else {
                C[(size_t)m * N + n] = v;
            }
        }
    }
}

// ---------------- Flash self-attention: 1 query/thread, 32-key tiles -----------------
__global__ void __launch_bounds__(128) flash_self_kernel(
    const float* __restrict__ Q, const float* __restrict__ K,
    const float* __restrict__ V, float* __restrict__ O)
{
    const float scale = 0.15811388300841897f; // 40^-0.5
    int h = blockIdx.y;
    int qrow = blockIdx.x * 128 + threadIdx.x;
    int tid = threadIdx.x;

    __shared__ __align__(16) float Ks[32][40];
    __shared__ __align__(16) float Vs[32][40];

    float4 q4[10], a4[10];
    const float* qp = Q + (size_t)qrow * D + h * DH;
    #pragma unroll
    for (int dd = 0; dd < 10; dd++) {
        float4 v = *(const float4*)(qp + dd * 4);
        q4[dd] = make_float4(v.x * scale, v.y * scale, v.z * scale, v.w * scale);
        a4[dd] = make_float4(0.f, 0.f, 0.f, 0.f);
    }
    float m = -1e30f, l = 0.f;

    for (int k0 = 0; k0 < N_TOK; k0 += 32) {
        __syncthreads();
        for (int i = tid; i < 320; i += 128) {   // 32 rows * 10 float4s
            int r = i / 10, c = (i % 10) * 4;
            size_t gi = (size_t)(k0 + r) * D + h * DH + c;
            *(float4*)&Ks[r][c] = *(const float4*)(K + gi);
            *(float4*)&Vs[r][c] = *(const float4*)(V + gi);
        }
        __syncthreads();

        float s[32];
        #pragma unroll
        for (int j = 0; j < 32; j++) {
            float acc = 0.f;
            #pragma unroll
            for (int dd = 0; dd < 10; dd++) {
                float4 kk = *(const float4*)&Ks[j][dd * 4];
                acc += q4[dd].x * kk.x + q4[dd].y * kk.y + q4[dd].z * kk.z + q4[dd].w * kk.w;
            }
            s[j] = acc;
        }
        float mt = m;
        #pragma unroll
        for (int j = 0; j < 32; j++) mt = fmaxf(mt, s[j]);
        float corr = __expf(m - mt);
        m = mt;
        l *= corr;
        #pragma unroll
        for (int dd = 0; dd < 10; dd++) {
            a4[dd].x *= corr; a4[dd].y *= corr; a4[dd].z *= corr; a4[dd].w *= corr;
        }
        #pragma unroll
        for (int j = 0; j < 32; j++) {
            float p = __expf(s[j] - m);
            l += p;
            #pragma unroll
            for (int dd = 0; dd < 10; dd++) {
                float4 vv = *(const float4*)&Vs[j][dd * 4];
                a4[dd].x += p * vv.x; a4[dd].y += p * vv.y;
                a4[dd].z += p * vv.z; a4[dd].w += p * vv.w;
            }
        }
    }
    float inv = 1.f / l;
    float* op = O + (size_t)qrow * D + h * DH;
    #pragma unroll
    for (int dd = 0; dd < 10; dd++) {
        *(float4*)(op + dd * 4) =
            make_float4(a4[dd].x * inv, a4[dd].y * inv, a4[dd].z * inv, a4[dd].w * inv);
    }
}

// ---------------- Cross attention: 77 keys fully resident in smem --------------------
__global__ void __launch_bounds__(128) cross_attn_kernel(
    const float* __restrict__ Q, const float* __restrict__ Kc,
    const float* __restrict__ Vc, float* __restrict__ O)
{
    const float scale = 0.15811388300841897f;
    int h = blockIdx.y;
    int qrow = blockIdx.x * 128 + threadIdx.x;
    int tid = threadIdx.x;

    __shared__ __align__(16) float Ks[CTX_N][40];
    __shared__ __align__(16) float Vs[CTX_N][40];
    for (int i = tid; i < CTX_N * 10; i += 128) {
        int r = i / 10, c = (i % 10) * 4;
        *(float4*)&Ks[r][c] = *(const float4*)(Kc + (size_t)r * D + h * DH + c);
        *(float4*)&Vs[r][c] = *(const float4*)(Vc + (size_t)r * D + h * DH + c);
    }
    __syncthreads();

    float4 q4[10], a4[10];
    const float* qp = Q + (size_t)qrow * D + h * DH;
    #pragma unroll
    for (int dd = 0; dd < 10; dd++) {
        float4 v = *(const float4*)(qp + dd * 4);
        q4[dd] = make_float4(v.x * scale, v.y * scale, v.z * scale, v.w * scale);
        a4[dd] = make_float4(0.f, 0.f, 0.f, 0.f);
    }
    float m = -1e30f, l = 0.f;
    for (int j = 0; j < CTX_N; j++) {
        float s = 0.f;
        #pragma unroll
        for (int dd = 0; dd < 10; dd++) {
            float4 kk = *(const float4*)&Ks[j][dd * 4];
            s += q4[dd].x * kk.x + q4[dd].y * kk.y + q4[dd].z * kk.z + q4[dd].w * kk.w;
        }
        float mt = fmaxf(m, s);
        float corr = __expf(m - mt);
        float p = __expf(s - mt);
        m = mt;
        l = l * corr + p;
        #pragma unroll
        for (int dd = 0; dd < 10; dd++) {
            float4 vv = *(const float4*)&Vs[j][dd * 4];
            a4[dd].x = a4[dd].x * corr + p * vv.x;
            a4[dd].y = a4[dd].y * corr + p * vv.y;
            a4[dd].z = a4[dd].z * corr + p * vv.z;
            a4[dd].w = a4[dd].w * corr + p * vv.w;
        }
    }
    float inv = 1.f / l;
    float* op = O + (size_t)qrow * D + h * DH;
    #pragma unroll
    for (int dd = 0; dd < 10; dd++) {
        *(float4*)(op + dd * 4) =
            make_float4(a4[dd].x * inv, a4[dd].y * inv, a4[dd].z * inv, a4[dd].w * inv);
    }
}

// ---------------- GEGLU: out = a * gelu_exact(g) -------------------------------------
__global__ void geglu_kernel(const float* __restrict__ H, float* __restrict__ G) {
    int idx = blockIdx.x * 256 + threadIdx.x;  // total N_TOK*FFI
    int r = idx / FFI, c = idx % FFI;
    float a = H[(size_t)r * (2 * FFI) + c];
    float g = H[(size_t)r * (2 * FFI) + FFI + c];
    float gg = 0.5f * g * (1.f + erff(g * 0.70710678118654752f));
    G[idx] = a * gg;
}

// ---------------- launch ------------------------------------------------------------
extern "C" void kernel_launch(void* const* d_in, const int* in_sizes, int n_in,
                              void* d_out, int out_size) {
    const float* x      = (const float*)d_in[0];
    const float* ctx    = (const float*)d_in[1];
    const float* gn_w   = (const float*)d_in[2];
    const float* gn_b   = (const float*)d_in[3];
    const float* pin_w  = (const float*)d_in[4];
    const float* pin_b  = (const float*)d_in[5];
    const float* ln1_w  = (const float*)d_in[6];
    const float* ln1_b  = (const float*)d_in[7];
    const float* q1     = (const float*)d_in[8];
    const float* k1     = (const float*)d_in[9];
    const float* v1     = (const float*)d_in[10];
    const float* o1_w   = (const float*)d_in[11];
    const float* o1_b   = (const float*)d_in[12];
    const float* ln2_w  = (const float*)d_in[13];
    const float* ln2_b  = (const float*)d_in[14];
    const float* q2     = (const float*)d_in[15];
    const float* k2     = (const float*)d_in[16];
    const float* v2     = (const float*)d_in[17];
    const float* o2_w   = (const float*)d_in[18];
    const float* o2_b   = (const float*)d_in[19];
    const float* ln3_w  = (const float*)d_in[20];
    const float* ln3_b  = (const float*)d_in[21];
    const float* ff1_w  = (const float*)d_in[22];
    const float* ff1_b  = (const float*)d_in[23];
    const float* ff2_w  = (const float*)d_in[24];
    const float* ff2_b  = (const float*)d_in[25];
    const float* pout_w = (const float*)d_in[26];
    const float* pout_b = (const float*)d_in[27];
    float* out = (float*)d_out;

    float *p_h, *p_h2, *p_ln, *p_q, *p_k, *p_v, *p_attn, *p_ffh, *p_ffg, *p_kc, *p_vc, *p_wT;
    cudaGetSymbolAddress((void**)&p_h,    g_h);
    cudaGetSymbolAddress((void**)&p_h2,   g_h2);
    cudaGetSymbolAddress((void**)&p_ln,   g_ln);
    cudaGetSymbolAddress((void**)&p_q,    g_q);
    cudaGetSymbolAddress((void**)&p_k,    g_k);
    cudaGetSymbolAddress((void**)&p_v,    g_v);
    cudaGetSymbolAddress((void**)&p_attn, g_attn);
    cudaGetSymbolAddress((void**)&p_ffh,  g_ffh);
    cudaGetSymbolAddress((void**)&p_ffg,  g_ffg);
    cudaGetSymbolAddress((void**)&p_kc,   g_kc);
    cudaGetSymbolAddress((void**)&p_vc,   g_vc);
    cudaGetSymbolAddress((void**)&p_wT,   g_wT);

    dim3 t32(32, 32);
    dim3 gemm64x5(5, 64);   // N=320, M=4096

    // GroupNorm + pin (conv1x1 via transposed weight)
    gn_stats_kernel<<<GROUPS, 256>>>(x);
    gn_apply_t_kernel<<<dim3(128, 10), t32>>>(x, gn_w, gn_b, p_ln);
    transpose320_kernel<<<dim3(10, 10), t32>>>(pin_w, p_wT);
    gemm_kernel<0><<<gemm64x5, 256>>>(p_ln, p_wT, pin_b, nullptr, p_h, N_TOK, D, D);

    // Self-attention block
    layernorm_kernel<<<N_TOK, 128>>>(p_h, ln1_w, ln1_b, p_ln);
    gemm_kernel<0><<<gemm64x5, 256>>>(p_ln, q1, nullptr, nullptr, p_q, N_TOK, D, D);
    gemm_kernel<0><<<gemm64x5, 256>>>(p_ln, k1, nullptr, nullptr, p_k, N_TOK, D, D);
    gemm_kernel<0><<<gemm64x5, 256>>>(p_ln, v1, nullptr, nullptr, p_v, N_TOK, D, D);
    flash_self_kernel<<<dim3(32, HEADS), 128>>>(p_q, p_k, p_v, p_attn);
    gemm_kernel<1><<<gemm64x5, 256>>>(p_attn, o1_w, o1_b, p_h, p_h2, N_TOK, D, D);

    // Cross-attention block
    layernorm_kernel<<<N_TOK, 128>>>(p_h2, ln2_w, ln2_b, p_ln);
    gemm_kernel<0><<<gemm64x5, 256>>>(p_ln, q2, nullptr, nullptr, p_q, N_TOK, D, D);
    gemm_kernel<0><<<dim3(5, 2), 256>>>(ctx, k2, nullptr, nullptr, p_kc, CTX_N, D, CTX_D);
    gemm_kernel<0><<<dim3(5, 2), 256>>>(ctx, v2, nullptr, nullptr, p_vc, CTX_N, D, CTX_D);
    cross_attn_kernel<<<dim3(32, HEADS), 128>>>(p_q, p_kc, p_vc, p_attn);
    gemm_kernel<1><<<gemm64x5, 256>>>(p_attn, o2_w, o2_b, p_h2, p_h, N_TOK, D, D);

    // GEGLU FF block
    layernorm_kernel<<<N_TOK, 128>>>(p_h, ln3_w, ln3_b, p_ln);
    gemm_kernel<0><<<dim3(40, 64), 256>>>(p_ln, ff1_w, ff1_b, nullptr, p_ffh, N_TOK, 2 * FFI, D);
    geglu_kernel<<<(N_TOK * FFI) / 256, 256>>>(p_ffh, p_ffg);
    gemm_kernel<1><<<gemm64x5, 256>>>(p_ffg, ff2_w, ff2_b, p_h, p_h2, N_TOK, D, FFI);

    // proj_out (conv1x1) + transposed store + input residual
    transpose320_kernel<<<dim3(10, 10), t32>>>(pout_w, p_wT);
    gemm_kernel<2><<<gemm64x5, 256>>>(p_h2, p_wT, pout_b, x, out, N_TOK, D, D);
}

// round 2
// speedup vs baseline: 2.1196x; 2.1196x over previous
#include <cuda_runtime.h>
#include <math.h>
#include <stdint.h>

#define N_TOK 4096
#define D     320
#define HEADS 8
#define DH    40
#define CTX_N 77
#define CTX_D 768
#define FFI   1280
#define GROUPS 32
#define LOG2E 1.4426950408889634f

// ---------------- scratch ----------------
__device__ float g_h   [N_TOK * D];
__device__ float g_h2  [N_TOK * D];
__device__ float g_ln  [N_TOK * D];
__device__ float g_q   [N_TOK * D];
__device__ float g_k   [N_TOK * D];
__device__ float g_v   [N_TOK * D];
__device__ float g_attn[N_TOK * D];
__device__ float g_ffh [N_TOK * 2 * FFI];
__device__ float g_ffg [N_TOK * FFI];
__device__ float g_kc  [CTX_N * D];
__device__ float g_vc  [CTX_N * D];
__device__ float g_wT  [D * D];
__device__ float g_mu  [GROUPS];
__device__ float g_rs  [GROUPS];

// ---------------- tf32 helpers ----------------
__device__ __forceinline__ uint32_t tf32u(float x) {
    uint32_t y;
    asm("cvt.rna.tf32.f32 %0, %1;" : "=r"(y) : "f"(x));
    return y;
}
__device__ __forceinline__ float tf32f(float x) { return __uint_as_float(tf32u(x)); }

__device__ __forceinline__ void mma_tf32(float* c, const uint32_t* a, const uint32_t* b) {
    asm volatile(
        "mma.sync.aligned.m16n8k8.row.col.f32.tf32.tf32.f32 "
        "{%0,%1,%2,%3}, {%4,%5,%6,%7}, {%8,%9}, {%0,%1,%2,%3};"
        : "+f"(c[0]), "+f"(c[1]), "+f"(c[2]), "+f"(c[3])
        : "r"(a[0]), "r"(a[1]), "r"(a[2]), "r"(a[3]), "r"(b[0]), "r"(b[1]));
}

// ---------------- GroupNorm stats ----------------
__global__ void gn_stats_kernel(const float* __restrict__ x) {
    int g = blockIdx.x;
    const float* p = x + g * (10 * N_TOK);
    float s = 0.f, s2 = 0.f;
    for (int i = threadIdx.x; i < 10 * N_TOK; i += 256) {
        float v = p[i];
        s += v; s2 += v * v;
    }
    __shared__ float sh1[8], sh2[8];
    int lane = threadIdx.x & 31, w = threadIdx.x >> 5;
    #pragma unroll
    for (int o = 16; o; o >>= 1) {
        s  += __shfl_xor_sync(0xffffffffu, s,  o);
        s2 += __shfl_xor_sync(0xffffffffu, s2, o);
    }
    if (lane == 0) { sh1[w] = s; sh2[w] = s2; }
    __syncthreads();
    if (threadIdx.x == 0) {
        s = 0.f; s2 = 0.f;
        #pragma unroll
        for (int i = 0; i < 8; i++) { s += sh1[i]; s2 += sh2[i]; }
        float m   = s  * (1.f / (10 * N_TOK));
        float var = s2 * (1.f / (10 * N_TOK)) - m * m;
        g_mu[g] = m;
        g_rs[g] = rsqrtf(var + 1e-6f);
    }
}

// ---------------- GN apply + transpose ----------------
__global__ void gn_apply_t_kernel(const float* __restrict__ x,
                                  const float* __restrict__ w,
                                  const float* __restrict__ b,
                                  float* __restrict__ out) {
    __shared__ float t[32][33];
    int p0 = blockIdx.x * 32, c0 = blockIdx.y * 32;
    int c = c0 + threadIdx.y, p = p0 + threadIdx.x;
    int g = c / 10;
    float v = (x[c * N_TOK + p] - g_mu[g]) * g_rs[g] * w[c] + b[c];
    t[threadIdx.y][threadIdx.x] = v;
    __syncthreads();
    out[(p0 + threadIdx.y) * D + c0 + threadIdx.x] = t[threadIdx.x][threadIdx.y];
}

// ---------------- LayerNorm ----------------
__global__ void layernorm_kernel(const float* __restrict__ in,
                                 const float* __restrict__ w,
                                 const float* __restrict__ b,
                                 float* __restrict__ out) {
    int row = blockIdx.x;
    const float* p = in + row * D;
    int t = threadIdx.x;
    float a0 = p[t], a1 = p[t + 128];
    float a2 = (t < 64) ? p[t + 256] : 0.f;
    float s  = a0 + a1 + a2;
    float s2 = a0 * a0 + a1 * a1 + a2 * a2;
    __shared__ float sh1[4], sh2[4];
    __shared__ float mr[2];
    int lane = t & 31, wp = t >> 5;
    #pragma unroll
    for (int o = 16; o; o >>= 1) {
        s  += __shfl_xor_sync(0xffffffffu, s,  o);
        s2 += __shfl_xor_sync(0xffffffffu, s2, o);
    }
    if (lane == 0) { sh1[wp] = s; sh2[wp] = s2; }
    __syncthreads();
    if (t == 0) {
        s = sh1[0] + sh1[1] + sh1[2] + sh1[3];
        s2 = sh2[0] + sh2[1] + sh2[2] + sh2[3];
        float m = s * (1.f / D);
        float var = s2 * (1.f / D) - m * m;
        mr[0] = m; mr[1] = rsqrtf(var + 1e-5f);
    }
    __syncthreads();
    float m = mr[0], r = mr[1];
    float* o = out + row * D;
    o[t]       = (a0 - m) * r * w[t]       + b[t];
    o[t + 128] = (a1 - m) * r * w[t + 128] + b[t + 128];
    if (t < 64)
        o[t + 256] = (a2 - m) * r * w[t + 256] + b[t + 256];
}

// ---------------- 320x320 transpose ----------------
__global__ void transpose320_kernel(const float* __restrict__ in, float* __restrict__ out) {
    __shared__ float t[32][33];
    int x0 = blockIdx.x * 32, y0 = blockIdx.y * 32;
    t[threadIdx.y][threadIdx.x] = in[(y0 + threadIdx.y) * D + x0 + threadIdx.x];
    __syncthreads();
    out[(x0 + threadIdx.y) * D + y0 + threadIdx.x] = t[threadIdx.x][threadIdx.y];
}

// ---------------- scalar fp32 GEMM (only for the tiny ctx K/V GEMMs, M=77) ---------
template <int EPI>
__global__ void __launch_bounds__(256) gemm_kernel(
    const float* __restrict__ A, const float* __restrict__ B,
    const float* __restrict__ bias, const float* __restrict__ R,
    float* __restrict__ C, int M, int N, int K)
{
    __shared__ __align__(16) float As[16][68];
    __shared__ __align__(16) float Bs[16][64];
    int bm = blockIdx.y * 64, bn = blockIdx.x * 64;
    int tid = threadIdx.x;
    int tx = tid & 15, ty = tid >> 4;

    float acc[4][4];
    #pragma unroll
    for (int i = 0; i < 4; i++)
        #pragma unroll
        for (int j = 0; j < 4; j++) acc[i][j] = 0.f;

    int amr = tid >> 2;
    int akc = (tid & 3) * 4;
    int bkr = tid >> 4;
    int bnc = (tid & 15) * 4;
    bool avalid = (bm + amr) < M;
    const float* Aptr = A + (size_t)(bm + amr) * K + akc;
    const float* Bptr = B + (size_t)bkr * N + bn + bnc;

    for (int k0 = 0; k0 < K; k0 += 16) {
        float4 av = avalid ? *(const float4*)Aptr : make_float4(0.f, 0.f, 0.f, 0.f);
        float4 bv = *(const float4*)Bptr;
        As[akc + 0][amr] = av.x;
        As[akc + 1][amr] = av.y;
        As[akc + 2][amr] = av.z;
        As[akc + 3][amr] = av.w;
        *(float4*)&Bs[bkr][bnc] = bv;
        __syncthreads();
        #pragma unroll
        for (int kk = 0; kk < 16; kk++) {
            float4 a = *(const float4*)&As[kk][ty * 4];
            float4 b = *(const float4*)&Bs[kk][tx * 4];
            acc[0][0] += a.x * b.x; acc[0][1] += a.x * b.y; acc[0][2] += a.x * b.z; acc[0][3] += a.x * b.w;
            acc[1][0] += a.y * b.x; acc[1][1] += a.y * b.y; acc[1][2] += a.y * b.z; acc[1][3] += a.y * b.w;
            acc[2][0] += a.z * b.x; acc[2][1] += a.z * b.y; acc[2][2] += a.z * b.z; acc[2][3] += a.z * b.w;
            acc[3][0] += a.w * b.x; acc[3][1] += a.w * b.y; acc[3][2] += a.w * b.z; acc[3][3] += a.w * b.w;
        }
        __syncthreads();
        Aptr += 16;
        Bptr += (size_t)16 * N;
    }

    #pragma unroll
    for (int i = 0; i < 4; i++) {
        int m = bm + ty * 4 + i;
        if (m >= M) continue;
        #pragma unroll
        for (int j = 0; j < 4; j++) {
            int n = bn + tx * 4 + j;
            float v = acc[i][j];
            if (bias) v += bias[n];
            if (EPI == 1) v += R[(size_t)m * N + n];
            C[(size_t)m * N + n] = v;
        }
    }
}

// ---------------- tf32 tensor-core GEMM: C[M,N] = A[M,K] @ B[K,N] -------------------
// EPI 0: +bias; EPI 1: +bias +R (row-major); EPI 2: transposed store +bias +R[n*M+m]
// Requires: M % 128 == 0, N % 64 == 0, K % 16 == 0.
template <int EPI>
__global__ void __launch_bounds__(256) gemm_tf32_kernel(
    const float* __restrict__ A, const float* __restrict__ B,
    const float* __restrict__ bias, const float* __restrict__ R,
    float* __restrict__ C, int M, int N, int K)
{
    __shared__ __align__(16) float As[128][20];
    __shared__ __align__(16) float Bs[16][72];
    int tid = threadIdx.x;
    int lane = tid & 31, wid = tid >> 5;
    int wm = wid & 3, wn = wid >> 2;      // 4 warps in M, 2 in N
    int g = lane >> 2, t = lane & 3;
    int bm = blockIdx.y * 128, bn = blockIdx.x * 64;

    float acc[2][4][4];
    #pragma unroll
    for (int mf = 0; mf < 2; mf++)
        #pragma unroll
        for (int nf = 0; nf < 4; nf++)
            #pragma unroll
            for (int r = 0; r < 4; r++) acc[mf][nf][r] = 0.f;

    int arow = tid >> 2;            // 0..63
    int acol = (tid & 3) << 2;      // 0,4,8,12
    int brow = tid >> 4;            // 0..15
    int bcol = (tid & 15) << 2;     // 0..60

    const float* Ap = A + (size_t)(bm + arow) * K + acol;
    const float* Bp = B + (size_t)brow * N + bn + bcol;

    float4 pa0 = *(const float4*)Ap;
    float4 pa1 = *(const float4*)(Ap + (size_t)64 * K);
    float4 pb  = *(const float4*)Bp;

    for (int k0 = 0; k0 < K; k0 += 16) {
        *(float4*)&As[arow][acol] =
            make_float4(tf32f(pa0.x), tf32f(pa0.y), tf32f(pa0.z), tf32f(pa0.w));
        *(float4*)&As[arow + 64][acol] =
            make_float4(tf32f(pa1.x), tf32f(pa1.y), tf32f(pa1.z), tf32f(pa1.w));
        *(float4*)&Bs[brow][bcol] =
            make_float4(tf32f(pb.x), tf32f(pb.y), tf32f(pb.z), tf32f(pb.w));
        __syncthreads();
        if (k0 + 16 < K) {
            Ap += 16;
            Bp += (size_t)16 * N;
            pa0 = *(const float4*)Ap;
            pa1 = *(const float4*)(Ap + (size_t)64 * K);
            pb  = *(const float4*)Bp;
        }
        #pragma unroll
        for (int kk = 0; kk < 2; kk++) {
            uint32_t a[2][4], b[4][2];
            #pragma unroll
            for (int mf = 0; mf < 2; mf++) {
                int r = wm * 32 + mf * 16;
                a[mf][0] = __float_as_uint(As[r + g    ][kk * 8 + t]);
                a[mf][1] = __float_as_uint(As[r + g + 8][kk * 8 + t]);
                a[mf][2] = __float_as_uint(As[r + g    ][kk * 8 + t + 4]);
                a[mf][3] = __float_as_uint(As[r + g + 8][kk * 8 + t + 4]);
            }
            #pragma unroll
            for (int nf = 0; nf < 4; nf++) {
                int c = wn * 32 + nf * 8 + g;
                b[nf][0] = __float_as_uint(Bs[kk * 8 + t    ][c]);
                b[nf][1] = __float_as_uint(Bs[kk * 8 + t + 4][c]);
            }
            #pragma unroll
            for (int mf = 0; mf < 2; mf++)
                #pragma unroll
                for (int nf = 0; nf < 4; nf++)
                    mma_tf32(acc[mf][nf], a[mf], b[nf]);
        }
        __syncthreads();
    }

    #pragma unroll
    for (int mf = 0; mf < 2; mf++) {
        #pragma unroll
        for (int nf = 0; nf < 4; nf++) {
            int m = bm + wm * 32 + mf * 16 + g;
            int n = bn + wn * 32 + nf * 8 + 2 * t;
            float b0 = bias ? bias[n] : 0.f;
            float b1 = bias ? bias[n + 1] : 0.f;
            float v0 = acc[mf][nf][0] + b0;
            float v1 = acc[mf][nf][1] + b1;
            float v2 = acc[mf][nf][2] + b0;
            float v3 = acc[mf][nf][3] + b1;
            if (EPI == 2) {
                C[(size_t)n * M + m]           = v0 + R[(size_t)n * M + m];
                C[(size_t)(n + 1) * M + m]     = v1 + R[(size_t)(n + 1) * M + m];
                C[(size_t)n * M + m + 8]       = v2 + R[(size_t)n * M + m + 8];
                C[(size_t)(n + 1) * M + m + 8] = v3 + R[(size_t)(n + 1) * M + m + 8];
            } else {
                if (EPI == 1) {
                    float2 r0 = *(const float2*)&R[(size_t)m * N + n];
                    float2 r1 = *(const float2*)&R[(size_t)(m + 8) * N + n];
                    v0 += r0.x; v1 += r0.y; v2 += r1.x; v3 += r1.y;
                }
                *(float2*)&C[(size_t)m * N + n]       = make_float2(v0, v1);
                *(float2*)&C[(size_t)(m + 8) * N + n] = make_float2(v2, v3);
            }
        }
    }
}

// ---------------- flash self-attention, tf32 mma ------------------------------------
// grid (64, 8); 128 threads = 4 warps; warp w owns query rows [w*16, w*16+16)
__global__ void __launch_bounds__(128) flash_mma_kernel(
    const float* __restrict__ Q, const float* __restrict__ K,
    const float* __restrict__ V, float* __restrict__ O)
{
    __shared__ __align__(16) float Ks[64][44];
    __shared__ __align__(16) float Vs[64][44];
    __shared__ __align__(16) float Ps[64][68];
    int h = blockIdx.y;
    int q0 = blockIdx.x * 64;
    int tid = threadIdx.x, wid = tid >> 5, lane = tid & 31;
    int g = lane >> 2, t = lane & 3;
    const float scale = 0.15811388300841897f;

    // Q fragments (resident), pre-scaled and tf32-rounded
    uint32_t qa[5][4];
    {
        const float* qb = Q + (size_t)q0 * D + h * DH;
        int r0 = wid * 16 + g;
        #pragma unroll
        for (int kk = 0; kk < 5; kk++) {
            qa[kk][0] = tf32u(qb[(size_t)r0 * D       + kk * 8 + t]     * scale);
            qa[kk][1] = tf32u(qb[(size_t)(r0 + 8) * D + kk * 8 + t]     * scale);
            qa[kk][2] = tf32u(qb[(size_t)r0 * D       + kk * 8 + t + 4] * scale);
            qa[kk][3] = tf32u(qb[(size_t)(r0 + 8) * D + kk * 8 + t + 4] * scale);
        }
    }

    float o[5][4];
    #pragma unroll
    for (int nf = 0; nf < 5; nf++)
        #pragma unroll
        for (int r = 0; r < 4; r++) o[nf][r] = 0.f;
    float mA = -1e30f, mB = -1e30f, lA = 0.f, lB = 0.f;

    for (int k0 = 0; k0 < N_TOK; k0 += 64) {
        __syncthreads();
        #pragma unroll
        for (int i = 0; i < 5; i++) {
            int idx = tid + i * 128;           // 640 = 64 rows * 10 float4
            int r = idx / 10, c = (idx % 10) * 4;
            float4 kv = *(const float4*)(K + (size_t)(k0 + r) * D + h * DH + c);
            float4 vv = *(const float4*)(V + (size_t)(k0 + r) * D + h * DH + c);
            *(float4*)&Ks[r][c] = make_float4(tf32f(kv.x), tf32f(kv.y), tf32f(kv.z), tf32f(kv.w));
            *(float4*)&Vs[r][c] = make_float4(tf32f(vv.x), tf32f(vv.y), tf32f(vv.z), tf32f(vv.w));
        }
        __syncthreads();

        // S = Q K^T
        float s[8][4];
        #pragma unroll
        for (int nf = 0; nf < 8; nf++)
            #pragma unroll
            for (int r = 0; r < 4; r++) s[nf][r] = 0.f;
        #pragma unroll
        for (int kk = 0; kk < 5; kk++) {
            #pragma unroll
            for (int nf = 0; nf < 8; nf++) {
                uint32_t bb[2];
                bb[0] = __float_as_uint(Ks[nf * 8 + g][kk * 8 + t]);
                bb[1] = __float_as_uint(Ks[nf * 8 + g][kk * 8 + t + 4]);
                mma_tf32(s[nf], qa[kk], bb);
            }
        }

        // online softmax (rows: A = lane/4, B = lane/4 + 8)
        float mtA = mA, mtB = mB;
        #pragma unroll
        for (int nf = 0; nf < 8; nf++) {
            mtA = fmaxf(mtA, fmaxf(s[nf][0], s[nf][1]));
            mtB = fmaxf(mtB, fmaxf(s[nf][2], s[nf][3]));
        }
        mtA = fmaxf(mtA, __shfl_xor_sync(0xffffffffu, mtA, 1));
        mtA = fmaxf(mtA, __shfl_xor_sync(0xffffffffu, mtA, 2));
        mtB = fmaxf(mtB, __shfl_xor_sync(0xffffffffu, mtB, 1));
        mtB = fmaxf(mtB, __shfl_xor_sync(0xffffffffu, mtB, 2));
        float corrA = exp2f((mA - mtA) * LOG2E);
        float corrB = exp2f((mB - mtB) * LOG2E);
        mA = mtA; mB = mtB;
        lA *= corrA; lB *= corrB;
        #pragma unroll
        for (int nf = 0; nf < 5; nf++) {
            o[nf][0] *= corrA; o[nf][1] *= corrA;
            o[nf][2] *= corrB; o[nf][3] *= corrB;
        }
        int pr = wid * 16 + g;
        #pragma unroll
        for (int nf = 0; nf < 8; nf++) {
            float p0 = exp2f((s[nf][0] - mA) * LOG2E);
            float p1 = exp2f((s[nf][1] - mA) * LOG2E);
            float p2 = exp2f((s[nf][2] - mB) * LOG2E);
            float p3 = exp2f((s[nf][3] - mB) * LOG2E);
            lA += p0 + p1; lB += p2 + p3;
            *(float2*)&Ps[pr][nf * 8 + 2 * t]     = make_float2(tf32f(p0), tf32f(p1));
            *(float2*)&Ps[pr + 8][nf * 8 + 2 * t] = make_float2(tf32f(p2), tf32f(p3));
        }
        __syncwarp();

        // O += P V
        #pragma unroll
        for (int kk = 0; kk < 8; kk++) {
            uint32_t pa[4];
            pa[0] = __float_as_uint(Ps[wid * 16 + g    ][kk * 8 + t]);
            pa[1] = __float_as_uint(Ps[wid * 16 + g + 8][kk * 8 + t]);
            pa[2] = __float_as_uint(Ps[wid * 16 + g    ][kk * 8 + t + 4]);
            pa[3] = __float_as_uint(Ps[wid * 16 + g + 8][kk * 8 + t + 4]);
            #pragma unroll
            for (int nf = 0; nf < 5; nf++) {
                uint32_t bb[2];
                bb[0] = __float_as_uint(Vs[kk * 8 + t    ][nf * 8 + g]);
                bb[1] = __float_as_uint(Vs[kk * 8 + t + 4][nf * 8 + g]);
                mma_tf32(o[nf], pa, bb);
            }
        }
    }

    lA += __shfl_xor_sync(0xffffffffu, lA, 1);
    lA += __shfl_xor_sync(0xffffffffu, lA, 2);
    lB += __shfl_xor_sync(0xffffffffu, lB, 1);
    lB += __shfl_xor_sync(0xffffffffu, lB, 2);
    float iA = 1.f / lA, iB = 1.f / lB;
    float* ob = O + (size_t)(q0 + wid * 16 + g) * D + h * DH;
    #pragma unroll
    for (int nf = 0; nf < 5; nf++) {
        *(float2*)(ob + nf * 8 + 2 * t) = make_float2(o[nf][0] * iA, o[nf][1] * iA);
        *(float2*)(ob + (size_t)8 * D + nf * 8 + 2 * t) = make_float2(o[nf][2] * iB, o[nf][3] * iB);
    }
}

// ---------------- cross attention (scalar; only 77 keys) ----------------------------
__global__ void __launch_bounds__(128) cross_attn_kernel(
    const float* __restrict__ Q, const float* __restrict__ Kc,
    const float* __restrict__ Vc, float* __restrict__ O)
{
    const float scale = 0.15811388300841897f;
    int h = blockIdx.y;
    int qrow = blockIdx.x * 128 + threadIdx.x;
    int tid = threadIdx.x;

    __shared__ __align__(16) float Ks[CTX_N][40];
    __shared__ __align__(16) float Vs[CTX_N][40];
    for (int i = tid; i < CTX_N * 10; i += 128) {
        int r = i / 10, c = (i % 10) * 4;
        *(float4*)&Ks[r][c] = *(const float4*)(Kc + (size_t)r * D + h * DH + c);
        *(float4*)&Vs[r][c] = *(const float4*)(Vc + (size_t)r * D + h * DH + c);
    }
    __syncthreads();

    float4 q4[10], a4[10];
    const float* qp = Q + (size_t)qrow * D + h * DH;
    #pragma unroll
    for (int dd = 0; dd < 10; dd++) {
        float4 v = *(const float4*)(qp + dd * 4);
        q4[dd] = make_float4(v.x * scale, v.y * scale, v.z * scale, v.w * scale);
        a4[dd] = make_float4(0.f, 0.f, 0.f, 0.f);
    }
    float m = -1e30f, l = 0.f;
    for (int j = 0; j < CTX_N; j++) {
        float s = 0.f;
        #pragma unroll
        for (int dd = 0; dd < 10; dd++) {
            float4 kk = *(const float4*)&Ks[j][dd * 4];
            s += q4[dd].x * kk.x + q4[dd].y * kk.y + q4[dd].z * kk.z + q4[dd].w * kk.w;
        }
        float mt = fmaxf(m, s);
        float corr = __expf(m - mt);
        float p = __expf(s - mt);
        m = mt;
        l = l * corr + p;
        #pragma unroll
        for (int dd = 0; dd < 10; dd++) {
            float4 vv = *(const float4*)&Vs[j][dd * 4];
            a4[dd].x = a4[dd].x * corr + p * vv.x;
            a4[dd].y = a4[dd].y * corr + p * vv.y;
            a4[dd].z = a4[dd].z * corr + p * vv.z;
            a4[dd].w = a4[dd].w * corr + p * vv.w;
        }
    }
    float inv = 1.f / l;
    float* op = O + (size_t)qrow * D + h * DH;
    #pragma unroll
    for (int dd = 0; dd < 10; dd++) {
        *(float4*)(op + dd * 4) =
            make_float4(a4[dd].x * inv, a4[dd].y * inv, a4[dd].z * inv, a4[dd].w * inv);
    }
}

// ---------------- GEGLU ----------------
__global__ void geglu_kernel(const float* __restrict__ H, float* __restrict__ G) {
    int idx = blockIdx.x * 256 + threadIdx.x;
    int r = idx / FFI, c = idx % FFI;
    float a = H[(size_t)r * (2 * FFI) + c];
    float g = H[(size_t)r * (2 * FFI) + FFI + c];
    float gg = 0.5f * g * (1.f + erff(g * 0.70710678118654752f));
    G[idx] = a * gg;
}

// ---------------- launch ----------------
extern "C" void kernel_launch(void* const* d_in, const int* in_sizes, int n_in,
                              void* d_out, int out_size) {
    const float* x      = (const float*)d_in[0];
    const float* ctx    = (const float*)d_in[1];
    const float* gn_w   = (const float*)d_in[2];
    const float* gn_b   = (const float*)d_in[3];
    const float* pin_w  = (const float*)d_in[4];
    const float* pin_b  = (const float*)d_in[5];
    const float* ln1_w  = (const float*)d_in[6];
    const float* ln1_b  = (const float*)d_in[7];
    const float* q1     = (const float*)d_in[8];
    const float* k1     = (const float*)d_in[9];
    const float* v1     = (const float*)d_in[10];
    const float* o1_w   = (const float*)d_in[11];
    const float* o1_b   = (const float*)d_in[12];
    const float* ln2_w  = (const float*)d_in[13];
    const float* ln2_b  = (const float*)d_in[14];
    const float* q2     = (const float*)d_in[15];
    const float* k2     = (const float*)d_in[16];
    const float* v2     = (const float*)d_in[17];
    const float* o2_w   = (const float*)d_in[18];
    const float* o2_b   = (const float*)d_in[19];
    const float* ln3_w  = (const float*)d_in[20];
    const float* ln3_b  = (const float*)d_in[21];
    const float* ff1_w  = (const float*)d_in[22];
    const float* ff1_b  = (const float*)d_in[23];
    const float* ff2_w  = (const float*)d_in[24];
    const float* ff2_b  = (const float*)d_in[25];
    const float* pout_w = (const float*)d_in[26];
    const float* pout_b = (const float*)d_in[27];
    float* out = (float*)d_out;

    float *p_h, *p_h2, *p_ln, *p_q, *p_k, *p_v, *p_attn, *p_ffh, *p_ffg, *p_kc, *p_vc, *p_wT;
    cudaGetSymbolAddress((void**)&p_h,    g_h);
    cudaGetSymbolAddress((void**)&p_h2,   g_h2);
    cudaGetSymbolAddress((void**)&p_ln,   g_ln);
    cudaGetSymbolAddress((void**)&p_q,    g_q);
    cudaGetSymbolAddress((void**)&p_k,    g_k);
    cudaGetSymbolAddress((void**)&p_v,    g_v);
    cudaGetSymbolAddress((void**)&p_attn, g_attn);
    cudaGetSymbolAddress((void**)&p_ffh,  g_ffh);
    cudaGetSymbolAddress((void**)&p_ffg,  g_ffg);
    cudaGetSymbolAddress((void**)&p_kc,   g_kc);
    cudaGetSymbolAddress((void**)&p_vc,   g_vc);
    cudaGetSymbolAddress((void**)&p_wT,   g_wT);

    dim3 t32(32, 32);
    dim3 gD(D / 64, N_TOK / 128);      // (5, 32) for N=320 GEMMs

    // GroupNorm + pin
    gn_stats_kernel<<<GROUPS, 256>>>(x);
    gn_apply_t_kernel<<<dim3(128, 10), t32>>>(x, gn_w, gn_b, p_ln);
    transpose320_kernel<<<dim3(10, 10), t32>>>(pin_w, p_wT);
    gemm_tf32_kernel<0><<<gD, 256>>>(p_ln, p_wT, pin_b, nullptr, p_h, N_TOK, D, D);

    // Self-attention block
    layernorm_kernel<<<N_TOK, 128>>>(p_h, ln1_w, ln1_b, p_ln);
    gemm_tf32_kernel<0><<<gD, 256>>>(p_ln, q1, nullptr, nullptr, p_q, N_TOK, D, D);
    gemm_tf32_kernel<0><<<gD, 256>>>(p_ln, k1, nullptr, nullptr, p_k, N_TOK, D, D);
    gemm_tf32_kernel<0><<<gD, 256>>>(p_ln, v1, nullptr, nullptr, p_v, N_TOK, D, D);
    flash_mma_kernel<<<dim3(N_TOK / 64, HEADS), 128>>>(p_q, p_k, p_v, p_attn);
    gemm_tf32_kernel<1><<<gD, 256>>>(p_attn, o1_w, o1_b, p_h, p_h2, N_TOK, D, D);

    // Cross-attention block
    layernorm_kernel<<<N_TOK, 128>>>(p_h2, ln2_w, ln2_b, p_ln);
    gemm_tf32_kernel<0><<<gD, 256>>>(p_ln, q2, nullptr, nullptr, p_q, N_TOK, D, D);
    gemm_kernel<0><<<dim3(5, 2), 256>>>(ctx, k2, nullptr, nullptr, p_kc, CTX_N, D, CTX_D);
    gemm_kernel<0><<<dim3(5, 2), 256>>>(ctx, v2, nullptr, nullptr, p_vc, CTX_N, D, CTX_D);
    cross_attn_kernel<<<dim3(N_TOK / 128, HEADS), 128>>>(p_q, p_kc, p_vc, p_attn);
    gemm_tf32_kernel<1><<<gD, 256>>>(p_attn, o2_w, o2_b, p_h2, p_h, N_TOK, D, D);

    // GEGLU FF block
    layernorm_kernel<<<N_TOK, 128>>>(p_h, ln3_w, ln3_b, p_ln);
    gemm_tf32_kernel<0><<<dim3(2 * FFI / 64, N_TOK / 128), 256>>>(p_ln, ff1_w, ff1_b, nullptr, p_ffh, N_TOK, 2 * FFI, D);
    geglu_kernel<<<(N_TOK * FFI) / 256, 256>>>(p_ffh, p_ffg);
    gemm_tf32_kernel<1><<<gD, 256>>>(p_ffg, ff2_w, ff2_b, p_h, p_h2, N_TOK, D, FFI);

    // proj_out + transposed store + input residual
    transpose320_kernel<<<dim3(10, 10), t32>>>(pout_w, p_wT);
    gemm_tf32_kernel<2><<<gD, 256>>>(p_h2, p_wT, pout_b, x, out, N_TOK, D, D);
}

// round 4
// speedup vs baseline: 3.0013x; 1.4160x over previous
#include <cuda_runtime.h>
#include <cuda_bf16.h>
#include <math.h>
#include <stdint.h>

#define N_TOK 4096
#define D     320
#define HEADS 8
#define DH    40
#define CTX_N 77
#define CTX_D 768
#define FFI   1280
#define GROUPS 32
#define LOG2E 1.4426950408889634f

typedef __nv_bfloat16 bf16;

// ---------------- scratch ----------------
__device__ float g_h  [N_TOK * D];
__device__ float g_h2 [N_TOK * D];
__device__ float g_kc [CTX_N * D];
__device__ float g_vc [CTX_N * D];
__device__ float g_mu [GROUPS];
__device__ float g_rs [GROUPS];

__device__ bf16 g_lnb [N_TOK * D];
__device__ bf16 g_qkvb[N_TOK * 3 * D];
__device__ bf16 g_vTb [D * N_TOK];
__device__ bf16 g_attnb[N_TOK * D];
__device__ bf16 g_q2b [N_TOK * D];
__device__ bf16 g_h2b [N_TOK * D];
__device__ bf16 g_ffhb[N_TOK * 2 * FFI];
__device__ bf16 g_ffgb[N_TOK * FFI];

// weights, bf16, stored as B^T = [N][K]
__device__ bf16 g_wqkv[3 * D * D];
__device__ bf16 g_wo1 [D * D];
__device__ bf16 g_wq2 [D * D];
__device__ bf16 g_wo2 [D * D];
__device__ bf16 g_wff1[2 * FFI * D];
__device__ bf16 g_wff2[D * FFI];
__device__ bf16 g_wpin[D * D];
__device__ bf16 g_wpout[D * D];

// ---------------- helpers ----------------
__device__ __forceinline__ uint32_t bf2pk(float lo, float hi) {
    uint32_t r;
    asm("cvt.rn.bf16x2.f32 %0, %1, %2;" : "=r"(r) : "f"(hi), "f"(lo));
    return r;
}
__device__ __forceinline__ void mma_bf16(float* c, const uint32_t* a, const uint32_t* b) {
    asm volatile(
        "mma.sync.aligned.m16n8k16.row.col.f32.bf16.bf16.f32 "
        "{%0,%1,%2,%3}, {%4,%5,%6,%7}, {%8,%9}, {%0,%1,%2,%3};"
        : "+f"(c[0]), "+f"(c[1]), "+f"(c[2]), "+f"(c[3])
        : "r"(a[0]), "r"(a[1]), "r"(a[2]), "r"(a[3]), "r"(b[0]), "r"(b[1]));
}

// ---------------- weight prep: fp32 [K][N] -> bf16 [N][K] (+ plain converts) --------
__global__ void __launch_bounds__(256) prep_weights_kernel(
    const float* __restrict__ q1, const float* __restrict__ k1, const float* __restrict__ v1,
    const float* __restrict__ o1, const float* __restrict__ q2, const float* __restrict__ o2,
    const float* __restrict__ ff1, const float* __restrict__ ff2,
    const float* __restrict__ pin, const float* __restrict__ pout)
{
    int b = blockIdx.x;
    int tx = threadIdx.x & 31, ty = threadIdx.x >> 5;   // 32 x 8
    if (b < 1800) {
        __shared__ float sm[32][33];
        const float* src; bf16* dst; int R, C, tile;
        if (b < 100)       { src = q1;  dst = g_wqkv;            R = 320;  C = 320;  tile = b; }
        else if (b < 200)  { src = k1;  dst = g_wqkv + 320*320;  R = 320;  C = 320;  tile = b - 100; }
        else if (b < 300)  { src = v1;  dst = g_wqkv + 640*320;  R = 320;  C = 320;  tile = b - 200; }
        else if (b < 400)  { src = o1;  dst = g_wo1;             R = 320;  C = 320;  tile = b - 300; }
        else if (b < 500)  { src = q2;  dst = g_wq2;             R = 320;  C = 320;  tile = b - 400; }
        else if (b < 600)  { src = o2;  dst = g_wo2;             R = 320;  C = 320;  tile = b - 500; }
        else if (b < 1400) { src = ff1; dst = g_wff1;            R = 320;  C = 2560; tile = b - 600; }
        else               { src = ff2; dst = g_wff2;            R = 1280; C = 320;  tile = b - 1400; }
        int tc = C / 32;
        int r0 = (tile / tc) * 32, c0 = (tile % tc) * 32;
        #pragma unroll
        for (int i = 0; i < 4; i++)
            sm[ty + 8 * i][tx] = src[(size_t)(r0 + ty + 8 * i) * C + c0 + tx];
        __syncthreads();
        #pragma unroll
        for (int i = 0; i < 4; i++)
            dst[(size_t)(c0 + ty + 8 * i) * R + r0 + tx] = __float2bfloat16(sm[tx][ty + 8 * i]);
    } else {
        const float* src = (b < 1900) ? pin : pout;
        bf16* dst = (b < 1900) ? g_wpin : g_wpout;
        int seg = b - ((b < 1900) ? 1800 : 1900);
        int base = seg * 1024 + threadIdx.x * 4;
        #pragma unroll
        for (int j = 0; j < 4; j++)
            dst[base + j] = __float2bfloat16(src[base + j]);
    }
}

// ---------------- GroupNorm stats ----------------
__global__ void gn_stats_kernel(const float* __restrict__ x) {
    int g = blockIdx.x;
    const float* p = x + g * (10 * N_TOK);
    float s = 0.f, s2 = 0.f;
    for (int i = threadIdx.x; i < 10 * N_TOK; i += 256) {
        float v = p[i];
        s += v; s2 += v * v;
    }
    __shared__ float sh1[8], sh2[8];
    int lane = threadIdx.x & 31, w = threadIdx.x >> 5;
    #pragma unroll
    for (int o = 16; o; o >>= 1) {
        s  += __shfl_xor_sync(0xffffffffu, s,  o);
        s2 += __shfl_xor_sync(0xffffffffu, s2, o);
    }
    if (lane == 0) { sh1[w] = s; sh2[w] = s2; }
    __syncthreads();
    if (threadIdx.x == 0) {
        s = 0.f; s2 = 0.f;
        #pragma unroll
        for (int i = 0; i < 8; i++) { s += sh1[i]; s2 += sh2[i]; }
        float m   = s  * (1.f / (10 * N_TOK));
        float var = s2 * (1.f / (10 * N_TOK)) - m * m;
        g_mu[g] = m;
        g_rs[g] = rsqrtf(var + 1e-6f);
    }
}

// ---------------- GN apply + transpose -> bf16 token-major ----------------
__global__ void gn_apply_t_kernel(const float* __restrict__ x,
                                  const float* __restrict__ w,
                                  const float* __restrict__ b,
                                  bf16* __restrict__ out) {
    __shared__ float t[32][33];
    int p0 = blockIdx.x * 32, c0 = blockIdx.y * 32;
    int c = c0 + threadIdx.y, p = p0 + threadIdx.x;
    int g = c / 10;
    float v = (x[c * N_TOK + p] - g_mu[g]) * g_rs[g] * w[c] + b[c];
    t[threadIdx.y][threadIdx.x] = v;
    __syncthreads();
    out[(p0 + threadIdx.y) * D + c0 + threadIdx.x] = __float2bfloat16(t[threadIdx.x][threadIdx.y]);
}

// ---------------- LayerNorm (fp32 in, bf16 out) ----------------
__global__ void layernorm_kernel(const float* __restrict__ in,
                                 const float* __restrict__ w,
                                 const float* __restrict__ b,
                                 bf16* __restrict__ out) {
    int row = blockIdx.x;
    const float* p = in + row * D;
    int t = threadIdx.x;
    float a0 = p[t], a1 = p[t + 128];
    float a2 = (t < 64) ? p[t + 256] : 0.f;
    float s  = a0 + a1 + a2;
    float s2 = a0 * a0 + a1 * a1 + a2 * a2;
    __shared__ float sh1[4], sh2[4];
    __shared__ float mr[2];
    int lane = t & 31, wp = t >> 5;
    #pragma unroll
    for (int o = 16; o; o >>= 1) {
        s  += __shfl_xor_sync(0xffffffffu, s,  o);
        s2 += __shfl_xor_sync(0xffffffffu, s2, o);
    }
    if (lane == 0) { sh1[wp] = s; sh2[wp] = s2; }
    __syncthreads();
    if (t == 0) {
        s = sh1[0] + sh1[1] + sh1[2] + sh1[3];
        s2 = sh2[0] + sh2[1] + sh2[2] + sh2[3];
        float m = s * (1.f / D);
        float var = s2 * (1.f / D) - m * m;
        mr[0] = m; mr[1] = rsqrtf(var + 1e-5f);
    }
    __syncthreads();
    float m = mr[0], r = mr[1];
    bf16* o = out + row * D;
    o[t]       = __float2bfloat16((a0 - m) * r * w[t]       + b[t]);
    o[t + 128] = __float2bfloat16((a1 - m) * r * w[t + 128] + b[t + 128]);
    if (t < 64)
        o[t + 256] = __float2bfloat16((a2 - m) * r * w[t + 256] + b[t + 256]);
}

// ---------------- bf16 NT GEMM: C[M,N] = A[M,K] @ Bt[N,K]^T ------------------------
// EPI 0: C fp32 = AB + bias
// EPI 1: C fp32 = AB + bias + R
// EPI 2: C fp32 [n*M+m] = AB + bias[n] + R[n*M+m]
// EPI 3: Cb bf16 = AB (+bias)
// EPI 4: C fp32 = AB + bias + R;  Cb bf16 = same
template <int EPI>
__global__ void __launch_bounds__(128) gemm_bf16_kernel(
    const bf16* __restrict__ A, const bf16* __restrict__ Bt,
    const float* __restrict__ bias, const float* __restrict__ R,
    float* __restrict__ C, bf16* __restrict__ Cb, int M, int N, int K)
{
    __shared__ __align__(16) bf16 As[64][40];
    __shared__ __align__(16) bf16 Bs[64][40];
    int tid = threadIdx.x;
    int lane = tid & 31, wid = tid >> 5;
    int wm = wid & 1, wn = wid >> 1;
    int g = lane >> 2, t = lane & 3;
    int bm = blockIdx.y * 64, bn = blockIdx.x * 64;

    float acc[2][4][4];
    #pragma unroll
    for (int mf = 0; mf < 2; mf++)
        #pragma unroll
        for (int nf = 0; nf < 4; nf++)
            #pragma unroll
            for (int r = 0; r < 4; r++) acc[mf][nf][r] = 0.f;

    int lrow = tid >> 1;
    int lcol = (tid & 1) * 16;
    const bf16* Ap = A + (size_t)(bm + lrow) * K + lcol;
    const bf16* Bp = Bt + (size_t)(bn + lrow) * K + lcol;

    uint2 ra[4], rb[4];
    #pragma unroll
    for (int j = 0; j < 4; j++) {
        ra[j] = *(const uint2*)(Ap + j * 4);
        rb[j] = *(const uint2*)(Bp + j * 4);
    }

    for (int k0 = 0; k0 < K; k0 += 32) {
        #pragma unroll
        for (int j = 0; j < 4; j++) {
            *(uint2*)&As[lrow][lcol + j * 4] = ra[j];
            *(uint2*)&Bs[lrow][lcol + j * 4] = rb[j];
        }
        __syncthreads();
        if (k0 + 32 < K) {
            Ap += 32; Bp += 32;
            #pragma unroll
            for (int j = 0; j < 4; j++) {
                ra[j] = *(const uint2*)(Ap + j * 4);
                rb[j] = *(const uint2*)(Bp + j * 4);
            }
        }
        #pragma unroll
        for (int kk = 0; kk < 2; kk++) {
            uint32_t a[2][4], b[4][2];
            #pragma unroll
            for (int mf = 0; mf < 2; mf++) {
                int r = wm * 32 + mf * 16;
                a[mf][0] = *(const uint32_t*)&As[r + g    ][kk * 16 + 2 * t];
                a[mf][1] = *(const uint32_t*)&As[r + g + 8][kk * 16 + 2 * t];
                a[mf][2] = *(const uint32_t*)&As[r + g    ][kk * 16 + 2 * t + 8];
                a[mf][3] = *(const uint32_t*)&As[r + g + 8][kk * 16 + 2 * t + 8];
            }
            #pragma unroll
            for (int nf = 0; nf < 4; nf++) {
                int n = wn * 32 + nf * 8 + g;
                b[nf][0] = *(const uint32_t*)&Bs[n][kk * 16 + 2 * t];
                b[nf][1] = *(const uint32_t*)&Bs[n][kk * 16 + 2 * t + 8];
            }
            #pragma unroll
            for (int mf = 0; mf < 2; mf++)
                #pragma unroll
                for (int nf = 0; nf < 4; nf++)
                    mma_bf16(acc[mf][nf], a[mf], b[nf]);
        }
        __syncthreads();
    }

    #pragma unroll
    for (int mf = 0; mf < 2; mf++) {
        #pragma unroll
        for (int nf = 0; nf < 4; nf++) {
            int m = bm + wm * 32 + mf * 16 + g;
            int n = bn + wn * 32 + nf * 8 + 2 * t;
            float b0 = bias ? bias[n] : 0.f;
            float b1 = bias ? bias[n + 1] : 0.f;
            float v0 = acc[mf][nf][0] + b0;
            float v1 = acc[mf][nf][1] + b1;
            float v2 = acc[mf][nf][2] + b0;
            float v3 = acc[mf][nf][3] + b1;
            if (EPI == 2) {
                C[(size_t)n * M + m]           = v0 + R[(size_t)n * M + m];
                C[(size_t)(n + 1) * M + m]     = v1 + R[(size_t)(n + 1) * M + m];
                C[(size_t)n * M + m + 8]       = v2 + R[(size_t)n * M + m + 8];
                C[(size_t)(n + 1) * M + m + 8] = v3 + R[(size_t)(n + 1) * M + m + 8];
            } else if (EPI == 3) {
                *(uint32_t*)&Cb[(size_t)m * N + n]       = bf2pk(v0, v1);
                *(uint32_t*)&Cb[(size_t)(m + 8) * N + n] = bf2pk(v2, v3);
            } else {
                if (EPI == 1 || EPI == 4) {
                    float2 r0 = *(const float2*)&R[(size_t)m * N + n];
                    float2 r1 = *(const float2*)&R[(size_t)(m + 8) * N + n];
                    v0 += r0.x; v1 += r0.y; v2 += r1.x; v3 += r1.y;
                }
                *(float2*)&C[(size_t)m * N + n]       = make_float2(v0, v1);
                *(float2*)&C[(size_t)(m + 8) * N + n] = make_float2(v2, v3);
                if (EPI == 4) {
                    *(uint32_t*)&Cb[(size_t)m * N + n]       = bf2pk(v0, v1);
                    *(uint32_t*)&Cb[(size_t)(m + 8) * N + n] = bf2pk(v2, v3);
                }
            }
        }
    }
}

// ---------------- V transpose: qkvb cols [640,960) -> vTb [320][4096] ----------------
__global__ void __launch_bounds__(256) vT_kernel() {
    __shared__ bf16 sm[32][33];
    int b = blockIdx.x;                 // 128 m-tiles x 10 n-tiles
    int m0 = (b / 10) * 32, n0 = (b % 10) * 32;
    int tx = threadIdx.x & 31, ty = threadIdx.x >> 5;
    #pragma unroll
    for (int i = 0; i < 4; i++)
        sm[ty + 8 * i][tx] = g_qkvb[(size_t)(m0 + ty + 8 * i) * 960 + 640 + n0 + tx];
    __syncthreads();
    #pragma unroll
    for (int i = 0; i < 4; i++)
        g_vTb[(size_t)(n0 + ty + 8 * i) * N_TOK + m0 + tx] = sm[tx][ty + 8 * i];
}

// ---------------- bf16 flash self-attention -----------------------------------------
// grid (64, 8), 128 threads = 4 warps; warp w owns query rows [w*16, w*16+16)
__global__ void __launch_bounds__(128) flash_bf16_kernel(
    const bf16* __restrict__ QKV, const bf16* __restrict__ VT, bf16* __restrict__ O)
{
    __shared__ __align__(16) bf16 Ks[64][56];
    __shared__ __align__(16) bf16 VsT[40][72];
    __shared__ __align__(16) bf16 Ps[64][72];
    int h = blockIdx.y;
    int q0 = blockIdx.x * 64;
    int tid = threadIdx.x, wid = tid >> 5, lane = tid & 31;
    int g = lane >> 2, t = lane & 3;
    const float scale = 0.15811388300841897f;

    // zero-fill Ks pad cols [40,56)
    for (int i = tid; i < 512; i += 128) {
        int r = i >> 3, c = 40 + (i & 7) * 2;
        *(uint32_t*)&Ks[r][c] = 0u;
    }

    // Q fragments (k padded to 48, zeros beyond 40)
    uint32_t qa[3][4];
    {
        const bf16* qb = QKV + (size_t)(q0 + wid * 16) * 960 + h * 40;
        #pragma unroll
        for (int kk = 0; kk < 3; kk++) {
            int d = kk * 16 + 2 * t;
            qa[kk][0] = *(const uint32_t*)(qb + (size_t)g * 960 + d);
            qa[kk][1] = *(const uint32_t*)(qb + (size_t)(g + 8) * 960 + d);
            if (kk < 2) {
                qa[kk][2] = *(const uint32_t*)(qb + (size_t)g * 960 + d + 8);
                qa[kk][3] = *(const uint32_t*)(qb + (size_t)(g + 8) * 960 + d + 8);
            } else {
                qa[kk][2] = 0u; qa[kk][3] = 0u;
            }
        }
    }

    float o[5][4];
    #pragma unroll
    for (int nf = 0; nf < 5; nf++)
        #pragma unroll
        for (int r = 0; r < 4; r++) o[nf][r] = 0.f;
    float mA = -1e30f, mB = -1e30f, lA = 0.f, lB = 0.f;

    for (int k0 = 0; k0 < N_TOK; k0 += 64) {
        __syncthreads();
        // K tile: 64 rows x 40 cols, 8B chunks
        #pragma unroll
        for (int i = 0; i < 5; i++) {
            int idx = tid + i * 128;         // 640 chunks
            int r = idx / 10, c = (idx % 10) * 4;
            *(uint2*)&Ks[r][c] =
                *(const uint2*)(QKV + (size_t)(k0 + r) * 960 + 320 + h * 40 + c);
        }
        // V^T tile: 40 rows x 64 keys
        #pragma unroll
        for (int i = 0; i < 5; i++) {
            int idx = tid + i * 128;         // 640 chunks
            int r = idx >> 4, c = (idx & 15) * 4;
            *(uint2*)&VsT[r][c] =
                *(const uint2*)(VT + (size_t)(h * 40 + r) * N_TOK + k0 + c);
        }
        __syncthreads();

        // S = Q K^T  (k = 48 padded)
        float s[8][4];
        #pragma unroll
        for (int nf = 0; nf < 8; nf++)
            #pragma unroll
            for (int r = 0; r < 4; r++) s[nf][r] = 0.f;
        #pragma unroll
        for (int kk = 0; kk < 3; kk++) {
            #pragma unroll
            for (int nf = 0; nf < 8; nf++) {
                uint32_t bb[2];
                bb[0] = *(const uint32_t*)&Ks[nf * 8 + g][kk * 16 + 2 * t];
                bb[1] = *(const uint32_t*)&Ks[nf * 8 + g][kk * 16 + 2 * t + 8];
                mma_bf16(s[nf], qa[kk], bb);
            }
        }
        #pragma unroll
        for (int nf = 0; nf < 8; nf++)
            #pragma unroll
            for (int r = 0; r < 4; r++) s[nf][r] *= scale;

        // online softmax
        float mtA = mA, mtB = mB;
        #pragma unroll
        for (int nf = 0; nf < 8; nf++) {
            mtA = fmaxf(mtA, fmaxf(s[nf][0], s[nf][1]));
            mtB = fmaxf(mtB, fmaxf(s[nf][2], s[nf][3]));
        }
        mtA = fmaxf(mtA, __shfl_xor_sync(0xffffffffu, mtA, 1));
        mtA = fmaxf(mtA, __shfl_xor_sync(0xffffffffu, mtA, 2));
        mtB = fmaxf(mtB, __shfl_xor_sync(0xffffffffu, mtB, 1));
        mtB = fmaxf(mtB, __shfl_xor_sync(0xffffffffu, mtB, 2));
        float corrA = exp2f((mA - mtA) * LOG2E);
        float corrB = exp2f((mB - mtB) * LOG2E);
        mA = mtA; mB = mtB;
        lA *= corrA; lB *= corrB;
        #pragma unroll
        for (int nf = 0; nf < 5; nf++) {
            o[nf][0] *= corrA; o[nf][1] *= corrA;
            o[nf][2] *= corrB; o[nf][3] *= corrB;
        }
        int pr = wid * 16 + g;
        #pragma unroll
        for (int nf = 0; nf < 8; nf++) {
            float p0 = exp2f((s[nf][0] - mA) * LOG2E);
            float p1 = exp2f((s[nf][1] - mA) * LOG2E);
            float p2 = exp2f((s[nf][2] - mB) * LOG2E);
            float p3 = exp2f((s[nf][3] - mB) * LOG2E);
            lA += p0 + p1; lB += p2 + p3;
            *(uint32_t*)&Ps[pr][nf * 8 + 2 * t]     = bf2pk(p0, p1);
            *(uint32_t*)&Ps[pr + 8][nf * 8 + 2 * t] = bf2pk(p2, p3);
        }
        __syncwarp();

        // O += P V   (k = 64 keys)
        #pragma unroll
        for (int kk = 0; kk < 4; kk++) {
            uint32_t pa[4];
            pa[0] = *(const uint32_t*)&Ps[wid * 16 + g    ][kk * 16 + 2 * t];
            pa[1] = *(const uint32_t*)&Ps[wid * 16 + g + 8][kk * 16 + 2 * t];
            pa[2] = *(const uint32_t*)&Ps[wid * 16 + g    ][kk * 16 + 2 * t + 8];
            pa[3] = *(const uint32_t*)&Ps[wid * 16 + g + 8][kk * 16 + 2 * t + 8];
            #pragma unroll
            for (int nf = 0; nf < 5; nf++) {
                uint32_t bb[2];
                bb[0] = *(const uint32_t*)&VsT[nf * 8 + g][kk * 16 + 2 * t];
                bb[1] = *(const uint32_t*)&VsT[nf * 8 + g][kk * 16 + 2 * t + 8];
                mma_bf16(o[nf], pa, bb);
            }
        }
    }

    lA += __shfl_xor_sync(0xffffffffu, lA, 1);
    lA += __shfl_xor_sync(0xffffffffu, lA, 2);
    lB += __shfl_xor_sync(0xffffffffu, lB, 1);
    lB += __shfl_xor_sync(0xffffffffu, lB, 2);
    float iA = 1.f / lA, iB = 1.f / lB;
    bf16* ob = O + (size_t)(q0 + wid * 16 + g) * D + h * 40;
    #pragma unroll
    for (int nf = 0; nf < 5; nf++) {
        *(uint32_t*)(ob + nf * 8 + 2 * t) = bf2pk(o[nf][0] * iA, o[nf][1] * iA);
        *(uint32_t*)(ob + (size_t)8 * D + nf * 8 + 2 * t) = bf2pk(o[nf][2] * iB, o[nf][3] * iB);
    }
}

// ---------------- scalar fp32 GEMM (ctx K/V only, M=77) ----------------
__global__ void __launch_bounds__(256) gemm_kernel(
    const float* __restrict__ A, const float* __restrict__ B,
    float* __restrict__ C, int M, int N, int K)
{
    __shared__ __align__(16) float As[16][68];
    __shared__ __align__(16) float Bs[16][64];
    int bm = blockIdx.y * 64, bn = blockIdx.x * 64;
    int tid = threadIdx.x;
    int tx = tid & 15, ty = tid >> 4;

    float acc[4][4];
    #pragma unroll
    for (int i = 0; i < 4; i++)
        #pragma unroll
        for (int j = 0; j < 4; j++) acc[i][j] = 0.f;

    int amr = tid >> 2;
    int akc = (tid & 3) * 4;
    int bkr = tid >> 4;
    int bnc = (tid & 15) * 4;
    bool avalid = (bm + amr) < M;
    const float* Aptr = A + (size_t)(bm + amr) * K + akc;
    const float* Bptr = B + (size_t)bkr * N + bn + bnc;

    for (int k0 = 0; k0 < K; k0 += 16) {
        float4 av = avalid ? *(const float4*)Aptr : make_float4(0.f, 0.f, 0.f, 0.f);
        float4 bv = *(const float4*)Bptr;
        As[akc + 0][amr] = av.x;
        As[akc + 1][amr] = av.y;
        As[akc + 2][amr] = av.z;
        As[akc + 3][amr] = av.w;
        *(float4*)&Bs[bkr][bnc] = bv;
        __syncthreads();
        #pragma unroll
        for (int kk = 0; kk < 16; kk++) {
            float4 a = *(const float4*)&As[kk][ty * 4];
            float4 b = *(const float4*)&Bs[kk][tx * 4];
            acc[0][0] += a.x * b.x; acc[0][1] += a.x * b.y; acc[0][2] += a.x * b.z; acc[0][3] += a.x * b.w;
            acc[1][0] += a.y * b.x; acc[1][1] += a.y * b.y; acc[1][2] += a.y * b.z; acc[1][3] += a.y * b.w;
            acc[2][0] += a.z * b.x; acc[2][1] += a.z * b.y; acc[2][2] += a.z * b.z; acc[2][3] += a.z * b.w;
            acc[3][0] += a.w * b.x; acc[3][1] += a.w * b.y; acc[3][2] += a.w * b.z; acc[3][3] += a.w * b.w;
        }
        __syncthreads();
        Aptr += 16;
        Bptr += (size_t)16 * N;
    }

    #pragma unroll
    for (int i = 0; i < 4; i++) {
        int m = bm + ty * 4 + i;
        if (m >= M) continue;
        #pragma unroll
        for (int j = 0; j < 4; j++)
            C[(size_t)m * N + bn + tx * 4 + j] = acc[i][j];
    }
}

// ---------------- cross attention (scalar; Q bf16, 77 keys) -------------------------
__global__ void __launch_bounds__(128) cross_attn_kernel(
    const bf16* __restrict__ Q, const float* __restrict__ Kc,
    const float* __restrict__ Vc, bf16* __restrict__ O)
{
    const float scale = 0.15811388300841897f;
    int h = blockIdx.y;
    int qrow = blockIdx.x * 128 + threadIdx.x;
    int tid = threadIdx.x;

    __shared__ __align__(16) float Ks[CTX_N][40];
    __shared__ __align__(16) float Vs[CTX_N][40];
    for (int i = tid; i < CTX_N * 10; i += 128) {
        int r = i / 10, c = (i % 10) * 4;
        *(float4*)&Ks[r][c] = *(const float4*)(Kc + (size_t)r * D + h * DH + c);
        *(float4*)&Vs[r][c] = *(const float4*)(Vc + (size_t)r * D + h * DH + c);
    }
    __syncthreads();

    float4 q4[10], a4[10];
    const bf16* qp = Q + (size_t)qrow * D + h * DH;
    #pragma unroll
    for (int dd = 0; dd < 10; dd++) {
        __nv_bfloat162 b0 = *(const __nv_bfloat162*)(qp + dd * 4);
        __nv_bfloat162 b1 = *(const __nv_bfloat162*)(qp + dd * 4 + 2);
        q4[dd] = make_float4(__low2float(b0) * scale, __high2float(b0) * scale,
                             __low2float(b1) * scale, __high2float(b1) * scale);
        a4[dd] = make_float4(0.f, 0.f, 0.f, 0.f);
    }
    float m = -1e30f, l = 0.f;
    for (int j = 0; j < CTX_N; j++) {
        float s = 0.f;
        #pragma unroll
        for (int dd = 0; dd < 10; dd++) {
            float4 kk = *(const float4*)&Ks[j][dd * 4];
            s += q4[dd].x * kk.x + q4[dd].y * kk.y + q4[dd].z * kk.z + q4[dd].w * kk.w;
        }
        float mt = fmaxf(m, s);
        float corr = __expf(m - mt);
        float p = __expf(s - mt);
        m = mt;
        l = l * corr + p;
        #pragma unroll
        for (int dd = 0; dd < 10; dd++) {
            float4 vv = *(const float4*)&Vs[j][dd * 4];
            a4[dd].x = a4[dd].x * corr + p * vv.x;
            a4[dd].y = a4[dd].y * corr + p * vv.y;
            a4[dd].z = a4[dd].z * corr + p * vv.z;
            a4[dd].w = a4[dd].w * corr + p * vv.w;
        }
    }
    float inv = 1.f / l;
    bf16* op = O + (size_t)qrow * D + h * DH;
    #pragma unroll
    for (int dd = 0; dd < 10; dd++) {
        *(uint32_t*)(op + dd * 4)     = bf2pk(a4[dd].x * inv, a4[dd].y * inv);
        *(uint32_t*)(op + dd * 4 + 2) = bf2pk(a4[dd].z * inv, a4[dd].w * inv);
    }
}

// ---------------- GEGLU (bf16 in/out) ----------------
__global__ void geglu_kernel(const bf16* __restrict__ H, bf16* __restrict__ G) {
    int idx2 = blockIdx.x * 256 + threadIdx.x;       // over N_TOK * FFI/2
    int r = idx2 / (FFI / 2), c = (idx2 % (FFI / 2)) * 2;
    __nv_bfloat162 ap = *(const __nv_bfloat162*)&H[(size_t)r * (2 * FFI) + c];
    __nv_bfloat162 gp = *(const __nv_bfloat162*)&H[(size_t)r * (2 * FFI) + FFI + c];
    float a0 = __low2float(ap), a1 = __high2float(ap);
    float g0 = __low2float(gp), g1 = __high2float(gp);
    float e0 = 0.5f * g0 * (1.f + erff(g0 * 0.70710678118654752f));
    float e1 = 0.5f * g1 * (1.f + erff(g1 * 0.70710678118654752f));
    *(uint32_t*)&G[(size_t)r * FFI + c] = bf2pk(a0 * e0, a1 * e1);
}

// ---------------- launch ----------------
extern "C" void kernel_launch(void* const* d_in, const int* in_sizes, int n_in,
                              void* d_out, int out_size) {
    const float* x      = (const float*)d_in[0];
    const float* ctx    = (const float*)d_in[1];
    const float* gn_w   = (const float*)d_in[2];
    const float* gn_b   = (const float*)d_in[3];
    const float* pin_w  = (const float*)d_in[4];
    const float* pin_b  = (const float*)d_in[5];
    const float* ln1_w  = (const float*)d_in[6];
    const float* ln1_b  = (const float*)d_in[7];
    const float* q1     = (const float*)d_in[8];
    const float* k1     = (const float*)d_in[9];
    const float* v1     = (const float*)d_in[10];
    const float* o1_w   = (const float*)d_in[11];
    const float* o1_b   = (const float*)d_in[12];
    const float* ln2_w  = (const float*)d_in[13];
    const float* ln2_b  = (const float*)d_in[14];
    const float* q2     = (const float*)d_in[15];
    const float* k2     = (const float*)d_in[16];
    const float* v2     = (const float*)d_in[17];
    const float* o2_w   = (const float*)d_in[18];
    const float* o2_b   = (const float*)d_in[19];
    const float* ln3_w  = (const float*)d_in[20];
    const float* ln3_b  = (const float*)d_in[21];
    const float* ff1_w  = (const float*)d_in[22];
    const float* ff1_b  = (const float*)d_in[23];
    const float* ff2_w  = (const float*)d_in[24];
    const float* ff2_b  = (const float*)d_in[25];
    const float* pout_w = (const float*)d_in[26];
    const float* pout_b = (const float*)d_in[27];
    float* out = (float*)d_out;

    float *p_h, *p_h2, *p_kc, *p_vc;
    bf16 *p_lnb, *p_qkvb, *p_vTb, *p_attnb, *p_q2b, *p_h2b, *p_ffhb, *p_ffgb;
    bf16 *p_wqkv, *p_wo1, *p_wq2, *p_wo2, *p_wff1, *p_wff2, *p_wpin, *p_wpout;
    cudaGetSymbolAddress((void**)&p_h,    g_h);
    cudaGetSymbolAddress((void**)&p_h2,   g_h2);
    cudaGetSymbolAddress((void**)&p_kc,   g_kc);
    cudaGetSymbolAddress((void**)&p_vc,   g_vc);
    cudaGetSymbolAddress((void**)&p_lnb,  g_lnb);
    cudaGetSymbolAddress((void**)&p_qkvb, g_qkvb);
    cudaGetSymbolAddress((void**)&p_vTb,  g_vTb);
    cudaGetSymbolAddress((void**)&p_attnb,g_attnb);
    cudaGetSymbolAddress((void**)&p_q2b,  g_q2b);
    cudaGetSymbolAddress((void**)&p_h2b,  g_h2b);
    cudaGetSymbolAddress((void**)&p_ffhb, g_ffhb);
    cudaGetSymbolAddress((void**)&p_ffgb, g_ffgb);
    cudaGetSymbolAddress((void**)&p_wqkv, g_wqkv);
    cudaGetSymbolAddress((void**)&p_wo1,  g_wo1);
    cudaGetSymbolAddress((void**)&p_wq2,  g_wq2);
    cudaGetSymbolAddress((void**)&p_wo2,  g_wo2);
    cudaGetSymbolAddress((void**)&p_wff1, g_wff1);
    cudaGetSymbolAddress((void**)&p_wff2, g_wff2);
    cudaGetSymbolAddress((void**)&p_wpin, g_wpin);
    cudaGetSymbolAddress((void**)&p_wpout,g_wpout);

    dim3 t32(32, 32);
    dim3 gD(D / 64, N_TOK / 64);            // (5, 64)

    // weight prep + GroupNorm
    prep_weights_kernel<<<2000, 256>>>(q1, k1, v1, o1_w, q2, o2_w, ff1_w, ff2_w, pin_w, pout_w);
    gn_stats_kernel<<<GROUPS, 256>>>(x);
    gn_apply_t_kernel<<<dim3(128, 10), t32>>>(x, gn_w, gn_b, p_lnb);
    gemm_bf16_kernel<0><<<gD, 128>>>(p_lnb, p_wpin, pin_b, nullptr, p_h, nullptr, N_TOK, D, D);

    // self-attention
    layernorm_kernel<<<N_TOK, 128>>>(p_h, ln1_w, ln1_b, p_lnb);
    gemm_bf16_kernel<3><<<dim3(3 * D / 64, N_TOK / 64), 128>>>(p_lnb, p_wqkv, nullptr, nullptr, nullptr, p_qkvb, N_TOK, 3 * D, D);
    vT_kernel<<<1280, 256>>>();
    flash_bf16_kernel<<<dim3(N_TOK / 64, HEADS), 128>>>(p_qkvb, p_vTb, p_attnb);
    gemm_bf16_kernel<1><<<gD, 128>>>(p_attnb, p_wo1, o1_b, p_h, p_h2, nullptr, N_TOK, D, D);

    // cross-attention
    layernorm_kernel<<<N_TOK, 128>>>(p_h2, ln2_w, ln2_b, p_lnb);
    gemm_bf16_kernel<3><<<gD, 128>>>(p_lnb, p_wq2, nullptr, nullptr, nullptr, p_q2b, N_TOK, D, D);
    gemm_kernel<<<dim3(5, 2), 256>>>(ctx, k2, p_kc, CTX_N, D, CTX_D);
    gemm_kernel<<<dim3(5, 2), 256>>>(ctx, v2, p_vc, CTX_N, D, CTX_D);
    cross_attn_kernel<<<dim3(N_TOK / 128, HEADS), 128>>>(p_q2b, p_kc, p_vc, p_attnb);
    gemm_bf16_kernel<1><<<gD, 128>>>(p_attnb, p_wo2, o2_b, p_h2, p_h, nullptr, N_TOK, D, D);

    // GEGLU FF
    layernorm_kernel<<<N_TOK, 128>>>(p_h, ln3_w, ln3_b, p_lnb);
    gemm_bf16_kernel<3><<<dim3(2 * FFI / 64, N_TOK / 64), 128>>>(p_lnb, p_wff1, ff1_b, nullptr, nullptr, p_ffhb, N_TOK, 2 * FFI, D);
    geglu_kernel<<<(N_TOK * FFI / 2) / 256, 256>>>(p_ffhb, p_ffgb);
    gemm_bf16_kernel<4><<<gD, 128>>>(p_ffgb, p_wff2, ff2_b, p_h, p_h2, p_h2b, N_TOK, D, FFI);

    // proj_out + residual (transposed store back to [C][HW])
    gemm_bf16_kernel<2><<<gD, 128>>>(p_h2b, p_wpout, pout_b, x, out, nullptr, N_TOK, D, D);
}

// round 6
// speedup vs baseline: 4.2812x; 1.4264x over previous
#include <cuda_runtime.h>
#include <cuda_bf16.h>
#include <math.h>
#include <stdint.h>

#define N_TOK 4096
#define D     320
#define HEADS 8
#define DH    40
#define CTX_N 77
#define CTX_M 96
#define CTX_D 768
#define FFI   1280
#define GROUPS 32
#define LOG2E 1.4426950408889634f

typedef __nv_bfloat16 bf16;

// ---------------- scratch ----------------
__device__ float g_h  [N_TOK * D];
__device__ float g_h2 [N_TOK * D];
__device__ float g_kc [CTX_M * D];
__device__ float g_vc [CTX_M * D];
__device__ float g_mu [GROUPS];
__device__ float g_rs [GROUPS];

__device__ bf16 g_lnb [N_TOK * D];
__device__ bf16 g_qkvb[N_TOK * 3 * D];
__device__ bf16 g_vTb [D * N_TOK];
__device__ bf16 g_attnb[N_TOK * D];
__device__ bf16 g_q2b [N_TOK * D];
__device__ bf16 g_h2b [N_TOK * D];
__device__ bf16 g_ffhb[N_TOK * 2 * FFI];
__device__ bf16 g_ffgb[N_TOK * FFI];
__device__ bf16 g_ctxb[CTX_M * CTX_D];

// weights, bf16, stored as B^T = [N][K]
__device__ bf16 g_wqkv[3 * D * D];
__device__ bf16 g_wo1 [D * D];
__device__ bf16 g_wq2 [D * D];
__device__ bf16 g_wo2 [D * D];
__device__ bf16 g_wff1[2 * FFI * D];
__device__ bf16 g_wff2[D * FFI];
__device__ bf16 g_wpin[D * D];
__device__ bf16 g_wpout[D * D];
__device__ bf16 g_wk2 [D * CTX_D];
__device__ bf16 g_wv2 [D * CTX_D];

// ---------------- helpers ----------------
__device__ __forceinline__ uint32_t bf2pk(float lo, float hi) {
    uint32_t r;
    asm("cvt.rn.bf16x2.f32 %0, %1, %2;" : "=r"(r) : "f"(hi), "f"(lo));
    return r;
}
__device__ __forceinline__ void mma_bf16(float* c, const uint32_t* a, const uint32_t* b) {
    asm volatile(
        "mma.sync.aligned.m16n8k16.row.col.f32.bf16.bf16.f32 "
        "{%0,%1,%2,%3}, {%4,%5,%6,%7}, {%8,%9}, {%0,%1,%2,%3};"
        : "+f"(c[0]), "+f"(c[1]), "+f"(c[2]), "+f"(c[3])
        : "r"(a[0]), "r"(a[1]), "r"(a[2]), "r"(a[3]), "r"(b[0]), "r"(b[1]));
}
__device__ __forceinline__ uint32_t smem_u32(const void* p) {
    return (uint32_t)__cvta_generic_to_shared(p);
}
__device__ __forceinline__ void cp16(uint32_t dst, const void* src) {
    asm volatile("cp.async.cg.shared.global [%0], [%1], 16;" :: "r"(dst), "l"(src));
}
__device__ __forceinline__ void cp8(uint32_t dst, const void* src) {
    asm volatile("cp.async.ca.shared.global [%0], [%1], 8;" :: "r"(dst), "l"(src));
}
#define CP_COMMIT() asm volatile("cp.async.commit_group;")
#define CP_WAIT1()  asm volatile("cp.async.wait_group 1;")
#define CP_WAIT0()  asm volatile("cp.async.wait_group 0;")

// ---------------- weight prep: fp32 [K][N] -> bf16 [N][K] (+ plain converts) --------
__global__ void __launch_bounds__(256) prep_weights_kernel(
    const float* __restrict__ q1, const float* __restrict__ k1, const float* __restrict__ v1,
    const float* __restrict__ o1, const float* __restrict__ q2, const float* __restrict__ o2,
    const float* __restrict__ ff1, const float* __restrict__ ff2,
    const float* __restrict__ pin, const float* __restrict__ pout,
    const float* __restrict__ k2, const float* __restrict__ v2)
{
    int b = blockIdx.x;
    int tx = threadIdx.x & 31, ty = threadIdx.x >> 5;   // 32 x 8
    if (b < 2280) {
        __shared__ float sm[32][33];
        const float* src; bf16* dst; int R, C, tile;
        if (b < 100)       { src = q1;  dst = g_wqkv;            R = 320;  C = 320;  tile = b; }
        else if (b < 200)  { src = k1;  dst = g_wqkv + 320*320;  R = 320;  C = 320;  tile = b - 100; }
        else if (b < 300)  { src = v1;  dst = g_wqkv + 640*320;  R = 320;  C = 320;  tile = b - 200; }
        else if (b < 400)  { src = o1;  dst = g_wo1;             R = 320;  C = 320;  tile = b - 300; }
        else if (b < 500)  { src = q2;  dst = g_wq2;             R = 320;  C = 320;  tile = b - 400; }
        else if (b < 600)  { src = o2;  dst = g_wo2;             R = 320;  C = 320;  tile = b - 500; }
        else if (b < 1400) { src = ff1; dst = g_wff1;            R = 320;  C = 2560; tile = b - 600; }
        else if (b < 1800) { src = ff2; dst = g_wff2;            R = 1280; C = 320;  tile = b - 1400; }
        else if (b < 2040) { src = k2;  dst = g_wk2;             R = 768;  C = 320;  tile = b - 1800; }
        else               { src = v2;  dst = g_wv2;             R = 768;  C = 320;  tile = b - 2040; }
        int tc = C / 32;
        int r0 = (tile / tc) * 32, c0 = (tile % tc) * 32;
        #pragma unroll
        for (int i = 0; i < 4; i++)
            sm[ty + 8 * i][tx] = src[(size_t)(r0 + ty + 8 * i) * C + c0 + tx];
        __syncthreads();
        #pragma unroll
        for (int i = 0; i < 4; i++)
            dst[(size_t)(c0 + ty + 8 * i) * R + r0 + tx] = __float2bfloat16(sm[tx][ty + 8 * i]);
    } else {
        const float* src = (b < 2380) ? pin : pout;
        bf16* dst = (b < 2380) ? g_wpin : g_wpout;
        int seg = b - ((b < 2380) ? 2280 : 2380);
        int base = seg * 1024 + threadIdx.x * 4;
        #pragma unroll
        for (int j = 0; j < 4; j++)
            dst[base + j] = __float2bfloat16(src[base + j]);
    }
}

// ---------------- ctx -> bf16, rows padded to 96 with zeros -------------------------
__global__ void __launch_bounds__(256) ctx_conv_kernel(const float* __restrict__ ctx) {
    int i = blockIdx.x * 256 + threadIdx.x;     // over 96*768
    int r = i / CTX_D;
    float v = (r < CTX_N) ? ctx[(size_t)r * CTX_D + (i % CTX_D)] : 0.f;
    g_ctxb[i] = __float2bfloat16(v);
}

// ---------------- GroupNorm stats ----------------
__global__ void gn_stats_kernel(const float* __restrict__ x) {
    int g = blockIdx.x;
    const float* p = x + g * (10 * N_TOK);
    float s = 0.f, s2 = 0.f;
    for (int i = threadIdx.x; i < 10 * N_TOK; i += 256) {
        float v = p[i];
        s += v; s2 += v * v;
    }
    __shared__ float sh1[8], sh2[8];
    int lane = threadIdx.x & 31, w = threadIdx.x >> 5;
    #pragma unroll
    for (int o = 16; o; o >>= 1) {
        s  += __shfl_xor_sync(0xffffffffu, s,  o);
        s2 += __shfl_xor_sync(0xffffffffu, s2, o);
    }
    if (lane == 0) { sh1[w] = s; sh2[w] = s2; }
    __syncthreads();
    if (threadIdx.x == 0) {
        s = 0.f; s2 = 0.f;
        #pragma unroll
        for (int i = 0; i < 8; i++) { s += sh1[i]; s2 += sh2[i]; }
        float m   = s  * (1.f / (10 * N_TOK));
        float var = s2 * (1.f / (10 * N_TOK)) - m * m;
        g_mu[g] = m;
        g_rs[g] = rsqrtf(var + 1e-6f);
    }
}

// ---------------- GN apply + transpose -> bf16 token-major ----------------
__global__ void gn_apply_t_kernel(const float* __restrict__ x,
                                  const float* __restrict__ w,
                                  const float* __restrict__ b,
                                  bf16* __restrict__ out) {
    __shared__ float t[32][33];
    int p0 = blockIdx.x * 32, c0 = blockIdx.y * 32;
    int c = c0 + threadIdx.y, p = p0 + threadIdx.x;
    int g = c / 10;
    float v = (x[c * N_TOK + p] - g_mu[g]) * g_rs[g] * w[c] + b[c];
    t[threadIdx.y][threadIdx.x] = v;
    __syncthreads();
    out[(p0 + threadIdx.y) * D + c0 + threadIdx.x] = __float2bfloat16(t[threadIdx.x][threadIdx.y]);
}

// ---------------- LayerNorm (fp32 in, bf16 out) ----------------
__global__ void layernorm_kernel(const float* __restrict__ in,
                                 const float* __restrict__ w,
                                 const float* __restrict__ b,
                                 bf16* __restrict__ out) {
    int row = blockIdx.x;
    const float* p = in + row * D;
    int t = threadIdx.x;
    float a0 = p[t], a1 = p[t + 128];
    float a2 = (t < 64) ? p[t + 256] : 0.f;
    float s  = a0 + a1 + a2;
    float s2 = a0 * a0 + a1 * a1 + a2 * a2;
    __shared__ float sh1[4], sh2[4];
    __shared__ float mr[2];
    int lane = t & 31, wp = t >> 5;
    #pragma unroll
    for (int o = 16; o; o >>= 1) {
        s  += __shfl_xor_sync(0xffffffffu, s,  o);
        s2 += __shfl_xor_sync(0xffffffffu, s2, o);
    }
    if (lane == 0) { sh1[wp] = s; sh2[wp] = s2; }
    __syncthreads();
    if (t == 0) {
        s = sh1[0] + sh1[1] + sh1[2] + sh1[3];
        s2 = sh2[0] + sh2[1] + sh2[2] + sh2[3];
        float m = s * (1.f / D);
        float var = s2 * (1.f / D) - m * m;
        mr[0] = m; mr[1] = rsqrtf(var + 1e-5f);
    }
    __syncthreads();
    float m = mr[0], r = mr[1];
    bf16* o = out + row * D;
    o[t]       = __float2bfloat16((a0 - m) * r * w[t]       + b[t]);
    o[t + 128] = __float2bfloat16((a1 - m) * r * w[t + 128] + b[t + 128]);
    if (t < 64)
        o[t + 256] = __float2bfloat16((a2 - m) * r * w[t + 256] + b[t + 256]);
}

// ---------------- bf16 NT GEMM, cp.async 3-stage: C[M,N] = A[M,K] @ Bt[N,K]^T -------
// tile 32x64, 128 threads (warps 2x2, warp tile 16x32)
// EPI 0: C fp32 = AB + bias
// EPI 1: C fp32 = AB + bias + R
// EPI 2: C fp32 [n*M+m] = AB + bias[n] + R[n*M+m]
// EPI 3: Cb bf16 = AB (+bias)
// EPI 4: C fp32 = AB + bias + R;  Cb bf16 = same
template <int EPI>
__global__ void __launch_bounds__(128) gemm_bf16_kernel(
    const bf16* __restrict__ A, const bf16* __restrict__ Bt,
    const float* __restrict__ bias, const float* __restrict__ R,
    float* __restrict__ C, bf16* __restrict__ Cb, int M, int N, int K)
{
    __shared__ __align__(16) bf16 As[3][32][40];
    __shared__ __align__(16) bf16 Bs[3][64][40];
    int tid = threadIdx.x;
    int lane = tid & 31, wid = tid >> 5;
    int wm = wid & 1, wn = wid >> 1;
    int g = lane >> 2, t = lane & 3;
    int bm = blockIdx.y * 32, bn = blockIdx.x * 64;

    float acc[4][4];
    #pragma unroll
    for (int nf = 0; nf < 4; nf++)
        #pragma unroll
        for (int r = 0; r < 4; r++) acc[nf][r] = 0.f;

    int ar = tid >> 2, ac = (tid & 3) * 8;      // A: 32 rows x 4 chunks of 8
    int br = tid >> 1, bc = (tid & 1) * 16;     // B: 64 rows x 2 chunks of 16
    const bf16* Abase = A  + (size_t)(bm + ar) * K + ac;
    const bf16* Bbase = Bt + (size_t)(bn + br) * K + bc;
    uint32_t sA = smem_u32(&As[0][ar][ac]);
    uint32_t sB = smem_u32(&Bs[0][br][bc]);
    const int ASS = 32 * 40 * 2, BSS = 64 * 40 * 2;

    int nt = K / 32;
    #pragma unroll
    for (int s = 0; s < 2; s++) {
        cp16(sA + s * ASS, Abase + s * 32);
        cp16(sB + s * BSS, Bbase + s * 32);
        cp16(sB + s * BSS + 16, Bbase + s * 32 + 8);
        CP_COMMIT();
    }

    for (int i = 0; i < nt; i++) {
        if (i + 1 < nt) { CP_WAIT1(); } else { CP_WAIT0(); }
        __syncthreads();
        if (i + 2 < nt) {
            int s = (i + 2) % 3;
            cp16(sA + s * ASS, Abase + (i + 2) * 32);
            cp16(sB + s * BSS, Bbase + (i + 2) * 32);
            cp16(sB + s * BSS + 16, Bbase + (i + 2) * 32 + 8);
            CP_COMMIT();
        }
        int cb = i % 3;
        #pragma unroll
        for (int kk = 0; kk < 2; kk++) {
            uint32_t a[4], b[4][2];
            a[0] = *(const uint32_t*)&As[cb][wm * 16 + g    ][kk * 16 + 2 * t];
            a[1] = *(const uint32_t*)&As[cb][wm * 16 + g + 8][kk * 16 + 2 * t];
            a[2] = *(const uint32_t*)&As[cb][wm * 16 + g    ][kk * 16 + 2 * t + 8];
            a[3] = *(const uint32_t*)&As[cb][wm * 16 + g + 8][kk * 16 + 2 * t + 8];
            #pragma unroll
            for (int nf = 0; nf < 4; nf++) {
                int n = wn * 32 + nf * 8 + g;
                b[nf][0] = *(const uint32_t*)&Bs[cb][n][kk * 16 + 2 * t];
                b[nf][1] = *(const uint32_t*)&Bs[cb][n][kk * 16 + 2 * t + 8];
            }
            #pragma unroll
            for (int nf = 0; nf < 4; nf++)
                mma_bf16(acc[nf], a, b[nf]);
        }
    }

    #pragma unroll
    for (int nf = 0; nf < 4; nf++) {
        int m = bm + wm * 16 + g;
        int n = bn + wn * 32 + nf * 8 + 2 * t;
        float b0 = bias ? bias[n] : 0.f;
        float b1 = bias ? bias[n + 1] : 0.f;
        float v0 = acc[nf][0] + b0;
        float v1 = acc[nf][1] + b1;
        float v2 = acc[nf][2] + b0;
        float v3 = acc[nf][3] + b1;
        if (EPI == 2) {
            C[(size_t)n * M + m]           = v0 + R[(size_t)n * M + m];
            C[(size_t)(n + 1) * M + m]     = v1 + R[(size_t)(n + 1) * M + m];
            C[(size_t)n * M + m + 8]       = v2 + R[(size_t)n * M + m + 8];
            C[(size_t)(n + 1) * M + m + 8] = v3 + R[(size_t)(n + 1) * M + m + 8];
        } else if (EPI == 3) {
            *(uint32_t*)&Cb[(size_t)m * N + n]       = bf2pk(v0, v1);
            *(uint32_t*)&Cb[(size_t)(m + 8) * N + n] = bf2pk(v2, v3);
        } else {
            if (EPI == 1 || EPI == 4) {
                float2 r0 = *(const float2*)&R[(size_t)m * N + n];
                float2 r1 = *(const float2*)&R[(size_t)(m + 8) * N + n];
                v0 += r0.x; v1 += r0.y; v2 += r1.x; v3 += r1.y;
            }
            *(float2*)&C[(size_t)m * N + n]       = make_float2(v0, v1);
            *(float2*)&C[(size_t)(m + 8) * N + n] = make_float2(v2, v3);
            if (EPI == 4) {
                *(uint32_t*)&Cb[(size_t)m * N + n]       = bf2pk(v0, v1);
                *(uint32_t*)&Cb[(size_t)(m + 8) * N + n] = bf2pk(v2, v3);
            }
        }
    }
}

// ---------------- V transpose: qkvb cols [640,960) -> vTb [320][4096] ----------------
__global__ void __launch_bounds__(256) vT_kernel() {
    __shared__ bf16 sm[32][33];
    int b = blockIdx.x;                 // 128 m-tiles x 10 n-tiles
    int m0 = (b / 10) * 32, n0 = (b % 10) * 32;
    int tx = threadIdx.x & 31, ty = threadIdx.x >> 5;
    #pragma unroll
    for (int i = 0; i < 4; i++)
        sm[ty + 8 * i][tx] = g_qkvb[(size_t)(m0 + ty + 8 * i) * 960 + 640 + n0 + tx];
    __syncthreads();
    #pragma unroll
    for (int i = 0; i < 4; i++)
        g_vTb[(size_t)(n0 + ty + 8 * i) * N_TOK + m0 + tx] = sm[tx][ty + 8 * i];
}

// ---------------- bf16 flash self-attention, cp.async 2-stage -----------------------
// grid (64, 8), 128 threads = 4 warps; warp w owns query rows [w*16, w*16+16)
__global__ void __launch_bounds__(128) flash_bf16_kernel(
    const bf16* __restrict__ QKV, const bf16* __restrict__ VT, bf16* __restrict__ O)
{
    __shared__ __align__(16) bf16 Ks[2][64][56];
    __shared__ __align__(16) bf16 VsT[2][40][72];
    __shared__ __align__(16) bf16 Ps[64][72];
    int h = blockIdx.y;
    int q0 = blockIdx.x * 64;
    int tid = threadIdx.x, wid = tid >> 5, lane = tid & 31;
    int g = lane >> 2, t = lane & 3;
    const float scale = 0.15811388300841897f;

    // zero-fill Ks pad cols [40,56), both buffers
    for (int i = tid; i < 1024; i += 128) {
        int buf = i >> 9, rem = i & 511;
        int r = rem >> 3, c = 40 + (rem & 7) * 2;
        *(uint32_t*)&Ks[buf][r][c] = 0u;
    }

    uint32_t ksb = smem_u32(&Ks[0][0][0]);
    uint32_t vsb = smem_u32(&VsT[0][0][0]);
    const int KSS = 64 * 56 * 2, VSS = 40 * 72 * 2;

    // Q fragments (k padded to 48, zeros beyond 40)
    uint32_t qa[3][4];
    {
        const bf16* qb = QKV + (size_t)(q0 + wid * 16) * 960 + h * 40;
        #pragma unroll
        for (int kk = 0; kk < 3; kk++) {
            int d = kk * 16 + 2 * t;
            qa[kk][0] = *(const uint32_t*)(qb + (size_t)g * 960 + d);
            qa[kk][1] = *(const uint32_t*)(qb + (size_t)(g + 8) * 960 + d);
            if (kk < 2) {
                qa[kk][2] = *(const uint32_t*)(qb + (size_t)g * 960 + d + 8);
                qa[kk][3] = *(const uint32_t*)(qb + (size_t)(g + 8) * 960 + d + 8);
            } else {
                qa[kk][2] = 0u; qa[kk][3] = 0u;
            }
        }
    }

    // issue tile 0
    {
        #pragma unroll
        for (int i = 0; i < 5; i++) {
            int idx = tid + i * 128;
            int r = idx / 10, c = (idx % 10) * 4;
            cp8(ksb + r * 112 + c * 2, QKV + (size_t)r * 960 + 320 + h * 40 + c);
            int vr = idx >> 4, vcx = (idx & 15) * 4;
            cp8(vsb + vr * 144 + vcx * 2, VT + (size_t)(h * 40 + vr) * N_TOK + vcx);
        }
        CP_COMMIT();
    }

    float o[5][4];
    #pragma unroll
    for (int nf = 0; nf < 5; nf++)
        #pragma unroll
        for (int r = 0; r < 4; r++) o[nf][r] = 0.f;
    float mA = -1e30f, mB = -1e30f, lA = 0.f, lB = 0.f;

    for (int it = 0; it < 64; it++) {
        int buf = it & 1;
        if (it < 63) {
            int k0 = (it + 1) * 64;
            uint32_t kd = ksb + (buf ^ 1) * KSS;
            uint32_t vd = vsb + (buf ^ 1) * VSS;
            #pragma unroll
            for (int i = 0; i < 5; i++) {
                int idx = tid + i * 128;
                int r = idx / 10, c = (idx % 10) * 4;
                cp8(kd + r * 112 + c * 2, QKV + (size_t)(k0 + r) * 960 + 320 + h * 40 + c);
                int vr = idx >> 4, vcx = (idx & 15) * 4;
                cp8(vd + vr * 144 + vcx * 2, VT + (size_t)(h * 40 + vr) * N_TOK + k0 + vcx);
            }
            CP_COMMIT();
            CP_WAIT1();
        } else {
            CP_WAIT0();
        }
        __syncthreads();

        // S = Q K^T  (k = 48 padded)
        float s[8][4];
        #pragma unroll
        for (int nf = 0; nf < 8; nf++)
            #pragma unroll
            for (int r = 0; r < 4; r++) s[nf][r] = 0.f;
        #pragma unroll
        for (int kk = 0; kk < 3; kk++) {
            #pragma unroll
            for (int nf = 0; nf < 8; nf++) {
                uint32_t bb[2];
                bb[0] = *(const uint32_t*)&Ks[buf][nf * 8 + g][kk * 16 + 2 * t];
                bb[1] = *(const uint32_t*)&Ks[buf][nf * 8 + g][kk * 16 + 2 * t + 8];
                mma_bf16(s[nf], qa[kk], bb);
            }
        }
        #pragma unroll
        for (int nf = 0; nf < 8; nf++)
            #pragma unroll
            for (int r = 0; r < 4; r++) s[nf][r] *= scale;

        // online softmax
        float mtA = mA, mtB = mB;
        #pragma unroll
        for (int nf = 0; nf < 8; nf++) {
            mtA = fmaxf(mtA, fmaxf(s[nf][0], s[nf][1]));
            mtB = fmaxf(mtB, fmaxf(s[nf][2], s[nf][3]));
        }
        mtA = fmaxf(mtA, __shfl_xor_sync(0xffffffffu, mtA, 1));
        mtA = fmaxf(mtA, __shfl_xor_sync(0xffffffffu, mtA, 2));
        mtB = fmaxf(mtB, __shfl_xor_sync(0xffffffffu, mtB, 1));
        mtB = fmaxf(mtB, __shfl_xor_sync(0xffffffffu, mtB, 2));
        float corrA = exp2f((mA - mtA) * LOG2E);
        float corrB = exp2f((mB - mtB) * LOG2E);
        mA = mtA; mB = mtB;
        lA *= corrA; lB *= corrB;
        #pragma unroll
        for (int nf = 0; nf < 5; nf++) {
            o[nf][0] *= corrA; o[nf][1] *= corrA;
            o[nf][2] *= corrB; o[nf][3] *= corrB;
        }
        int pr = wid * 16 + g;
        #pragma unroll
        for (int nf = 0; nf < 8; nf++) {
            float p0 = exp2f((s[nf][0] - mA) * LOG2E);
            float p1 = exp2f((s[nf][1] - mA) * LOG2E);
            float p2 = exp2f((s[nf][2] - mB) * LOG2E);
            float p3 = exp2f((s[nf][3] - mB) * LOG2E);
            lA += p0 + p1; lB += p2 + p3;
            *(uint32_t*)&Ps[pr][nf * 8 + 2 * t]     = bf2pk(p0, p1);
            *(uint32_t*)&Ps[pr + 8][nf * 8 + 2 * t] = bf2pk(p2, p3);
        }
        __syncwarp();

        // O += P V   (k = 64 keys)
        #pragma unroll
        for (int kk = 0; kk < 4; kk++) {
            uint32_t pa[4];
            pa[0] = *(const uint32_t*)&Ps[wid * 16 + g    ][kk * 16 + 2 * t];
            pa[1] = *(const uint32_t*)&Ps[wid * 16 + g + 8][kk * 16 + 2 * t];
            pa[2] = *(const uint32_t*)&Ps[wid * 16 + g    ][kk * 16 + 2 * t + 8];
            pa[3] = *(const uint32_t*)&Ps[wid * 16 + g + 8][kk * 16 + 2 * t + 8];
            #pragma unroll
            for (int nf = 0; nf < 5; nf++) {
                uint32_t bb[2];
                bb[0] = *(const uint32_t*)&VsT[buf][nf * 8 + g][kk * 16 + 2 * t];
                bb[1] = *(const uint32_t*)&VsT[buf][nf * 8 + g][kk * 16 + 2 * t + 8];
                mma_bf16(o[nf], pa, bb);
            }
        }
        __syncthreads();
    }

    lA += __shfl_xor_sync(0xffffffffu, lA, 1);
    lA += __shfl_xor_sync(0xffffffffu, lA, 2);
    lB += __shfl_xor_sync(0xffffffffu, lB, 1);
    lB += __shfl_xor_sync(0xffffffffu, lB, 2);
    float iA = 1.f / lA, iB = 1.f / lB;
    bf16* ob = O + (size_t)(q0 + wid * 16 + g) * D + h * 40;
    #pragma unroll
    for (int nf = 0; nf < 5; nf++) {
        *(uint32_t*)(ob + nf * 8 + 2 * t) = bf2pk(o[nf][0] * iA, o[nf][1] * iA);
        *(uint32_t*)(ob + (size_t)8 * D + nf * 8 + 2 * t) = bf2pk(o[nf][2] * iB, o[nf][3] * iB);
    }
}

// ---------------- cross attention (scalar; Q bf16, 77 keys) -------------------------
__global__ void __launch_bounds__(128) cross_attn_kernel(
    const bf16* __restrict__ Q, const float* __restrict__ Kc,
    const float* __restrict__ Vc, bf16* __restrict__ O)
{
    const float scale = 0.15811388300841897f;
    int h = blockIdx.y;
    int qrow = blockIdx.x * 128 + threadIdx.x;
    int tid = threadIdx.x;

    __shared__ __align__(16) float Ks[CTX_N][40];
    __shared__ __align__(16) float Vs[CTX_N][40];
    for (int i = tid; i < CTX_N * 10; i += 128) {
        int r = i / 10, c = (i % 10) * 4;
        *(float4*)&Ks[r][c] = *(const float4*)(Kc + (size_t)r * D + h * DH + c);
        *(float4*)&Vs[r][c] = *(const float4*)(Vc + (size_t)r * D + h * DH + c);
    }
    __syncthreads();

    float4 q4[10], a4[10];
    const bf16* qp = Q + (size_t)qrow * D + h * DH;
    #pragma unroll
    for (int dd = 0; dd < 10; dd++) {
        __nv_bfloat162 b0 = *(const __nv_bfloat162*)(qp + dd * 4);
        __nv_bfloat162 b1 = *(const __nv_bfloat162*)(qp + dd * 4 + 2);
        q4[dd] = make_float4(__low2float(b0) * scale, __high2float(b0) * scale,
                             __low2float(b1) * scale, __high2float(b1) * scale);
        a4[dd] = make_float4(0.f, 0.f, 0.f, 0.f);
    }
    float m = -1e30f, l = 0.f;
    for (int j = 0; j < CTX_N; j++) {
        float s = 0.f;
        #pragma unroll
        for (int dd = 0; dd < 10; dd++) {
            float4 kk = *(const float4*)&Ks[j][dd * 4];
            s += q4[dd].x * kk.x + q4[dd].y * kk.y + q4[dd].z * kk.z + q4[dd].w * kk.w;
        }
        float mt = fmaxf(m, s);
        float corr = __expf(m - mt);
        float p = __expf(s - mt);
        m = mt;
        l = l * corr + p;
        #pragma unroll
        for (int dd = 0; dd < 10; dd++) {
            float4 vv = *(const float4*)&Vs[j][dd * 4];
            a4[dd].x = a4[dd].x * corr + p * vv.x;
            a4[dd].y = a4[dd].y * corr + p * vv.y;
            a4[dd].z = a4[dd].z * corr + p * vv.z;
            a4[dd].w = a4[dd].w * corr + p * vv.w;
        }
    }
    float inv = 1.f / l;
    bf16* op = O + (size_t)qrow * D + h * DH;
    #pragma unroll
    for (int dd = 0; dd < 10; dd++) {
        *(uint32_t*)(op + dd * 4)     = bf2pk(a4[dd].x * inv, a4[dd].y * inv);
        *(uint32_t*)(op + dd * 4 + 2) = bf2pk(a4[dd].z * inv, a4[dd].w * inv);
    }
}

// ---------------- GEGLU (bf16 in/out) ----------------
__global__ void geglu_kernel(const bf16* __restrict__ H, bf16* __restrict__ G) {
    int idx2 = blockIdx.x * 256 + threadIdx.x;       // over N_TOK * FFI/2
    int r = idx2 / (FFI / 2), c = (idx2 % (FFI / 2)) * 2;
    __nv_bfloat162 ap = *(const __nv_bfloat162*)&H[(size_t)r * (2 * FFI) + c];
    __nv_bfloat162 gp = *(const __nv_bfloat162*)&H[(size_t)r * (2 * FFI) + FFI + c];
    float a0 = __low2float(ap), a1 = __high2float(ap);
    float g0 = __low2float(gp), g1 = __high2float(gp);
    float e0 = 0.5f * g0 * (1.f + erff(g0 * 0.70710678118654752f));
    float e1 = 0.5f * g1 * (1.f + erff(g1 * 0.70710678118654752f));
    *(uint32_t*)&G[(size_t)r * FFI + c] = bf2pk(a0 * e0, a1 * e1);
}

// ---------------- launch ----------------
extern "C" void kernel_launch(void* const* d_in, const int* in_sizes, int n_in,
                              void* d_out, int out_size) {
    const float* x      = (const float*)d_in[0];
    const float* ctx    = (const float*)d_in[1];
    const float* gn_w   = (const float*)d_in[2];
    const float* gn_b   = (const float*)d_in[3];
    const float* pin_w  = (const float*)d_in[4];
    const float* pin_b  = (const float*)d_in[5];
    const float* ln1_w  = (const float*)d_in[6];
    const float* ln1_b  = (const float*)d_in[7];
    const float* q1     = (const float*)d_in[8];
    const float* k1     = (const float*)d_in[9];
    const float* v1     = (const float*)d_in[10];
    const float* o1_w   = (const float*)d_in[11];
    const float* o1_b   = (const float*)d_in[12];
    const float* ln2_w  = (const float*)d_in[13];
    const float* ln2_b  = (const float*)d_in[14];
    const float* q2     = (const float*)d_in[15];
    const float* k2     = (const float*)d_in[16];
    const float* v2     = (const float*)d_in[17];
    const float* o2_w   = (const float*)d_in[18];
    const float* o2_b   = (const float*)d_in[19];
    const float* ln3_w  = (const float*)d_in[20];
    const float* ln3_b  = (const float*)d_in[21];
    const float* ff1_w  = (const float*)d_in[22];
    const float* ff1_b  = (const float*)d_in[23];
    const float* ff2_w  = (const float*)d_in[24];
    const float* ff2_b  = (const float*)d_in[25];
    const float* pout_w = (const float*)d_in[26];
    const float* pout_b = (const float*)d_in[27];
    float* out = (float*)d_out;

    float *p_h, *p_h2, *p_kc, *p_vc;
    bf16 *p_lnb, *p_qkvb, *p_vTb, *p_attnb, *p_q2b, *p_h2b, *p_ffhb, *p_ffgb, *p_ctxb;
    bf16 *p_wqkv, *p_wo1, *p_wq2, *p_wo2, *p_wff1, *p_wff2, *p_wpin, *p_wpout, *p_wk2, *p_wv2;
    cudaGetSymbolAddress((void**)&p_h,    g_h);
    cudaGetSymbolAddress((void**)&p_h2,   g_h2);
    cudaGetSymbolAddress((void**)&p_kc,   g_kc);
    cudaGetSymbolAddress((void**)&p_vc,   g_vc);
    cudaGetSymbolAddress((void**)&p_lnb,  g_lnb);
    cudaGetSymbolAddress((void**)&p_qkvb, g_qkvb);
    cudaGetSymbolAddress((void**)&p_vTb,  g_vTb);
    cudaGetSymbolAddress((void**)&p_attnb,g_attnb);
    cudaGetSymbolAddress((void**)&p_q2b,  g_q2b);
    cudaGetSymbolAddress((void**)&p_h2b,  g_h2b);
    cudaGetSymbolAddress((void**)&p_ffhb, g_ffhb);
    cudaGetSymbolAddress((void**)&p_ffgb, g_ffgb);
    cudaGetSymbolAddress((void**)&p_ctxb, g_ctxb);
    cudaGetSymbolAddress((void**)&p_wqkv, g_wqkv);
    cudaGetSymbolAddress((void**)&p_wo1,  g_wo1);
    cudaGetSymbolAddress((void**)&p_wq2,  g_wq2);
    cudaGetSymbolAddress((void**)&p_wo2,  g_wo2);
    cudaGetSymbolAddress((void**)&p_wff1, g_wff1);
    cudaGetSymbolAddress((void**)&p_wff2, g_wff2);
    cudaGetSymbolAddress((void**)&p_wpin, g_wpin);
    cudaGetSymbolAddress((void**)&p_wpout,g_wpout);
    cudaGetSymbolAddress((void**)&p_wk2,  g_wk2);
    cudaGetSymbolAddress((void**)&p_wv2,  g_wv2);

    dim3 t32(32, 32);
    dim3 gD(D / 64, N_TOK / 32);            // (5, 128)

    // weight prep + ctx conversion + GroupNorm
    prep_weights_kernel<<<2480, 256>>>(q1, k1, v1, o1_w, q2, o2_w, ff1_w, ff2_w, pin_w, pout_w, k2, v2);
    ctx_conv_kernel<<<(CTX_M * CTX_D) / 256, 256>>>(ctx);
    gn_stats_kernel<<<GROUPS, 256>>>(x);
    gn_apply_t_kernel<<<dim3(128, 10), t32>>>(x, gn_w, gn_b, p_lnb);
    gemm_bf16_kernel<0><<<gD, 128>>>(p_lnb, p_wpin, pin_b, nullptr, p_h, nullptr, N_TOK, D, D);

    // self-attention
    layernorm_kernel<<<N_TOK, 128>>>(p_h, ln1_w, ln1_b, p_lnb);
    gemm_bf16_kernel<3><<<dim3(3 * D / 64, N_TOK / 32), 128>>>(p_lnb, p_wqkv, nullptr, nullptr, nullptr, p_qkvb, N_TOK, 3 * D, D);
    vT_kernel<<<1280, 256>>>();
    flash_bf16_kernel<<<dim3(N_TOK / 64, HEADS), 128>>>(p_qkvb, p_vTb, p_attnb);
    gemm_bf16_kernel<1><<<gD, 128>>>(p_attnb, p_wo1, o1_b, p_h, p_h2, nullptr, N_TOK, D, D);

    // cross-attention
    layernorm_kernel<<<N_TOK, 128>>>(p_h2, ln2_w, ln2_b, p_lnb);
    gemm_bf16_kernel<3><<<gD, 128>>>(p_lnb, p_wq2, nullptr, nullptr, nullptr, p_q2b, N_TOK, D, D);
    gemm_bf16_kernel<0><<<dim3(5, CTX_M / 32), 128>>>(p_ctxb, p_wk2, nullptr, nullptr, p_kc, nullptr, CTX_M, D, CTX_D);
    gemm_bf16_kernel<0><<<dim3(5, CTX_M / 32), 128>>>(p_ctxb, p_wv2, nullptr, nullptr, p_vc, nullptr, CTX_M, D, CTX_D);
    cross_attn_kernel<<<dim3(N_TOK / 128, HEADS), 128>>>(p_q2b, p_kc, p_vc, p_attnb);
    gemm_bf16_kernel<1><<<gD, 128>>>(p_attnb, p_wo2, o2_b, p_h2, p_h, nullptr, N_TOK, D, D);

    // GEGLU FF
    layernorm_kernel<<<N_TOK, 128>>>(p_h, ln3_w, ln3_b, p_lnb);
    gemm_bf16_kernel<3><<<dim3(2 * FFI / 64, N_TOK / 32), 128>>>(p_lnb, p_wff1, ff1_b, nullptr, nullptr, p_ffhb, N_TOK, 2 * FFI, D);
    geglu_kernel<<<(N_TOK * FFI / 2) / 256, 256>>>(p_ffhb, p_ffgb);
    gemm_bf16_kernel<4><<<gD, 128>>>(p_ffgb, p_wff2, ff2_b, p_h, p_h2, p_h2b, N_TOK, D, FFI);

    // proj_out + residual (transposed store back to [C][HW])
    gemm_bf16_kernel<2><<<gD, 128>>>(p_h2b, p_wpout, pout_b, x, out, nullptr, N_TOK, D, D);
}

// round 7
// speedup vs baseline: 4.4289x; 1.0345x over previous
#include <cuda_runtime.h>
#include <cuda_bf16.h>
#include <math.h>
#include <stdint.h>

#define N_TOK 4096
#define D     320
#define HEADS 8
#define DH    40
#define CTX_N 77
#define CTX_M 96
#define CTX_D 768
#define FFI   1280
#define GROUPS 32
#define LOG2E 1.4426950408889634f

typedef __nv_bfloat16 bf16;

// ---------------- scratch ----------------
__device__ float g_h  [N_TOK * D];
__device__ float g_h2 [N_TOK * D];
__device__ float g_kc [CTX_M * D];
__device__ float g_vc [CTX_M * D];
__device__ float g_mu [GROUPS];
__device__ float g_rs [GROUPS];

__device__ bf16 g_lnb [N_TOK * D];
__device__ bf16 g_qkvb[N_TOK * 3 * D];
__device__ bf16 g_vTb [D * N_TOK];
__device__ bf16 g_attnb[N_TOK * D];
__device__ bf16 g_q2b [N_TOK * D];
__device__ bf16 g_h2b [N_TOK * D];
__device__ bf16 g_ffgb[N_TOK * FFI];
__device__ bf16 g_ctxb[CTX_M * CTX_D];

// weights, bf16, stored as B^T = [N][K]
__device__ bf16 g_wqkv[3 * D * D];
__device__ bf16 g_wo1 [D * D];
__device__ bf16 g_wq2 [D * D];
__device__ bf16 g_wo2 [D * D];
__device__ bf16 g_wff1[2 * FFI * D];     // INTERLEAVED: row 2c = a_c, row 2c+1 = g_c
__device__ bf16 g_wff2[D * FFI];
__device__ bf16 g_wpin[D * D];
__device__ bf16 g_wpout[D * D];
__device__ bf16 g_wk2 [D * CTX_D];
__device__ bf16 g_wv2 [D * CTX_D];

// ---------------- helpers ----------------
__device__ __forceinline__ uint32_t bf2pk(float lo, float hi) {
    uint32_t r;
    asm("cvt.rn.bf16x2.f32 %0, %1, %2;" : "=r"(r) : "f"(hi), "f"(lo));
    return r;
}
__device__ __forceinline__ void mma_bf16(float* c, const uint32_t* a, const uint32_t* b) {
    asm volatile(
        "mma.sync.aligned.m16n8k16.row.col.f32.bf16.bf16.f32 "
        "{%0,%1,%2,%3}, {%4,%5,%6,%7}, {%8,%9}, {%0,%1,%2,%3};"
        : "+f"(c[0]), "+f"(c[1]), "+f"(c[2]), "+f"(c[3])
        : "r"(a[0]), "r"(a[1]), "r"(a[2]), "r"(a[3]), "r"(b[0]), "r"(b[1]));
}
__device__ __forceinline__ uint32_t smem_u32(const void* p) {
    return (uint32_t)__cvta_generic_to_shared(p);
}
__device__ __forceinline__ void cp16(uint32_t dst, const void* src) {
    asm volatile("cp.async.cg.shared.global [%0], [%1], 16;" :: "r"(dst), "l"(src));
}
__device__ __forceinline__ void cp8(uint32_t dst, const void* src) {
    asm volatile("cp.async.ca.shared.global [%0], [%1], 8;" :: "r"(dst), "l"(src));
}
#define CP_COMMIT() asm volatile("cp.async.commit_group;")
#define CP_WAIT1()  asm volatile("cp.async.wait_group 1;")
#define CP_WAIT0()  asm volatile("cp.async.wait_group 0;")

__device__ __forceinline__ float gelu_exact(float g) {
    return 0.5f * g * (1.f + erff(g * 0.70710678118654752f));
}

// ---------------- weight prep: fp32 [K][N] -> bf16 [N][K] (+ plain converts) --------
// ff1 columns get interleaved: src col c<1280 -> row 2c (a);  c>=1280 -> row 2(c-1280)+1 (g)
__global__ void __launch_bounds__(256) prep_weights_kernel(
    const float* __restrict__ q1, const float* __restrict__ k1, const float* __restrict__ v1,
    const float* __restrict__ o1, const float* __restrict__ q2, const float* __restrict__ o2,
    const float* __restrict__ ff1, const float* __restrict__ ff2,
    const float* __restrict__ pin, const float* __restrict__ pout,
    const float* __restrict__ k2, const float* __restrict__ v2)
{
    int b = blockIdx.x;
    int tx = threadIdx.x & 31, ty = threadIdx.x >> 5;   // 32 x 8
    if (b < 2280) {
        __shared__ float sm[32][33];
        const float* src; bf16* dst; int R, C, tile; bool ileave = false;
        if (b < 100)       { src = q1;  dst = g_wqkv;            R = 320;  C = 320;  tile = b; }
        else if (b < 200)  { src = k1;  dst = g_wqkv + 320*320;  R = 320;  C = 320;  tile = b - 100; }
        else if (b < 300)  { src = v1;  dst = g_wqkv + 640*320;  R = 320;  C = 320;  tile = b - 200; }
        else if (b < 400)  { src = o1;  dst = g_wo1;             R = 320;  C = 320;  tile = b - 300; }
        else if (b < 500)  { src = q2;  dst = g_wq2;             R = 320;  C = 320;  tile = b - 400; }
        else if (b < 600)  { src = o2;  dst = g_wo2;             R = 320;  C = 320;  tile = b - 500; }
        else if (b < 1400) { src = ff1; dst = g_wff1;            R = 320;  C = 2560; tile = b - 600; ileave = true; }
        else if (b < 1800) { src = ff2; dst = g_wff2;            R = 1280; C = 320;  tile = b - 1400; }
        else if (b < 2040) { src = k2;  dst = g_wk2;             R = 768;  C = 320;  tile = b - 1800; }
        else               { src = v2;  dst = g_wv2;             R = 768;  C = 320;  tile = b - 2040; }
        int tc = C / 32;
        int r0 = (tile / tc) * 32, c0 = (tile % tc) * 32;
        #pragma unroll
        for (int i = 0; i < 4; i++)
            sm[ty + 8 * i][tx] = src[(size_t)(r0 + ty + 8 * i) * C + c0 + tx];
        __syncthreads();
        #pragma unroll
        for (int i = 0; i < 4; i++) {
            int sc = c0 + ty + 8 * i;
            int dr = ileave ? ((sc < FFI) ? 2 * sc : 2 * (sc - FFI) + 1) : sc;
            dst[(size_t)dr * R + r0 + tx] = __float2bfloat16(sm[tx][ty + 8 * i]);
        }
    } else {
        const float* src = (b < 2380) ? pin : pout;
        bf16* dst = (b < 2380) ? g_wpin : g_wpout;
        int seg = b - ((b < 2380) ? 2280 : 2380);
        int base = seg * 1024 + threadIdx.x * 4;
        #pragma unroll
        for (int j = 0; j < 4; j++)
            dst[base + j] = __float2bfloat16(src[base + j]);
    }
}

// ---------------- ctx -> bf16, rows padded to 96 with zeros -------------------------
__global__ void __launch_bounds__(256) ctx_conv_kernel(const float* __restrict__ ctx) {
    int i = blockIdx.x * 256 + threadIdx.x;     // over 96*768
    int r = i / CTX_D;
    float v = (r < CTX_N) ? ctx[(size_t)r * CTX_D + (i % CTX_D)] : 0.f;
    g_ctxb[i] = __float2bfloat16(v);
}

// ---------------- GroupNorm stats ----------------
__global__ void gn_stats_kernel(const float* __restrict__ x) {
    int g = blockIdx.x;
    const float* p = x + g * (10 * N_TOK);
    float s = 0.f, s2 = 0.f;
    for (int i = threadIdx.x; i < 10 * N_TOK; i += 256) {
        float v = p[i];
        s += v; s2 += v * v;
    }
    __shared__ float sh1[8], sh2[8];
    int lane = threadIdx.x & 31, w = threadIdx.x >> 5;
    #pragma unroll
    for (int o = 16; o; o >>= 1) {
        s  += __shfl_xor_sync(0xffffffffu, s,  o);
        s2 += __shfl_xor_sync(0xffffffffu, s2, o);
    }
    if (lane == 0) { sh1[w] = s; sh2[w] = s2; }
    __syncthreads();
    if (threadIdx.x == 0) {
        s = 0.f; s2 = 0.f;
        #pragma unroll
        for (int i = 0; i < 8; i++) { s += sh1[i]; s2 += sh2[i]; }
        float m   = s  * (1.f / (10 * N_TOK));
        float var = s2 * (1.f / (10 * N_TOK)) - m * m;
        g_mu[g] = m;
        g_rs[g] = rsqrtf(var + 1e-6f);
    }
}

// ---------------- GN apply + transpose -> bf16 token-major ----------------
__global__ void gn_apply_t_kernel(const float* __restrict__ x,
                                  const float* __restrict__ w,
                                  const float* __restrict__ b,
                                  bf16* __restrict__ out) {
    __shared__ float t[32][33];
    int p0 = blockIdx.x * 32, c0 = blockIdx.y * 32;
    int c = c0 + threadIdx.y, p = p0 + threadIdx.x;
    int g = c / 10;
    float v = (x[c * N_TOK + p] - g_mu[g]) * g_rs[g] * w[c] + b[c];
    t[threadIdx.y][threadIdx.x] = v;
    __syncthreads();
    out[(p0 + threadIdx.y) * D + c0 + threadIdx.x] = __float2bfloat16(t[threadIdx.x][threadIdx.y]);
}

// ---------------- LayerNorm (fp32 in, bf16 out) ----------------
__global__ void layernorm_kernel(const float* __restrict__ in,
                                 const float* __restrict__ w,
                                 const float* __restrict__ b,
                                 bf16* __restrict__ out) {
    int row = blockIdx.x;
    const float* p = in + row * D;
    int t = threadIdx.x;
    float a0 = p[t], a1 = p[t + 128];
    float a2 = (t < 64) ? p[t + 256] : 0.f;
    float s  = a0 + a1 + a2;
    float s2 = a0 * a0 + a1 * a1 + a2 * a2;
    __shared__ float sh1[4], sh2[4];
    __shared__ float mr[2];
    int lane = t & 31, wp = t >> 5;
    #pragma unroll
    for (int o = 16; o; o >>= 1) {
        s  += __shfl_xor_sync(0xffffffffu, s,  o);
        s2 += __shfl_xor_sync(0xffffffffu, s2, o);
    }
    if (lane == 0) { sh1[wp] = s; sh2[wp] = s2; }
    __syncthreads();
    if (t == 0) {
        s = sh1[0] + sh1[1] + sh1[2] + sh1[3];
        s2 = sh2[0] + sh2[1] + sh2[2] + sh2[3];
        float m = s * (1.f / D);
        float var = s2 * (1.f / D) - m * m;
        mr[0] = m; mr[1] = rsqrtf(var + 1e-5f);
    }
    __syncthreads();
    float m = mr[0], r = mr[1];
    bf16* o = out + row * D;
    o[t]       = __float2bfloat16((a0 - m) * r * w[t]       + b[t]);
    o[t + 128] = __float2bfloat16((a1 - m) * r * w[t + 128] + b[t + 128]);
    if (t < 64)
        o[t + 256] = __float2bfloat16((a2 - m) * r * w[t + 256] + b[t + 256]);
}

// ---------------- bf16 NT GEMM, cp.async 3-stage: C[M,N] = A[M,K] @ Bt[N,K]^T -------
// tile 32x64, 128 threads (warps 2x2, warp tile 16x32)
// EPI 0: C fp32 = AB + bias
// EPI 1: C fp32 = AB + bias + R
// EPI 2: C fp32 [n*M+m] = AB + bias[n] + R[n*M+m]
// EPI 3: Cb bf16 = AB (+bias)
// EPI 4: C fp32 = AB + bias + R;  Cb bf16 = same
// EPI 5: GEGLU: cols interleaved (a,g); Cb bf16 [M][N/2]: a*gelu(g); bias = ff1_b raw layout
template <int EPI>
__global__ void __launch_bounds__(128) gemm_bf16_kernel(
    const bf16* __restrict__ A, const bf16* __restrict__ Bt,
    const float* __restrict__ bias, const float* __restrict__ R,
    float* __restrict__ C, bf16* __restrict__ Cb, int M, int N, int K)
{
    __shared__ __align__(16) bf16 As[3][32][40];
    __shared__ __align__(16) bf16 Bs[3][64][40];
    int tid = threadIdx.x;
    int lane = tid & 31, wid = tid >> 5;
    int wm = wid & 1, wn = wid >> 1;
    int g = lane >> 2, t = lane & 3;
    int bm = blockIdx.y * 32, bn = blockIdx.x * 64;

    float acc[4][4];
    #pragma unroll
    for (int nf = 0; nf < 4; nf++)
        #pragma unroll
        for (int r = 0; r < 4; r++) acc[nf][r] = 0.f;

    int ar = tid >> 2, ac = (tid & 3) * 8;      // A: 32 rows x 4 chunks of 8
    int br = tid >> 1, bc = (tid & 1) * 16;     // B: 64 rows x 2 chunks of 16
    const bf16* Abase = A  + (size_t)(bm + ar) * K + ac;
    const bf16* Bbase = Bt + (size_t)(bn + br) * K + bc;
    uint32_t sA = smem_u32(&As[0][ar][ac]);
    uint32_t sB = smem_u32(&Bs[0][br][bc]);
    const int ASS = 32 * 40 * 2, BSS = 64 * 40 * 2;

    int nt = K / 32;
    #pragma unroll
    for (int s = 0; s < 2; s++) {
        cp16(sA + s * ASS, Abase + s * 32);
        cp16(sB + s * BSS, Bbase + s * 32);
        cp16(sB + s * BSS + 16, Bbase + s * 32 + 8);
        CP_COMMIT();
    }

    for (int i = 0; i < nt; i++) {
        if (i + 1 < nt) { CP_WAIT1(); } else { CP_WAIT0(); }
        __syncthreads();
        if (i + 2 < nt) {
            int s = (i + 2) % 3;
            cp16(sA + s * ASS, Abase + (i + 2) * 32);
            cp16(sB + s * BSS, Bbase + (i + 2) * 32);
            cp16(sB + s * BSS + 16, Bbase + (i + 2) * 32 + 8);
            CP_COMMIT();
        }
        int cb = i % 3;
        #pragma unroll
        for (int kk = 0; kk < 2; kk++) {
            uint32_t a[4], b[4][2];
            a[0] = *(const uint32_t*)&As[cb][wm * 16 + g    ][kk * 16 + 2 * t];
            a[1] = *(const uint32_t*)&As[cb][wm * 16 + g + 8][kk * 16 + 2 * t];
            a[2] = *(const uint32_t*)&As[cb][wm * 16 + g    ][kk * 16 + 2 * t + 8];
            a[3] = *(const uint32_t*)&As[cb][wm * 16 + g + 8][kk * 16 + 2 * t + 8];
            #pragma unroll
            for (int nf = 0; nf < 4; nf++) {
                int n = wn * 32 + nf * 8 + g;
                b[nf][0] = *(const uint32_t*)&Bs[cb][n][kk * 16 + 2 * t];
                b[nf][1] = *(const uint32_t*)&Bs[cb][n][kk * 16 + 2 * t + 8];
            }
            #pragma unroll
            for (int nf = 0; nf < 4; nf++)
                mma_bf16(acc[nf], a, b[nf]);
        }
    }

    #pragma unroll
    for (int nf = 0; nf < 4; nf++) {
        int m = bm + wm * 16 + g;
        int n = bn + wn * 32 + nf * 8 + 2 * t;
        if (EPI == 5) {
            // interleaved: col n = a_{n/2}, col n+1 = g_{n/2}
            int c2 = n >> 1;
            float ab = bias[c2], gb = bias[FFI + c2];
            float a0 = acc[nf][0] + ab, g0 = acc[nf][1] + gb;
            float a1 = acc[nf][2] + ab, g1 = acc[nf][3] + gb;
            Cb[(size_t)m * (N / 2) + c2]       = __float2bfloat16(a0 * gelu_exact(g0));
            Cb[(size_t)(m + 8) * (N / 2) + c2] = __float2bfloat16(a1 * gelu_exact(g1));
            continue;
        }
        float b0 = bias ? bias[n] : 0.f;
        float b1 = bias ? bias[n + 1] : 0.f;
        float v0 = acc[nf][0] + b0;
        float v1 = acc[nf][1] + b1;
        float v2 = acc[nf][2] + b0;
        float v3 = acc[nf][3] + b1;
        if (EPI == 2) {
            C[(size_t)n * M + m]           = v0 + R[(size_t)n * M + m];
            C[(size_t)(n + 1) * M + m]     = v1 + R[(size_t)(n + 1) * M + m];
            C[(size_t)n * M + m + 8]       = v2 + R[(size_t)n * M + m + 8];
            C[(size_t)(n + 1) * M + m + 8] = v3 + R[(size_t)(n + 1) * M + m + 8];
        } else if (EPI == 3) {
            *(uint32_t*)&Cb[(size_t)m * N + n]       = bf2pk(v0, v1);
            *(uint32_t*)&Cb[(size_t)(m + 8) * N + n] = bf2pk(v2, v3);
        } else {
            if (EPI == 1 || EPI == 4) {
                float2 r0 = *(const float2*)&R[(size_t)m * N + n];
                float2 r1 = *(const float2*)&R[(size_t)(m + 8) * N + n];
                v0 += r0.x; v1 += r0.y; v2 += r1.x; v3 += r1.y;
            }
            *(float2*)&C[(size_t)m * N + n]       = make_float2(v0, v1);
            *(float2*)&C[(size_t)(m + 8) * N + n] = make_float2(v2, v3);
            if (EPI == 4) {
                *(uint32_t*)&Cb[(size_t)m * N + n]       = bf2pk(v0, v1);
                *(uint32_t*)&Cb[(size_t)(m + 8) * N + n] = bf2pk(v2, v3);
            }
        }
    }
}

// ---------------- V transpose: qkvb cols [640,960) -> vTb [320][4096] ----------------
__global__ void __launch_bounds__(256) vT_kernel() {
    __shared__ bf16 sm[32][33];
    int b = blockIdx.x;                 // 128 m-tiles x 10 n-tiles
    int m0 = (b / 10) * 32, n0 = (b % 10) * 32;
    int tx = threadIdx.x & 31, ty = threadIdx.x >> 5;
    #pragma unroll
    for (int i = 0; i < 4; i++)
        sm[ty + 8 * i][tx] = g_qkvb[(size_t)(m0 + ty + 8 * i) * 960 + 640 + n0 + tx];
    __syncthreads();
    #pragma unroll
    for (int i = 0; i < 4; i++)
        g_vTb[(size_t)(n0 + ty + 8 * i) * N_TOK + m0 + tx] = sm[tx][ty + 8 * i];
}

// ---------------- bf16 flash self-attention, cp.async 2-stage, 128-query blocks -----
// grid (32, 8), 256 threads = 8 warps; warp w owns query rows [w*16, w*16+16)
__global__ void __launch_bounds__(256) flash_bf16_kernel(
    const bf16* __restrict__ QKV, const bf16* __restrict__ VT, bf16* __restrict__ O)
{
    __shared__ __align__(16) bf16 Ks[2][64][56];
    __shared__ __align__(16) bf16 VsT[2][40][72];
    __shared__ __align__(16) bf16 Ps[128][72];
    int h = blockIdx.y;
    int q0 = blockIdx.x * 128;
    int tid = threadIdx.x, wid = tid >> 5, lane = tid & 31;
    int g = lane >> 2, t = lane & 3;
    const float scale = 0.15811388300841897f;

    // zero-fill Ks pad cols [40,56), both buffers
    for (int i = tid; i < 1024; i += 256) {
        int buf = i >> 9, rem = i & 511;
        int r = rem >> 3, c = 40 + (rem & 7) * 2;
        *(uint32_t*)&Ks[buf][r][c] = 0u;
    }

    uint32_t ksb = smem_u32(&Ks[0][0][0]);
    uint32_t vsb = smem_u32(&VsT[0][0][0]);
    const int KSS = 64 * 56 * 2, VSS = 40 * 72 * 2;

    // Q fragments (k padded to 48, zeros beyond 40)
    uint32_t qa[3][4];
    {
        const bf16* qb = QKV + (size_t)(q0 + wid * 16) * 960 + h * 40;
        #pragma unroll
        for (int kk = 0; kk < 3; kk++) {
            int d = kk * 16 + 2 * t;
            qa[kk][0] = *(const uint32_t*)(qb + (size_t)g * 960 + d);
            qa[kk][1] = *(const uint32_t*)(qb + (size_t)(g + 8) * 960 + d);
            if (kk < 2) {
                qa[kk][2] = *(const uint32_t*)(qb + (size_t)g * 960 + d + 8);
                qa[kk][3] = *(const uint32_t*)(qb + (size_t)(g + 8) * 960 + d + 8);
            } else {
                qa[kk][2] = 0u; qa[kk][3] = 0u;
            }
        }
    }

    // issue tile 0 (640 K-chunks + 640 V-chunks, 256 threads)
    {
        for (int idx = tid; idx < 640; idx += 256) {
            int r = idx / 10, c = (idx % 10) * 4;
            cp8(ksb + r * 112 + c * 2, QKV + (size_t)r * 960 + 320 + h * 40 + c);
            int vr = idx >> 4, vcx = (idx & 15) * 4;
            cp8(vsb + vr * 144 + vcx * 2, VT + (size_t)(h * 40 + vr) * N_TOK + vcx);
        }
        CP_COMMIT();
    }

    float o[5][4];
    #pragma unroll
    for (int nf = 0; nf < 5; nf++)
        #pragma unroll
        for (int r = 0; r < 4; r++) o[nf][r] = 0.f;
    float mA = -1e30f, mB = -1e30f, lA = 0.f, lB = 0.f;

    for (int it = 0; it < 64; it++) {
        int buf = it & 1;
        if (it < 63) {
            int k0 = (it + 1) * 64;
            uint32_t kd = ksb + (buf ^ 1) * KSS;
            uint32_t vd = vsb + (buf ^ 1) * VSS;
            for (int idx = tid; idx < 640; idx += 256) {
                int r = idx / 10, c = (idx % 10) * 4;
                cp8(kd + r * 112 + c * 2, QKV + (size_t)(k0 + r) * 960 + 320 + h * 40 + c);
                int vr = idx >> 4, vcx = (idx & 15) * 4;
                cp8(vd + vr * 144 + vcx * 2, VT + (size_t)(h * 40 + vr) * N_TOK + k0 + vcx);
            }
            CP_COMMIT();
            CP_WAIT1();
        } else {
            CP_WAIT0();
        }
        __syncthreads();

        // S = Q K^T  (k = 48 padded)
        float s[8][4];
        #pragma unroll
        for (int nf = 0; nf < 8; nf++)
            #pragma unroll
            for (int r = 0; r < 4; r++) s[nf][r] = 0.f;
        #pragma unroll
        for (int kk = 0; kk < 3; kk++) {
            #pragma unroll
            for (int nf = 0; nf < 8; nf++) {
                uint32_t bb[2];
                bb[0] = *(const uint32_t*)&Ks[buf][nf * 8 + g][kk * 16 + 2 * t];
                bb[1] = *(const uint32_t*)&Ks[buf][nf * 8 + g][kk * 16 + 2 * t + 8];
                mma_bf16(s[nf], qa[kk], bb);
            }
        }
        #pragma unroll
        for (int nf = 0; nf < 8; nf++)
            #pragma unroll
            for (int r = 0; r < 4; r++) s[nf][r] *= scale;

        // online softmax
        float mtA = mA, mtB = mB;
        #pragma unroll
        for (int nf = 0; nf < 8; nf++) {
            mtA = fmaxf(mtA, fmaxf(s[nf][0], s[nf][1]));
            mtB = fmaxf(mtB, fmaxf(s[nf][2], s[nf][3]));
        }
        mtA = fmaxf(mtA, __shfl_xor_sync(0xffffffffu, mtA, 1));
        mtA = fmaxf(mtA, __shfl_xor_sync(0xffffffffu, mtA, 2));
        mtB = fmaxf(mtB, __shfl_xor_sync(0xffffffffu, mtB, 1));
        mtB = fmaxf(mtB, __shfl_xor_sync(0xffffffffu, mtB, 2));
        float corrA = exp2f((mA - mtA) * LOG2E);
        float corrB = exp2f((mB - mtB) * LOG2E);
        mA = mtA; mB = mtB;
        lA *= corrA; lB *= corrB;
        #pragma unroll
        for (int nf = 0; nf < 5; nf++) {
            o[nf][0] *= corrA; o[nf][1] *= corrA;
            o[nf][2] *= corrB; o[nf][3] *= corrB;
        }
        int pr = wid * 16 + g;
        #pragma unroll
        for (int nf = 0; nf < 8; nf++) {
            float p0 = exp2f((s[nf][0] - mA) * LOG2E);
            float p1 = exp2f((s[nf][1] - mA) * LOG2E);
            float p2 = exp2f((s[nf][2] - mB) * LOG2E);
            float p3 = exp2f((s[nf][3] - mB) * LOG2E);
            lA += p0 + p1; lB += p2 + p3;
            *(uint32_t*)&Ps[pr][nf * 8 + 2 * t]     = bf2pk(p0, p1);
            *(uint32_t*)&Ps[pr + 8][nf * 8 + 2 * t] = bf2pk(p2, p3);
        }
        __syncwarp();

        // O += P V   (k = 64 keys)
        #pragma unroll
        for (int kk = 0; kk < 4; kk++) {
            uint32_t pa[4];
            pa[0] = *(const uint32_t*)&Ps[wid * 16 + g    ][kk * 16 + 2 * t];
            pa[1] = *(const uint32_t*)&Ps[wid * 16 + g + 8][kk * 16 + 2 * t];
            pa[2] = *(const uint32_t*)&Ps[wid * 16 + g    ][kk * 16 + 2 * t + 8];
            pa[3] = *(const uint32_t*)&Ps[wid * 16 + g + 8][kk * 16 + 2 * t + 8];
            #pragma unroll
            for (int nf = 0; nf < 5; nf++) {
                uint32_t bb[2];
                bb[0] = *(const uint32_t*)&VsT[buf][nf * 8 + g][kk * 16 + 2 * t];
                bb[1] = *(const uint32_t*)&VsT[buf][nf * 8 + g][kk * 16 + 2 * t + 8];
                mma_bf16(o[nf], pa, bb);
            }
        }
        __syncthreads();
    }

    lA += __shfl_xor_sync(0xffffffffu, lA, 1);
    lA += __shfl_xor_sync(0xffffffffu, lA, 2);
    lB += __shfl_xor_sync(0xffffffffu, lB, 1);
    lB += __shfl_xor_sync(0xffffffffu, lB, 2);
    float iA = 1.f / lA, iB = 1.f / lB;
    bf16* ob = O + (size_t)(q0 + wid * 16 + g) * D + h * 40;
    #pragma unroll
    for (int nf = 0; nf < 5; nf++) {
        *(uint32_t*)(ob + nf * 8 + 2 * t) = bf2pk(o[nf][0] * iA, o[nf][1] * iA);
        *(uint32_t*)(ob + (size_t)8 * D + nf * 8 + 2 * t) = bf2pk(o[nf][2] * iB, o[nf][3] * iB);
    }
}

// ---------------- cross attention (scalar; Q bf16, 77 keys) -------------------------
__global__ void __launch_bounds__(128) cross_attn_kernel(
    const bf16* __restrict__ Q, const float* __restrict__ Kc,
    const float* __restrict__ Vc, bf16* __restrict__ O)
{
    const float scale = 0.15811388300841897f;
    int h = blockIdx.y;
    int qrow = blockIdx.x * 128 + threadIdx.x;
    int tid = threadIdx.x;

    __shared__ __align__(16) float Ks[CTX_N][40];
    __shared__ __align__(16) float Vs[CTX_N][40];
    for (int i = tid; i < CTX_N * 10; i += 128) {
        int r = i / 10, c = (i % 10) * 4;
        *(float4*)&Ks[r][c] = *(const float4*)(Kc + (size_t)r * D + h * DH + c);
        *(float4*)&Vs[r][c] = *(const float4*)(Vc + (size_t)r * D + h * DH + c);
    }
    __syncthreads();

    float4 q4[10], a4[10];
    const bf16* qp = Q + (size_t)qrow * D + h * DH;
    #pragma unroll
    for (int dd = 0; dd < 10; dd++) {
        __nv_bfloat162 b0 = *(const __nv_bfloat162*)(qp + dd * 4);
        __nv_bfloat162 b1 = *(const __nv_bfloat162*)(qp + dd * 4 + 2);
        q4[dd] = make_float4(__low2float(b0) * scale, __high2float(b0) * scale,
                             __low2float(b1) * scale, __high2float(b1) * scale);
        a4[dd] = make_float4(0.f, 0.f, 0.f, 0.f);
    }
    float m = -1e30f, l = 0.f;
    for (int j = 0; j < CTX_N; j++) {
        float s = 0.f;
        #pragma unroll
        for (int dd = 0; dd < 10; dd++) {
            float4 kk = *(const float4*)&Ks[j][dd * 4];
            s += q4[dd].x * kk.x + q4[dd].y * kk.y + q4[dd].z * kk.z + q4[dd].w * kk.w;
        }
        float mt = fmaxf(m, s);
        float corr = __expf(m - mt);
        float p = __expf(s - mt);
        m = mt;
        l = l * corr + p;
        #pragma unroll
        for (int dd = 0; dd < 10; dd++) {
            float4 vv = *(const float4*)&Vs[j][dd * 4];
            a4[dd].x = a4[dd].x * corr + p * vv.x;
            a4[dd].y = a4[dd].y * corr + p * vv.y;
            a4[dd].z = a4[dd].z * corr + p * vv.z;
            a4[dd].w = a4[dd].w * corr + p * vv.w;
        }
    }
    float inv = 1.f / l;
    bf16* op = O + (size_t)qrow * D + h * DH;
    #pragma unroll
    for (int dd = 0; dd < 10; dd++) {
        *(uint32_t*)(op + dd * 4)     = bf2pk(a4[dd].x * inv, a4[dd].y * inv);
        *(uint32_t*)(op + dd * 4 + 2) = bf2pk(a4[dd].z * inv, a4[dd].w * inv);
    }
}

// ---------------- launch ----------------
extern "C" void kernel_launch(void* const* d_in, const int* in_sizes, int n_in,
                              void* d_out, int out_size) {
    const float* x      = (const float*)d_in[0];
    const float* ctx    = (const float*)d_in[1];
    const float* gn_w   = (const float*)d_in[2];
    const float* gn_b   = (const float*)d_in[3];
    const float* pin_w  = (const float*)d_in[4];
    const float* pin_b  = (const float*)d_in[5];
    const float* ln1_w  = (const float*)d_in[6];
    const float* ln1_b  = (const float*)d_in[7];
    const float* q1     = (const float*)d_in[8];
    const float* k1     = (const float*)d_in[9];
    const float* v1     = (const float*)d_in[10];
    const float* o1_w   = (const float*)d_in[11];
    const float* o1_b   = (const float*)d_in[12];
    const float* ln2_w  = (const float*)d_in[13];
    const float* ln2_b  = (const float*)d_in[14];
    const float* q2     = (const float*)d_in[15];
    const float* k2     = (const float*)d_in[16];
    const float* v2     = (const float*)d_in[17];
    const float* o2_w   = (const float*)d_in[18];
    const float* o2_b   = (const float*)d_in[19];
    const float* ln3_w  = (const float*)d_in[20];
    const float* ln3_b  = (const float*)d_in[21];
    const float* ff1_w  = (const float*)d_in[22];
    const float* ff1_b  = (const float*)d_in[23];
    const float* ff2_w  = (const float*)d_in[24];
    const float* ff2_b  = (const float*)d_in[25];
    const float* pout_w = (const float*)d_in[26];
    const float* pout_b = (const float*)d_in[27];
    float* out = (float*)d_out;

    float *p_h, *p_h2, *p_kc, *p_vc;
    bf16 *p_lnb, *p_qkvb, *p_vTb, *p_attnb, *p_q2b, *p_h2b, *p_ffgb, *p_ctxb;
    bf16 *p_wqkv, *p_wo1, *p_wq2, *p_wo2, *p_wff1, *p_wff2, *p_wpin, *p_wpout, *p_wk2, *p_wv2;
    cudaGetSymbolAddress((void**)&p_h,    g_h);
    cudaGetSymbolAddress((void**)&p_h2,   g_h2);
    cudaGetSymbolAddress((void**)&p_kc,   g_kc);
    cudaGetSymbolAddress((void**)&p_vc,   g_vc);
    cudaGetSymbolAddress((void**)&p_lnb,  g_lnb);
    cudaGetSymbolAddress((void**)&p_qkvb, g_qkvb);
    cudaGetSymbolAddress((void**)&p_vTb,  g_vTb);
    cudaGetSymbolAddress((void**)&p_attnb,g_attnb);
    cudaGetSymbolAddress((void**)&p_q2b,  g_q2b);
    cudaGetSymbolAddress((void**)&p_h2b,  g_h2b);
    cudaGetSymbolAddress((void**)&p_ffgb, g_ffgb);
    cudaGetSymbolAddress((void**)&p_ctxb, g_ctxb);
    cudaGetSymbolAddress((void**)&p_wqkv, g_wqkv);
    cudaGetSymbolAddress((void**)&p_wo1,  g_wo1);
    cudaGetSymbolAddress((void**)&p_wq2,  g_wq2);
    cudaGetSymbolAddress((void**)&p_wo2,  g_wo2);
    cudaGetSymbolAddress((void**)&p_wff1, g_wff1);
    cudaGetSymbolAddress((void**)&p_wff2, g_wff2);
    cudaGetSymbolAddress((void**)&p_wpin, g_wpin);
    cudaGetSymbolAddress((void**)&p_wpout,g_wpout);
    cudaGetSymbolAddress((void**)&p_wk2,  g_wk2);
    cudaGetSymbolAddress((void**)&p_wv2,  g_wv2);

    dim3 t32(32, 32);
    dim3 gD(D / 64, N_TOK / 32);            // (5, 128)

    // weight prep + ctx conversion + GroupNorm
    prep_weights_kernel<<<2480, 256>>>(q1, k1, v1, o1_w, q2, o2_w, ff1_w, ff2_w, pin_w, pout_w, k2, v2);
    ctx_conv_kernel<<<(CTX_M * CTX_D) / 256, 256>>>(ctx);
    gn_stats_kernel<<<GROUPS, 256>>>(x);
    gn_apply_t_kernel<<<dim3(128, 10), t32>>>(x, gn_w, gn_b, p_lnb);
    gemm_bf16_kernel<0><<<gD, 128>>>(p_lnb, p_wpin, pin_b, nullptr, p_h, nullptr, N_TOK, D, D);

    // self-attention
    layernorm_kernel<<<N_TOK, 128>>>(p_h, ln1_w, ln1_b, p_lnb);
    gemm_bf16_kernel<3><<<dim3(3 * D / 64, N_TOK / 32), 128>>>(p_lnb, p_wqkv, nullptr, nullptr, nullptr, p_qkvb, N_TOK, 3 * D, D);
    vT_kernel<<<1280, 256>>>();
    flash_bf16_kernel<<<dim3(N_TOK / 128, HEADS), 256>>>(p_qkvb, p_vTb, p_attnb);
    gemm_bf16_kernel<1><<<gD, 128>>>(p_attnb, p_wo1, o1_b, p_h, p_h2, nullptr, N_TOK, D, D);

    // cross-attention
    layernorm_kernel<<<N_TOK, 128>>>(p_h2, ln2_w, ln2_b, p_lnb);
    gemm_bf16_kernel<3><<<gD, 128>>>(p_lnb, p_wq2, nullptr, nullptr, nullptr, p_q2b, N_TOK, D, D);
    gemm_bf16_kernel<0><<<dim3(5, CTX_M / 32), 128>>>(p_ctxb, p_wk2, nullptr, nullptr, p_kc, nullptr, CTX_M, D, CTX_D);
    gemm_bf16_kernel<0><<<dim3(5, CTX_M / 32), 128>>>(p_ctxb, p_wv2, nullptr, nullptr, p_vc, nullptr, CTX_M, D, CTX_D);
    cross_attn_kernel<<<dim3(N_TOK / 128, HEADS), 128>>>(p_q2b, p_kc, p_vc, p_attnb);
    gemm_bf16_kernel<1><<<gD, 128>>>(p_attnb, p_wo2, o2_b, p_h2, p_h, nullptr, N_TOK, D, D);

    // GEGLU FF (GEGLU fused into ff1 epilogue via interleaved weights)
    layernorm_kernel<<<N_TOK, 128>>>(p_h, ln3_w, ln3_b, p_lnb);
    gemm_bf16_kernel<5><<<dim3(2 * FFI / 64, N_TOK / 32), 128>>>(p_lnb, p_wff1, ff1_b, nullptr, nullptr, p_ffgb, N_TOK, 2 * FFI, D);
    gemm_bf16_kernel<4><<<gD, 128>>>(p_ffgb, p_wff2, ff2_b, p_h, p_h2, p_h2b, N_TOK, D, FFI);

    // proj_out + residual (transposed store back to [C][HW])
    gemm_bf16_kernel<2><<<gD, 128>>>(p_h2b, p_wpout, pout_b, x, out, nullptr, N_TOK, D, D);
}

// round 8
// speedup vs baseline: 4.5432x; 1.0258x over previous
#include <cuda_runtime.h>
#include <cuda_bf16.h>
#include <math.h>
#include <stdint.h>

#define N_TOK 4096
#define D     320
#define HEADS 8
#define DH    40
#define CTX_N 77
#define CTX_M 96
#define CTX_D 768
#define FFI   1280
#define GROUPS 32
#define LOG2E 1.4426950408889634f

typedef __nv_bfloat16 bf16;

// ---------------- scratch ----------------
__device__ float g_h  [N_TOK * D];
__device__ float g_h2 [N_TOK * D];
__device__ float g_kvc[CTX_M * 2 * D];     // [96][640]: cols 0-319 = K, 320-639 = V
__device__ float g_mu [GROUPS];
__device__ float g_rs [GROUPS];

__device__ bf16 g_lnb [N_TOK * D];
__device__ bf16 g_qkvb[N_TOK * 3 * D];
__device__ bf16 g_attnb[N_TOK * D];
__device__ bf16 g_q2b [N_TOK * D];
__device__ bf16 g_h2b [N_TOK * D];
__device__ bf16 g_ffgb[N_TOK * FFI];
__device__ bf16 g_ctxb[CTX_M * CTX_D];

// weights, bf16, stored as B^T = [N][K]
__device__ bf16 g_wqkv[3 * D * D];
__device__ bf16 g_wo1 [D * D];
__device__ bf16 g_wq2 [D * D];
__device__ bf16 g_wo2 [D * D];
__device__ bf16 g_wff1[2 * FFI * D];     // INTERLEAVED: row 2c = a_c, row 2c+1 = g_c
__device__ bf16 g_wff2[D * FFI];
__device__ bf16 g_wpin[D * D];
__device__ bf16 g_wpout[D * D];
__device__ bf16 g_wkv2[2 * D * CTX_D];   // rows 0-319 = k2^T, 320-639 = v2^T

// ---------------- helpers ----------------
__device__ __forceinline__ uint32_t bf2pk(float lo, float hi) {
    uint32_t r;
    asm("cvt.rn.bf16x2.f32 %0, %1, %2;" : "=r"(r) : "f"(hi), "f"(lo));
    return r;
}
__device__ __forceinline__ void mma_bf16(float* c, const uint32_t* a, const uint32_t* b) {
    asm volatile(
        "mma.sync.aligned.m16n8k16.row.col.f32.bf16.bf16.f32 "
        "{%0,%1,%2,%3}, {%4,%5,%6,%7}, {%8,%9}, {%0,%1,%2,%3};"
        : "+f"(c[0]), "+f"(c[1]), "+f"(c[2]), "+f"(c[3])
        : "r"(a[0]), "r"(a[1]), "r"(a[2]), "r"(a[3]), "r"(b[0]), "r"(b[1]));
}
__device__ __forceinline__ uint32_t smem_u32(const void* p) {
    return (uint32_t)__cvta_generic_to_shared(p);
}
__device__ __forceinline__ void cp16(uint32_t dst, const void* src) {
    asm volatile("cp.async.cg.shared.global [%0], [%1], 16;" :: "r"(dst), "l"(src));
}
__device__ __forceinline__ void cp8(uint32_t dst, const void* src) {
    asm volatile("cp.async.ca.shared.global [%0], [%1], 8;" :: "r"(dst), "l"(src));
}
#define CP_COMMIT() asm volatile("cp.async.commit_group;")
#define CP_WAIT1()  asm volatile("cp.async.wait_group 1;")
#define CP_WAIT0()  asm volatile("cp.async.wait_group 0;")

__device__ __forceinline__ float gelu_exact(float g) {
    return 0.5f * g * (1.f + erff(g * 0.70710678118654752f));
}
__device__ __forceinline__ void ldmatrix_x2_trans(uint32_t& d0, uint32_t& d1, uint32_t addr) {
    asm volatile("ldmatrix.sync.aligned.m8n8.x2.trans.shared.b16 {%0,%1}, [%2];"
                 : "=r"(d0), "=r"(d1) : "r"(addr));
}

// ---------------- weight prep: fp32 [K][N] -> bf16 [N][K] (+ plain converts) --------
__global__ void __launch_bounds__(256) prep_weights_kernel(
    const float* __restrict__ q1, const float* __restrict__ k1, const float* __restrict__ v1,
    const float* __restrict__ o1, const float* __restrict__ q2, const float* __restrict__ o2,
    const float* __restrict__ ff1, const float* __restrict__ ff2,
    const float* __restrict__ pin, const float* __restrict__ pout,
    const float* __restrict__ k2, const float* __restrict__ v2)
{
    int b = blockIdx.x;
    int tx = threadIdx.x & 31, ty = threadIdx.x >> 5;   // 32 x 8
    if (b < 2280) {
        __shared__ float sm[32][33];
        const float* src; bf16* dst; int R, C, tile; bool ileave = false;
        if (b < 100)       { src = q1;  dst = g_wqkv;            R = 320;  C = 320;  tile = b; }
        else if (b < 200)  { src = k1;  dst = g_wqkv + 320*320;  R = 320;  C = 320;  tile = b - 100; }
        else if (b < 300)  { src = v1;  dst = g_wqkv + 640*320;  R = 320;  C = 320;  tile = b - 200; }
        else if (b < 400)  { src = o1;  dst = g_wo1;             R = 320;  C = 320;  tile = b - 300; }
        else if (b < 500)  { src = q2;  dst = g_wq2;             R = 320;  C = 320;  tile = b - 400; }
        else if (b < 600)  { src = o2;  dst = g_wo2;             R = 320;  C = 320;  tile = b - 500; }
        else if (b < 1400) { src = ff1; dst = g_wff1;            R = 320;  C = 2560; tile = b - 600; ileave = true; }
        else if (b < 1800) { src = ff2; dst = g_wff2;            R = 1280; C = 320;  tile = b - 1400; }
        else if (b < 2040) { src = k2;  dst = g_wkv2;            R = 768;  C = 320;  tile = b - 1800; }
        else               { src = v2;  dst = g_wkv2 + 320*768;  R = 768;  C = 320;  tile = b - 2040; }
        int tc = C / 32;
        int r0 = (tile / tc) * 32, c0 = (tile % tc) * 32;
        #pragma unroll
        for (int i = 0; i < 4; i++)
            sm[ty + 8 * i][tx] = src[(size_t)(r0 + ty + 8 * i) * C + c0 + tx];
        __syncthreads();
        #pragma unroll
        for (int i = 0; i < 4; i++) {
            int sc = c0 + ty + 8 * i;
            int dr = ileave ? ((sc < FFI) ? 2 * sc : 2 * (sc - FFI) + 1) : sc;
            dst[(size_t)dr * R + r0 + tx] = __float2bfloat16(sm[tx][ty + 8 * i]);
        }
    } else {
        const float* src = (b < 2380) ? pin : pout;
        bf16* dst = (b < 2380) ? g_wpin : g_wpout;
        int seg = b - ((b < 2380) ? 2280 : 2380);
        int base = seg * 1024 + threadIdx.x * 4;
        #pragma unroll
        for (int j = 0; j < 4; j++)
            dst[base + j] = __float2bfloat16(src[base + j]);
    }
}

// ---------------- ctx -> bf16, rows padded to 96 with zeros -------------------------
__global__ void __launch_bounds__(256) ctx_conv_kernel(const float* __restrict__ ctx) {
    int i = blockIdx.x * 256 + threadIdx.x;     // over 96*768
    int r = i / CTX_D;
    float v = (r < CTX_N) ? ctx[(size_t)r * CTX_D + (i % CTX_D)] : 0.f;
    g_ctxb[i] = __float2bfloat16(v);
}

// ---------------- GroupNorm stats (float4) ----------------
__global__ void gn_stats_kernel(const float* __restrict__ x) {
    int g = blockIdx.x;
    const float4* p = (const float4*)(x + g * (10 * N_TOK));
    float s = 0.f, s2 = 0.f;
    for (int i = threadIdx.x; i < 10 * N_TOK / 4; i += 256) {
        float4 v = p[i];
        s  += v.x + v.y + v.z + v.w;
        s2 += v.x * v.x + v.y * v.y + v.z * v.z + v.w * v.w;
    }
    __shared__ float sh1[8], sh2[8];
    int lane = threadIdx.x & 31, w = threadIdx.x >> 5;
    #pragma unroll
    for (int o = 16; o; o >>= 1) {
        s  += __shfl_xor_sync(0xffffffffu, s,  o);
        s2 += __shfl_xor_sync(0xffffffffu, s2, o);
    }
    if (lane == 0) { sh1[w] = s; sh2[w] = s2; }
    __syncthreads();
    if (threadIdx.x == 0) {
        s = 0.f; s2 = 0.f;
        #pragma unroll
        for (int i = 0; i < 8; i++) { s += sh1[i]; s2 += sh2[i]; }
        float m   = s  * (1.f / (10 * N_TOK));
        float var = s2 * (1.f / (10 * N_TOK)) - m * m;
        g_mu[g] = m;
        g_rs[g] = rsqrtf(var + 1e-6f);
    }
}

// ---------------- GN apply + transpose -> bf16 token-major (vectorized) -------------
// grid (32, 10), 256 threads; tile: 32 c x 128 p
__global__ void __launch_bounds__(256) gn_apply_t_kernel(
    const float* __restrict__ x, const float* __restrict__ w,
    const float* __restrict__ b, bf16* __restrict__ out)
{
    __shared__ float sm[32][133];
    int p0 = blockIdx.x * 128, c0 = blockIdx.y * 32;
    int tx = threadIdx.x & 31, ty = threadIdx.x >> 5;   // load: 32 p-quads x 8 c
    #pragma unroll
    for (int i = 0; i < 4; i++) {
        int c = c0 + ty + 8 * i;
        float4 v = *(const float4*)(x + (size_t)c * N_TOK + p0 + tx * 4);
        sm[ty + 8 * i][tx * 4 + 0] = v.x;
        sm[ty + 8 * i][tx * 4 + 1] = v.y;
        sm[ty + 8 * i][tx * 4 + 2] = v.z;
        sm[ty + 8 * i][tx * 4 + 3] = v.w;
    }
    __syncthreads();
    int txc = threadIdx.x & 7, typ = threadIdx.x >> 3;  // write: 8 c-quads x 32 p
    int cb = c0 + txc * 4;
    float w0 = w[cb], w1 = w[cb + 1], w2 = w[cb + 2], w3 = w[cb + 3];
    float b0 = b[cb], b1 = b[cb + 1], b2 = b[cb + 2], b3 = b[cb + 3];
    float mu0 = g_mu[cb / 10],  rs0 = g_rs[cb / 10];
    float mu1 = g_mu[(cb+1)/10], rs1 = g_rs[(cb+1)/10];
    float mu2 = g_mu[(cb+2)/10], rs2 = g_rs[(cb+2)/10];
    float mu3 = g_mu[(cb+3)/10], rs3 = g_rs[(cb+3)/10];
    #pragma unroll
    for (int i = 0; i < 4; i++) {
        int pl = typ + 32 * i;
        float v0 = (sm[txc * 4 + 0][pl] - mu0) * rs0 * w0 + b0;
        float v1 = (sm[txc * 4 + 1][pl] - mu1) * rs1 * w1 + b1;
        float v2 = (sm[txc * 4 + 2][pl] - mu2) * rs2 * w2 + b2;
        float v3 = (sm[txc * 4 + 3][pl] - mu3) * rs3 * w3 + b3;
        uint2 pk = make_uint2(bf2pk(v0, v1), bf2pk(v2, v3));
        *(uint2*)(out + (size_t)(p0 + pl) * D + cb) = pk;
    }
}

// ---------------- LayerNorm (fp32 in, bf16 out) ----------------
__global__ void layernorm_kernel(const float* __restrict__ in,
                                 const float* __restrict__ w,
                                 const float* __restrict__ b,
                                 bf16* __restrict__ out) {
    int row = blockIdx.x;
    const float* p = in + row * D;
    int t = threadIdx.x;
    float a0 = p[t], a1 = p[t + 128];
    float a2 = (t < 64) ? p[t + 256] : 0.f;
    float s  = a0 + a1 + a2;
    float s2 = a0 * a0 + a1 * a1 + a2 * a2;
    __shared__ float sh1[4], sh2[4];
    __shared__ float mr[2];
    int lane = t & 31, wp = t >> 5;
    #pragma unroll
    for (int o = 16; o; o >>= 1) {
        s  += __shfl_xor_sync(0xffffffffu, s,  o);
        s2 += __shfl_xor_sync(0xffffffffu, s2, o);
    }
    if (lane == 0) { sh1[wp] = s; sh2[wp] = s2; }
    __syncthreads();
    if (t == 0) {
        s = sh1[0] + sh1[1] + sh1[2] + sh1[3];
        s2 = sh2[0] + sh2[1] + sh2[2] + sh2[3];
        float m = s * (1.f / D);
        float var = s2 * (1.f / D) - m * m;
        mr[0] = m; mr[1] = rsqrtf(var + 1e-5f);
    }
    __syncthreads();
    float m = mr[0], r = mr[1];
    bf16* o = out + row * D;
    o[t]       = __float2bfloat16((a0 - m) * r * w[t]       + b[t]);
    o[t + 128] = __float2bfloat16((a1 - m) * r * w[t + 128] + b[t + 128]);
    if (t < 64)
        o[t + 256] = __float2bfloat16((a2 - m) * r * w[t + 256] + b[t + 256]);
}

// ---------------- bf16 NT GEMM, cp.async 3-stage: C[M,N] = A[M,K] @ Bt[N,K]^T -------
// tile 32x64, 128 threads (warps 2x2, warp tile 16x32)
// EPI 0: C fp32 = AB + bias
// EPI 1: C fp32 = AB + bias + R
// EPI 2: C fp32 [n*M+m] = AB + bias[n] + R[n*M+m]
// EPI 3: Cb bf16 = AB (+bias)
// EPI 4: C fp32 = AB + bias + R;  Cb bf16 = same
// EPI 5: GEGLU: cols interleaved (a,g); Cb bf16 [M][N/2]: a*gelu(g); bias = ff1_b raw layout
template <int EPI>
__global__ void __launch_bounds__(128) gemm_bf16_kernel(
    const bf16* __restrict__ A, const bf16* __restrict__ Bt,
    const float* __restrict__ bias, const float* __restrict__ R,
    float* __restrict__ C, bf16* __restrict__ Cb, int M, int N, int K)
{
    __shared__ __align__(16) bf16 As[3][32][40];
    __shared__ __align__(16) bf16 Bs[3][64][40];
    int tid = threadIdx.x;
    int lane = tid & 31, wid = tid >> 5;
    int wm = wid & 1, wn = wid >> 1;
    int g = lane >> 2, t = lane & 3;
    int bm = blockIdx.y * 32, bn = blockIdx.x * 64;

    float acc[4][4];
    #pragma unroll
    for (int nf = 0; nf < 4; nf++)
        #pragma unroll
        for (int r = 0; r < 4; r++) acc[nf][r] = 0.f;

    int ar = tid >> 2, ac = (tid & 3) * 8;      // A: 32 rows x 4 chunks of 8
    int br = tid >> 1, bc = (tid & 1) * 16;     // B: 64 rows x 2 chunks of 16
    const bf16* Abase = A  + (size_t)(bm + ar) * K + ac;
    const bf16* Bbase = Bt + (size_t)(bn + br) * K + bc;
    uint32_t sA = smem_u32(&As[0][ar][ac]);
    uint32_t sB = smem_u32(&Bs[0][br][bc]);
    const int ASS = 32 * 40 * 2, BSS = 64 * 40 * 2;

    int nt = K / 32;
    #pragma unroll
    for (int s = 0; s < 2; s++) {
        cp16(sA + s * ASS, Abase + s * 32);
        cp16(sB + s * BSS, Bbase + s * 32);
        cp16(sB + s * BSS + 16, Bbase + s * 32 + 8);
        CP_COMMIT();
    }

    for (int i = 0; i < nt; i++) {
        if (i + 1 < nt) { CP_WAIT1(); } else { CP_WAIT0(); }
        __syncthreads();
        if (i + 2 < nt) {
            int s = (i + 2) % 3;
            cp16(sA + s * ASS, Abase + (i + 2) * 32);
            cp16(sB + s * BSS, Bbase + (i + 2) * 32);
            cp16(sB + s * BSS + 16, Bbase + (i + 2) * 32 + 8);
            CP_COMMIT();
        }
        int cb = i % 3;
        #pragma unroll
        for (int kk = 0; kk < 2; kk++) {
            uint32_t a[4], b[4][2];
            a[0] = *(const uint32_t*)&As[cb][wm * 16 + g    ][kk * 16 + 2 * t];
            a[1] = *(const uint32_t*)&As[cb][wm * 16 + g + 8][kk * 16 + 2 * t];
            a[2] = *(const uint32_t*)&As[cb][wm * 16 + g    ][kk * 16 + 2 * t + 8];
            a[3] = *(const uint32_t*)&As[cb][wm * 16 + g + 8][kk * 16 + 2 * t + 8];
            #pragma unroll
            for (int nf = 0; nf < 4; nf++) {
                int n = wn * 32 + nf * 8 + g;
                b[nf][0] = *(const uint32_t*)&Bs[cb][n][kk * 16 + 2 * t];
                b[nf][1] = *(const uint32_t*)&Bs[cb][n][kk * 16 + 2 * t + 8];
            }
            #pragma unroll
            for (int nf = 0; nf < 4; nf++)
                mma_bf16(acc[nf], a, b[nf]);
        }
    }

    #pragma unroll
    for (int nf = 0; nf < 4; nf++) {
        int m = bm + wm * 16 + g;
        int n = bn + wn * 32 + nf * 8 + 2 * t;
        if (EPI == 5) {
            int c2 = n >> 1;
            float ab = bias[c2], gb = bias[FFI + c2];
            float a0 = acc[nf][0] + ab, g0 = acc[nf][1] + gb;
            float a1 = acc[nf][2] + ab, g1 = acc[nf][3] + gb;
            Cb[(size_t)m * (N / 2) + c2]       = __float2bfloat16(a0 * gelu_exact(g0));
            Cb[(size_t)(m + 8) * (N / 2) + c2] = __float2bfloat16(a1 * gelu_exact(g1));
            continue;
        }
        float b0 = bias ? bias[n] : 0.f;
        float b1 = bias ? bias[n + 1] : 0.f;
        float v0 = acc[nf][0] + b0;
        float v1 = acc[nf][1] + b1;
        float v2 = acc[nf][2] + b0;
        float v3 = acc[nf][3] + b1;
        if (EPI == 2) {
            C[(size_t)n * M + m]           = v0 + R[(size_t)n * M + m];
            C[(size_t)(n + 1) * M + m]     = v1 + R[(size_t)(n + 1) * M + m];
            C[(size_t)n * M + m + 8]       = v2 + R[(size_t)n * M + m + 8];
            C[(size_t)(n + 1) * M + m + 8] = v3 + R[(size_t)(n + 1) * M + m + 8];
        } else if (EPI == 3) {
            *(uint32_t*)&Cb[(size_t)m * N + n]       = bf2pk(v0, v1);
            *(uint32_t*)&Cb[(size_t)(m + 8) * N + n] = bf2pk(v2, v3);
        } else {
            if (EPI == 1 || EPI == 4) {
                float2 r0 = *(const float2*)&R[(size_t)m * N + n];
                float2 r1 = *(const float2*)&R[(size_t)(m + 8) * N + n];
                v0 += r0.x; v1 += r0.y; v2 += r1.x; v3 += r1.y;
            }
            *(float2*)&C[(size_t)m * N + n]       = make_float2(v0, v1);
            *(float2*)&C[(size_t)(m + 8) * N + n] = make_float2(v2, v3);
            if (EPI == 4) {
                *(uint32_t*)&Cb[(size_t)m * N + n]       = bf2pk(v0, v1);
                *(uint32_t*)&Cb[(size_t)(m + 8) * N + n] = bf2pk(v2, v3);
            }
        }
    }
}

// ---------------- bf16 flash self-attention, cp.async 2-stage, 128-query blocks -----
// grid (32, 8), 256 threads = 8 warps; warp w owns query rows [w*16, w*16+16)
// V loaded row-major [key][d]; PV B-fragments via ldmatrix.x2.trans (no VT buffer)
__global__ void __launch_bounds__(256) flash_bf16_kernel(
    const bf16* __restrict__ QKV, bf16* __restrict__ O)
{
    __shared__ __align__(16) bf16 Ks[2][64][56];
    __shared__ __align__(16) bf16 Vs[2][64][40];
    __shared__ __align__(16) bf16 Ps[128][72];
    int h = blockIdx.y;
    int q0 = blockIdx.x * 128;
    int tid = threadIdx.x, wid = tid >> 5, lane = tid & 31;
    int g = lane >> 2, t = lane & 3;
    const float scale = 0.15811388300841897f;

    // zero-fill Ks pad cols [40,56), both buffers
    for (int i = tid; i < 1024; i += 256) {
        int buf = i >> 9, rem = i & 511;
        int r = rem >> 3, c = 40 + (rem & 7) * 2;
        *(uint32_t*)&Ks[buf][r][c] = 0u;
    }

    uint32_t ksb = smem_u32(&Ks[0][0][0]);
    uint32_t vsb = smem_u32(&Vs[0][0][0]);
    const int KSS = 64 * 56 * 2, VSS = 64 * 40 * 2;

    // Q fragments (k padded to 48, zeros beyond 40)
    uint32_t qa[3][4];
    {
        const bf16* qb = QKV + (size_t)(q0 + wid * 16) * 960 + h * 40;
        #pragma unroll
        for (int kk = 0; kk < 3; kk++) {
            int d = kk * 16 + 2 * t;
            qa[kk][0] = *(const uint32_t*)(qb + (size_t)g * 960 + d);
            qa[kk][1] = *(const uint32_t*)(qb + (size_t)(g + 8) * 960 + d);
            if (kk < 2) {
                qa[kk][2] = *(const uint32_t*)(qb + (size_t)g * 960 + d + 8);
                qa[kk][3] = *(const uint32_t*)(qb + (size_t)(g + 8) * 960 + d + 8);
            } else {
                qa[kk][2] = 0u; qa[kk][3] = 0u;
            }
        }
    }

    // issue tile 0
    {
        for (int idx = tid; idx < 640; idx += 256) {
            int r = idx / 10, c = (idx % 10) * 4;
            cp8(ksb + r * 112 + c * 2, QKV + (size_t)r * 960 + 320 + h * 40 + c);
            cp8(vsb + r * 80 + c * 2,  QKV + (size_t)r * 960 + 640 + h * 40 + c);
        }
        CP_COMMIT();
    }

    float o[5][4];
    #pragma unroll
    for (int nf = 0; nf < 5; nf++)
        #pragma unroll
        for (int r = 0; r < 4; r++) o[nf][r] = 0.f;
    float mA = -1e30f, mB = -1e30f, lA = 0.f, lB = 0.f;

    for (int it = 0; it < 64; it++) {
        int buf = it & 1;
        if (it < 63) {
            int k0 = (it + 1) * 64;
            uint32_t kd = ksb + (buf ^ 1) * KSS;
            uint32_t vd = vsb + (buf ^ 1) * VSS;
            for (int idx = tid; idx < 640; idx += 256) {
                int r = idx / 10, c = (idx % 10) * 4;
                cp8(kd + r * 112 + c * 2, QKV + (size_t)(k0 + r) * 960 + 320 + h * 40 + c);
                cp8(vd + r * 80 + c * 2,  QKV + (size_t)(k0 + r) * 960 + 640 + h * 40 + c);
            }
            CP_COMMIT();
            CP_WAIT1();
        } else {
            CP_WAIT0();
        }
        __syncthreads();

        // S = Q K^T  (k = 48 padded)
        float s[8][4];
        #pragma unroll
        for (int nf = 0; nf < 8; nf++)
            #pragma unroll
            for (int r = 0; r < 4; r++) s[nf][r] = 0.f;
        #pragma unroll
        for (int kk = 0; kk < 3; kk++) {
            #pragma unroll
            for (int nf = 0; nf < 8; nf++) {
                uint32_t bb[2];
                bb[0] = *(const uint32_t*)&Ks[buf][nf * 8 + g][kk * 16 + 2 * t];
                bb[1] = *(const uint32_t*)&Ks[buf][nf * 8 + g][kk * 16 + 2 * t + 8];
                mma_bf16(s[nf], qa[kk], bb);
            }
        }
        #pragma unroll
        for (int nf = 0; nf < 8; nf++)
            #pragma unroll
            for (int r = 0; r < 4; r++) s[nf][r] *= scale;

        // online softmax
        float mtA = mA, mtB = mB;
        #pragma unroll
        for (int nf = 0; nf < 8; nf++) {
            mtA = fmaxf(mtA, fmaxf(s[nf][0], s[nf][1]));
            mtB = fmaxf(mtB, fmaxf(s[nf][2], s[nf][3]));
        }
        mtA = fmaxf(mtA, __shfl_xor_sync(0xffffffffu, mtA, 1));
        mtA = fmaxf(mtA, __shfl_xor_sync(0xffffffffu, mtA, 2));
        mtB = fmaxf(mtB, __shfl_xor_sync(0xffffffffu, mtB, 1));
        mtB = fmaxf(mtB, __shfl_xor_sync(0xffffffffu, mtB, 2));
        float corrA = exp2f((mA - mtA) * LOG2E);
        float corrB = exp2f((mB - mtB) * LOG2E);
        mA = mtA; mB = mtB;
        lA *= corrA; lB *= corrB;
        #pragma unroll
        for (int nf = 0; nf < 5; nf++) {
            o[nf][0] *= corrA; o[nf][1] *= corrA;
            o[nf][2] *= corrB; o[nf][3] *= corrB;
        }
        int pr = wid * 16 + g;
        #pragma unroll
        for (int nf = 0; nf < 8; nf++) {
            float p0 = exp2f((s[nf][0] - mA) * LOG2E);
            float p1 = exp2f((s[nf][1] - mA) * LOG2E);
            float p2 = exp2f((s[nf][2] - mB) * LOG2E);
            float p3 = exp2f((s[nf][3] - mB) * LOG2E);
            lA += p0 + p1; lB += p2 + p3;
            *(uint32_t*)&Ps[pr][nf * 8 + 2 * t]     = bf2pk(p0, p1);
            *(uint32_t*)&Ps[pr + 8][nf * 8 + 2 * t] = bf2pk(p2, p3);
        }
        __syncwarp();

        // O += P V   (k = 64 keys; V row-major, B fragments via ldmatrix.trans)
        uint32_t vbase = vsb + buf * VSS;
        #pragma unroll
        for (int kk = 0; kk < 4; kk++) {
            uint32_t pa[4];
            pa[0] = *(const uint32_t*)&Ps[wid * 16 + g    ][kk * 16 + 2 * t];
            pa[1] = *(const uint32_t*)&Ps[wid * 16 + g + 8][kk * 16 + 2 * t];
            pa[2] = *(const uint32_t*)&Ps[wid * 16 + g    ][kk * 16 + 2 * t + 8];
            pa[3] = *(const uint32_t*)&Ps[wid * 16 + g + 8][kk * 16 + 2 * t + 8];
            uint32_t rowaddr = vbase + (kk * 16 + (lane & 15)) * 80;
            #pragma unroll
            for (int nf = 0; nf < 5; nf++) {
                uint32_t bb[2];
                ldmatrix_x2_trans(bb[0], bb[1], rowaddr + nf * 16);
                mma_bf16(o[nf], pa, bb);
            }
        }
        __syncthreads();
    }

    lA += __shfl_xor_sync(0xffffffffu, lA, 1);
    lA += __shfl_xor_sync(0xffffffffu, lA, 2);
    lB += __shfl_xor_sync(0xffffffffu, lB, 1);
    lB += __shfl_xor_sync(0xffffffffu, lB, 2);
    float iA = 1.f / lA, iB = 1.f / lB;
    bf16* ob = O + (size_t)(q0 + wid * 16 + g) * D + h * 40;
    #pragma unroll
    for (int nf = 0; nf < 5; nf++) {
        *(uint32_t*)(ob + nf * 8 + 2 * t) = bf2pk(o[nf][0] * iA, o[nf][1] * iA);
        *(uint32_t*)(ob + (size_t)8 * D + nf * 8 + 2 * t) = bf2pk(o[nf][2] * iB, o[nf][3] * iB);
    }
}

// ---------------- cross attention (scalar; Q bf16, 77 keys; KV merged [96][640]) ----
__global__ void __launch_bounds__(128) cross_attn_kernel(
    const bf16* __restrict__ Q, const float* __restrict__ KV, bf16* __restrict__ O)
{
    const float scale = 0.15811388300841897f;
    int h = blockIdx.y;
    int qrow = blockIdx.x * 128 + threadIdx.x;
    int tid = threadIdx.x;

    __shared__ __align__(16) float Ks[CTX_N][40];
    __shared__ __align__(16) float Vs[CTX_N][40];
    for (int i = tid; i < CTX_N * 10; i += 128) {
        int r = i / 10, c = (i % 10) * 4;
        *(float4*)&Ks[r][c] = *(const float4*)(KV + (size_t)r * 640 + h * DH + c);
        *(float4*)&Vs[r][c] = *(const float4*)(KV + (size_t)r * 640 + 320 + h * DH + c);
    }
    __syncthreads();

    float4 q4[10], a4[10];
    const bf16* qp = Q + (size_t)qrow * D + h * DH;
    #pragma unroll
    for (int dd = 0; dd < 10; dd++) {
        __nv_bfloat162 b0 = *(const __nv_bfloat162*)(qp + dd * 4);
        __nv_bfloat162 b1 = *(const __nv_bfloat162*)(qp + dd * 4 + 2);
        q4[dd] = make_float4(__low2float(b0) * scale, __high2float(b0) * scale,
                             __low2float(b1) * scale, __high2float(b1) * scale);
        a4[dd] = make_float4(0.f, 0.f, 0.f, 0.f);
    }
    float m = -1e30f, l = 0.f;
    for (int j = 0; j < CTX_N; j++) {
        float s = 0.f;
        #pragma unroll
        for (int dd = 0; dd < 10; dd++) {
            float4 kk = *(const float4*)&Ks[j][dd * 4];
            s += q4[dd].x * kk.x + q4[dd].y * kk.y + q4[dd].z * kk.z + q4[dd].w * kk.w;
        }
        float mt = fmaxf(m, s);
        float corr = __expf(m - mt);
        float p = __expf(s - mt);
        m = mt;
        l = l * corr + p;
        #pragma unroll
        for (int dd = 0; dd < 10; dd++) {
            float4 vv = *(const float4*)&Vs[j][dd * 4];
            a4[dd].x = a4[dd].x * corr + p * vv.x;
            a4[dd].y = a4[dd].y * corr + p * vv.y;
            a4[dd].z = a4[dd].z * corr + p * vv.z;
            a4[dd].w = a4[dd].w * corr + p * vv.w;
        }
    }
    float inv = 1.f / l;
    bf16* op = O + (size_t)qrow * D + h * DH;
    #pragma unroll
    for (int dd = 0; dd < 10; dd++) {
        *(uint32_t*)(op + dd * 4)     = bf2pk(a4[dd].x * inv, a4[dd].y * inv);
        *(uint32_t*)(op + dd * 4 + 2) = bf2pk(a4[dd].z * inv, a4[dd].w * inv);
    }
}

// ---------------- launch ----------------
extern "C" void kernel_launch(void* const* d_in, const int* in_sizes, int n_in,
                              void* d_out, int out_size) {
    const float* x      = (const float*)d_in[0];
    const float* ctx    = (const float*)d_in[1];
    const float* gn_w   = (const float*)d_in[2];
    const float* gn_b   = (const float*)d_in[3];
    const float* pin_w  = (const float*)d_in[4];
    const float* pin_b  = (const float*)d_in[5];
    const float* ln1_w  = (const float*)d_in[6];
    const float* ln1_b  = (const float*)d_in[7];
    const float* q1     = (const float*)d_in[8];
    const float* k1     = (const float*)d_in[9];
    const float* v1     = (const float*)d_in[10];
    const float* o1_w   = (const float*)d_in[11];
    const float* o1_b   = (const float*)d_in[12];
    const float* ln2_w  = (const float*)d_in[13];
    const float* ln2_b  = (const float*)d_in[14];
    const float* q2     = (const float*)d_in[15];
    const float* k2     = (const float*)d_in[16];
    const float* v2     = (const float*)d_in[17];
    const float* o2_w   = (const float*)d_in[18];
    const float* o2_b   = (const float*)d_in[19];
    const float* ln3_w  = (const float*)d_in[20];
    const float* ln3_b  = (const float*)d_in[21];
    const float* ff1_w  = (const float*)d_in[22];
    const float* ff1_b  = (const float*)d_in[23];
    const float* ff2_w  = (const float*)d_in[24];
    const float* ff2_b  = (const float*)d_in[25];
    const float* pout_w = (const float*)d_in[26];
    const float* pout_b = (const float*)d_in[27];
    float* out = (float*)d_out;

    float *p_h, *p_h2, *p_kvc;
    bf16 *p_lnb, *p_qkvb, *p_attnb, *p_q2b, *p_h2b, *p_ffgb, *p_ctxb;
    bf16 *p_wqkv, *p_wo1, *p_wq2, *p_wo2, *p_wff1, *p_wff2, *p_wpin, *p_wpout, *p_wkv2;
    cudaGetSymbolAddress((void**)&p_h,    g_h);
    cudaGetSymbolAddress((void**)&p_h2,   g_h2);
    cudaGetSymbolAddress((void**)&p_kvc,  g_kvc);
    cudaGetSymbolAddress((void**)&p_lnb,  g_lnb);
    cudaGetSymbolAddress((void**)&p_qkvb, g_qkvb);
    cudaGetSymbolAddress((void**)&p_attnb,g_attnb);
    cudaGetSymbolAddress((void**)&p_q2b,  g_q2b);
    cudaGetSymbolAddress((void**)&p_h2b,  g_h2b);
    cudaGetSymbolAddress((void**)&p_ffgb, g_ffgb);
    cudaGetSymbolAddress((void**)&p_ctxb, g_ctxb);
    cudaGetSymbolAddress((void**)&p_wqkv, g_wqkv);
    cudaGetSymbolAddress((void**)&p_wo1,  g_wo1);
    cudaGetSymbolAddress((void**)&p_wq2,  g_wq2);
    cudaGetSymbolAddress((void**)&p_wo2,  g_wo2);
    cudaGetSymbolAddress((void**)&p_wff1, g_wff1);
    cudaGetSymbolAddress((void**)&p_wff2, g_wff2);
    cudaGetSymbolAddress((void**)&p_wpin, g_wpin);
    cudaGetSymbolAddress((void**)&p_wpout,g_wpout);
    cudaGetSymbolAddress((void**)&p_wkv2, g_wkv2);

    dim3 gD(D / 64, N_TOK / 32);            // (5, 128)

    // weight prep + ctx conversion + GroupNorm
    prep_weights_kernel<<<2480, 256>>>(q1, k1, v1, o1_w, q2, o2_w, ff1_w, ff2_w, pin_w, pout_w, k2, v2);
    ctx_conv_kernel<<<(CTX_M * CTX_D) / 256, 256>>>(ctx);
    gn_stats_kernel<<<GROUPS, 256>>>(x);
    gn_apply_t_kernel<<<dim3(32, 10), 256>>>(x, gn_w, gn_b, p_lnb);
    gemm_bf16_kernel<0><<<gD, 128>>>(p_lnb, p_wpin, pin_b, nullptr, p_h, nullptr, N_TOK, D, D);

    // self-attention
    layernorm_kernel<<<N_TOK, 128>>>(p_h, ln1_w, ln1_b, p_lnb);
    gemm_bf16_kernel<3><<<dim3(3 * D / 64, N_TOK / 32), 128>>>(p_lnb, p_wqkv, nullptr, nullptr, nullptr, p_qkvb, N_TOK, 3 * D, D);
    flash_bf16_kernel<<<dim3(N_TOK / 128, HEADS), 256>>>(p_qkvb, p_attnb);
    gemm_bf16_kernel<1><<<gD, 128>>>(p_attnb, p_wo1, o1_b, p_h, p_h2, nullptr, N_TOK, D, D);

    // cross-attention
    layernorm_kernel<<<N_TOK, 128>>>(p_h2, ln2_w, ln2_b, p_lnb);
    gemm_bf16_kernel<3><<<gD, 128>>>(p_lnb, p_wq2, nullptr, nullptr, nullptr, p_q2b, N_TOK, D, D);
    gemm_bf16_kernel<0><<<dim3(2 * D / 64, CTX_M / 32), 128>>>(p_ctxb, p_wkv2, nullptr, nullptr, p_kvc, nullptr, CTX_M, 2 * D, CTX_D);
    cross_attn_kernel<<<dim3(N_TOK / 128, HEADS), 128>>>(p_q2b, p_kvc, p_attnb);
    gemm_bf16_kernel<1><<<gD, 128>>>(p_attnb, p_wo2, o2_b, p_h2, p_h, nullptr, N_TOK, D, D);

    // GEGLU FF (fused into ff1 epilogue via interleaved weights)
    layernorm_kernel<<<N_TOK, 128>>>(p_h, ln3_w, ln3_b, p_lnb);
    gemm_bf16_kernel<5><<<dim3(2 * FFI / 64, N_TOK / 32), 128>>>(p_lnb, p_wff1, ff1_b, nullptr, nullptr, p_ffgb, N_TOK, 2 * FFI, D);
    gemm_bf16_kernel<4><<<gD, 128>>>(p_ffgb, p_wff2, ff2_b, p_h, p_h2, p_h2b, N_TOK, D, FFI);

    // proj_out + residual (transposed store back to [C][HW])
    gemm_bf16_kernel<2><<<gD, 128>>>(p_h2b, p_wpout, pout_b, x, out, nullptr, N_TOK, D, D);
}

// round 9
// speedup vs baseline: 4.8317x; 1.0635x over previous
#include <cuda_runtime.h>
#include <cuda_bf16.h>
#include <math.h>
#include <stdint.h>

#define N_TOK 4096
#define D     320
#define HEADS 8
#define DH    40
#define CTX_N 77
#define CTX_M 96
#define CTX_D 768
#define FFI   1280
#define GROUPS 32
#define LOG2E 1.4426950408889634f

typedef __nv_bfloat16 bf16;

// ---------------- scratch ----------------
__device__ float g_h  [N_TOK * D];
__device__ float g_h2 [N_TOK * D];
__device__ float g_kvc[CTX_M * 2 * D];
__device__ float g_mu [GROUPS];
__device__ float g_rs [GROUPS];

__device__ bf16 g_lnb [N_TOK * D];
__device__ bf16 g_qkvb[N_TOK * 3 * D];
__device__ bf16 g_attnb[N_TOK * D];
__device__ bf16 g_q2b [N_TOK * D];
__device__ bf16 g_h2b [N_TOK * D];
__device__ bf16 g_ffgb[N_TOK * FFI];
__device__ bf16 g_ctxb[CTX_M * CTX_D];

// weights, bf16, stored as B^T = [N][K]
__device__ bf16 g_wqkv[3 * D * D];
__device__ bf16 g_wo1 [D * D];
__device__ bf16 g_wq2 [D * D];
__device__ bf16 g_wo2 [D * D];
__device__ bf16 g_wff1[2 * FFI * D];     // INTERLEAVED: row 2c = a_c, row 2c+1 = g_c
__device__ bf16 g_wff2[D * FFI];
__device__ bf16 g_wpin[D * D];
__device__ bf16 g_wpout[D * D];
__device__ bf16 g_wkv2[2 * D * CTX_D];   // rows 0-319 = k2^T, 320-639 = v2^T

// ---------------- helpers ----------------
__device__ __forceinline__ uint32_t bf2pk(float lo, float hi) {
    uint32_t r;
    asm("cvt.rn.bf16x2.f32 %0, %1, %2;" : "=r"(r) : "f"(hi), "f"(lo));
    return r;
}
__device__ __forceinline__ void mma_bf16(float* c, const uint32_t* a, const uint32_t* b) {
    asm volatile(
        "mma.sync.aligned.m16n8k16.row.col.f32.bf16.bf16.f32 "
        "{%0,%1,%2,%3}, {%4,%5,%6,%7}, {%8,%9}, {%0,%1,%2,%3};"
        : "+f"(c[0]), "+f"(c[1]), "+f"(c[2]), "+f"(c[3])
        : "r"(a[0]), "r"(a[1]), "r"(a[2]), "r"(a[3]), "r"(b[0]), "r"(b[1]));
}
__device__ __forceinline__ void mma_bf16_k8(float* c, const uint32_t* a, uint32_t b) {
    asm volatile(
        "mma.sync.aligned.m16n8k8.row.col.f32.bf16.bf16.f32 "
        "{%0,%1,%2,%3}, {%4,%5}, {%6}, {%0,%1,%2,%3};"
        : "+f"(c[0]), "+f"(c[1]), "+f"(c[2]), "+f"(c[3])
        : "r"(a[0]), "r"(a[1]), "r"(b));
}
__device__ __forceinline__ uint32_t smem_u32(const void* p) {
    return (uint32_t)__cvta_generic_to_shared(p);
}
__device__ __forceinline__ void cp16(uint32_t dst, const void* src) {
    asm volatile("cp.async.cg.shared.global [%0], [%1], 16;" :: "r"(dst), "l"(src));
}
__device__ __forceinline__ void cp8(uint32_t dst, const void* src) {
    asm volatile("cp.async.ca.shared.global [%0], [%1], 8;" :: "r"(dst), "l"(src));
}
#define CP_COMMIT() asm volatile("cp.async.commit_group;")
#define CP_WAIT1()  asm volatile("cp.async.wait_group 1;")
#define CP_WAIT0()  asm volatile("cp.async.wait_group 0;")

__device__ __forceinline__ float gelu_exact(float g) {
    return 0.5f * g * (1.f + erff(g * 0.70710678118654752f));
}
__device__ __forceinline__ void ldmatrix_x2_trans(uint32_t& d0, uint32_t& d1, uint32_t addr) {
    asm volatile("ldmatrix.sync.aligned.m8n8.x2.trans.shared.b16 {%0,%1}, [%2];"
                 : "=r"(d0), "=r"(d1) : "r"(addr));
}
__device__ __forceinline__ void ldmatrix_x4(uint32_t& d0, uint32_t& d1, uint32_t& d2,
                                            uint32_t& d3, uint32_t addr) {
    asm volatile("ldmatrix.sync.aligned.m8n8.x4.shared.b16 {%0,%1,%2,%3}, [%4];"
                 : "=r"(d0), "=r"(d1), "=r"(d2), "=r"(d3) : "r"(addr));
}

// ---------------- weight prep (+ ctx conversion fused) ------------------------------
__global__ void __launch_bounds__(256) prep_weights_kernel(
    const float* __restrict__ q1, const float* __restrict__ k1, const float* __restrict__ v1,
    const float* __restrict__ o1, const float* __restrict__ q2, const float* __restrict__ o2,
    const float* __restrict__ ff1, const float* __restrict__ ff2,
    const float* __restrict__ pin, const float* __restrict__ pout,
    const float* __restrict__ k2, const float* __restrict__ v2,
    const float* __restrict__ ctx)
{
    int b = blockIdx.x;
    int tx = threadIdx.x & 31, ty = threadIdx.x >> 5;   // 32 x 8
    if (b < 2280) {
        __shared__ float sm[32][33];
        const float* src; bf16* dst; int R, C, tile; bool ileave = false;
        if (b < 100)       { src = q1;  dst = g_wqkv;            R = 320;  C = 320;  tile = b; }
        else if (b < 200)  { src = k1;  dst = g_wqkv + 320*320;  R = 320;  C = 320;  tile = b - 100; }
        else if (b < 300)  { src = v1;  dst = g_wqkv + 640*320;  R = 320;  C = 320;  tile = b - 200; }
        else if (b < 400)  { src = o1;  dst = g_wo1;             R = 320;  C = 320;  tile = b - 300; }
        else if (b < 500)  { src = q2;  dst = g_wq2;             R = 320;  C = 320;  tile = b - 400; }
        else if (b < 600)  { src = o2;  dst = g_wo2;             R = 320;  C = 320;  tile = b - 500; }
        else if (b < 1400) { src = ff1; dst = g_wff1;            R = 320;  C = 2560; tile = b - 600; ileave = true; }
        else if (b < 1800) { src = ff2; dst = g_wff2;            R = 1280; C = 320;  tile = b - 1400; }
        else if (b < 2040) { src = k2;  dst = g_wkv2;            R = 768;  C = 320;  tile = b - 1800; }
        else               { src = v2;  dst = g_wkv2 + 320*768;  R = 768;  C = 320;  tile = b - 2040; }
        int tc = C / 32;
        int r0 = (tile / tc) * 32, c0 = (tile % tc) * 32;
        #pragma unroll
        for (int i = 0; i < 4; i++)
            sm[ty + 8 * i][tx] = src[(size_t)(r0 + ty + 8 * i) * C + c0 + tx];
        __syncthreads();
        #pragma unroll
        for (int i = 0; i < 4; i++) {
            int sc = c0 + ty + 8 * i;
            int dr = ileave ? ((sc < FFI) ? 2 * sc : 2 * (sc - FFI) + 1) : sc;
            dst[(size_t)dr * R + r0 + tx] = __float2bfloat16(sm[tx][ty + 8 * i]);
        }
    } else if (b < 2480) {
        const float* src = (b < 2380) ? pin : pout;
        bf16* dst = (b < 2380) ? g_wpin : g_wpout;
        int seg = b - ((b < 2380) ? 2280 : 2380);
        int base = seg * 1024 + threadIdx.x * 4;
        #pragma unroll
        for (int j = 0; j < 4; j++)
            dst[base + j] = __float2bfloat16(src[base + j]);
    } else {
        int i = (b - 2480) * 256 + threadIdx.x;     // over 96*768
        int r = i / CTX_D;
        float v = (r < CTX_N) ? ctx[(size_t)r * CTX_D + (i % CTX_D)] : 0.f;
        g_ctxb[i] = __float2bfloat16(v);
    }
}

// ---------------- GroupNorm stats (float4) ----------------
__global__ void gn_stats_kernel(const float* __restrict__ x) {
    int g = blockIdx.x;
    const float4* p = (const float4*)(x + g * (10 * N_TOK));
    float s = 0.f, s2 = 0.f;
    for (int i = threadIdx.x; i < 10 * N_TOK / 4; i += 256) {
        float4 v = p[i];
        s  += v.x + v.y + v.z + v.w;
        s2 += v.x * v.x + v.y * v.y + v.z * v.z + v.w * v.w;
    }
    __shared__ float sh1[8], sh2[8];
    int lane = threadIdx.x & 31, w = threadIdx.x >> 5;
    #pragma unroll
    for (int o = 16; o; o >>= 1) {
        s  += __shfl_xor_sync(0xffffffffu, s,  o);
        s2 += __shfl_xor_sync(0xffffffffu, s2, o);
    }
    if (lane == 0) { sh1[w] = s; sh2[w] = s2; }
    __syncthreads();
    if (threadIdx.x == 0) {
        s = 0.f; s2 = 0.f;
        #pragma unroll
        for (int i = 0; i < 8; i++) { s += sh1[i]; s2 += sh2[i]; }
        float m   = s  * (1.f / (10 * N_TOK));
        float var = s2 * (1.f / (10 * N_TOK)) - m * m;
        g_mu[g] = m;
        g_rs[g] = rsqrtf(var + 1e-6f);
    }
}

// ---------------- GN apply + transpose -> bf16 token-major (vectorized) -------------
__global__ void __launch_bounds__(256) gn_apply_t_kernel(
    const float* __restrict__ x, const float* __restrict__ w,
    const float* __restrict__ b, bf16* __restrict__ out)
{
    __shared__ float sm[32][133];
    int p0 = blockIdx.x * 128, c0 = blockIdx.y * 32;
    int tx = threadIdx.x & 31, ty = threadIdx.x >> 5;
    #pragma unroll
    for (int i = 0; i < 4; i++) {
        int c = c0 + ty + 8 * i;
        float4 v = *(const float4*)(x + (size_t)c * N_TOK + p0 + tx * 4);
        sm[ty + 8 * i][tx * 4 + 0] = v.x;
        sm[ty + 8 * i][tx * 4 + 1] = v.y;
        sm[ty + 8 * i][tx * 4 + 2] = v.z;
        sm[ty + 8 * i][tx * 4 + 3] = v.w;
    }
    __syncthreads();
    int txc = threadIdx.x & 7, typ = threadIdx.x >> 3;
    int cb = c0 + txc * 4;
    float w0 = w[cb], w1 = w[cb + 1], w2 = w[cb + 2], w3 = w[cb + 3];
    float b0 = b[cb], b1 = b[cb + 1], b2 = b[cb + 2], b3 = b[cb + 3];
    float mu0 = g_mu[cb / 10],  rs0 = g_rs[cb / 10];
    float mu1 = g_mu[(cb+1)/10], rs1 = g_rs[(cb+1)/10];
    float mu2 = g_mu[(cb+2)/10], rs2 = g_rs[(cb+2)/10];
    float mu3 = g_mu[(cb+3)/10], rs3 = g_rs[(cb+3)/10];
    #pragma unroll
    for (int i = 0; i < 4; i++) {
        int pl = typ + 32 * i;
        float v0 = (sm[txc * 4 + 0][pl] - mu0) * rs0 * w0 + b0;
        float v1 = (sm[txc * 4 + 1][pl] - mu1) * rs1 * w1 + b1;
        float v2 = (sm[txc * 4 + 2][pl] - mu2) * rs2 * w2 + b2;
        float v3 = (sm[txc * 4 + 3][pl] - mu3) * rs3 * w3 + b3;
        uint2 pk = make_uint2(bf2pk(v0, v1), bf2pk(v2, v3));
        *(uint2*)(out + (size_t)(p0 + pl) * D + cb) = pk;
    }
}

// ---------------- LayerNorm (fp32 in, bf16 out) ----------------
__global__ void layernorm_kernel(const float* __restrict__ in,
                                 const float* __restrict__ w,
                                 const float* __restrict__ b,
                                 bf16* __restrict__ out) {
    int row = blockIdx.x;
    const float* p = in + row * D;
    int t = threadIdx.x;
    float a0 = p[t], a1 = p[t + 128];
    float a2 = (t < 64) ? p[t + 256] : 0.f;
    float s  = a0 + a1 + a2;
    float s2 = a0 * a0 + a1 * a1 + a2 * a2;
    __shared__ float sh1[4], sh2[4];
    __shared__ float mr[2];
    int lane = t & 31, wp = t >> 5;
    #pragma unroll
    for (int o = 16; o; o >>= 1) {
        s  += __shfl_xor_sync(0xffffffffu, s,  o);
        s2 += __shfl_xor_sync(0xffffffffu, s2, o);
    }
    if (lane == 0) { sh1[wp] = s; sh2[wp] = s2; }
    __syncthreads();
    if (t == 0) {
        s = sh1[0] + sh1[1] + sh1[2] + sh1[3];
        s2 = sh2[0] + sh2[1] + sh2[2] + sh2[3];
        float m = s * (1.f / D);
        float var = s2 * (1.f / D) - m * m;
        mr[0] = m; mr[1] = rsqrtf(var + 1e-5f);
    }
    __syncthreads();
    float m = mr[0], r = mr[1];
    bf16* o = out + row * D;
    o[t]       = __float2bfloat16((a0 - m) * r * w[t]       + b[t]);
    o[t + 128] = __float2bfloat16((a1 - m) * r * w[t + 128] + b[t + 128]);
    if (t < 64)
        o[t + 256] = __float2bfloat16((a2 - m) * r * w[t + 256] + b[t + 256]);
}

// ---------------- bf16 NT GEMM, cp.async 3-stage, ldmatrix fragments ----------------
// tile 32x64, 128 threads (warps 2x2, warp tile 16x32)
template <int EPI>
__global__ void __launch_bounds__(128) gemm_bf16_kernel(
    const bf16* __restrict__ A, const bf16* __restrict__ Bt,
    const float* __restrict__ bias, const float* __restrict__ R,
    float* __restrict__ C, bf16* __restrict__ Cb, int M, int N, int K)
{
    __shared__ __align__(16) bf16 As[3][32][40];
    __shared__ __align__(16) bf16 Bs[3][64][40];
    int tid = threadIdx.x;
    int lane = tid & 31, wid = tid >> 5;
    int wm = wid & 1, wn = wid >> 1;
    int g = lane >> 2, t = lane & 3;
    int bm = blockIdx.y * 32, bn = blockIdx.x * 64;

    float acc[4][4];
    #pragma unroll
    for (int nf = 0; nf < 4; nf++)
        #pragma unroll
        for (int r = 0; r < 4; r++) acc[nf][r] = 0.f;

    int ar = tid >> 2, ac = (tid & 3) * 8;
    int br = tid >> 1, bc = (tid & 1) * 16;
    const bf16* Abase = A  + (size_t)(bm + ar) * K + ac;
    const bf16* Bbase = Bt + (size_t)(bn + br) * K + bc;
    uint32_t sA = smem_u32(&As[0][ar][ac]);
    uint32_t sB = smem_u32(&Bs[0][br][bc]);
    uint32_t sA0 = smem_u32(&As[0][0][0]);
    uint32_t sB0 = smem_u32(&Bs[0][0][0]);
    const int ASS = 32 * 40 * 2, BSS = 64 * 40 * 2;

    // ldmatrix lane address bases (bytes)
    uint32_t aBase = sA0 + (uint32_t)((wm * 16 + (lane & 15)) * 40 + (lane >> 4) * 8) * 2;
    uint32_t bBase = sB0 + (uint32_t)((wn * 32 + (lane & 7) + ((lane & 16) ? 8 : 0)) * 40
                                      + ((lane & 8) ? 8 : 0)) * 2;

    int nt = K / 32;
    #pragma unroll
    for (int s = 0; s < 2; s++) {
        cp16(sA + s * ASS, Abase + s * 32);
        cp16(sB + s * BSS, Bbase + s * 32);
        cp16(sB + s * BSS + 16, Bbase + s * 32 + 8);
        CP_COMMIT();
    }

    for (int i = 0; i < nt; i++) {
        if (i + 1 < nt) { CP_WAIT1(); } else { CP_WAIT0(); }
        __syncthreads();
        if (i + 2 < nt) {
            int s = (i + 2) % 3;
            cp16(sA + s * ASS, Abase + (i + 2) * 32);
            cp16(sB + s * BSS, Bbase + (i + 2) * 32);
            cp16(sB + s * BSS + 16, Bbase + (i + 2) * 32 + 8);
            CP_COMMIT();
        }
        int cb = i % 3;
        uint32_t aAddr = aBase + cb * ASS;
        uint32_t bAddr = bBase + cb * BSS;
        #pragma unroll
        for (int kk = 0; kk < 2; kk++) {
            uint32_t a[4], b01[4], b23[4];
            ldmatrix_x4(a[0], a[1], a[2], a[3], aAddr + kk * 32);
            ldmatrix_x4(b01[0], b01[1], b01[2], b01[3], bAddr + kk * 32);
            ldmatrix_x4(b23[0], b23[1], b23[2], b23[3], bAddr + 1280 + kk * 32);
            mma_bf16(acc[0], a, b01 + 0);
            mma_bf16(acc[1], a, b01 + 2);
            mma_bf16(acc[2], a, b23 + 0);
            mma_bf16(acc[3], a, b23 + 2);
        }
    }

    #pragma unroll
    for (int nf = 0; nf < 4; nf++) {
        int m = bm + wm * 16 + g;
        int n = bn + wn * 32 + nf * 8 + 2 * t;
        if (EPI == 5) {
            int c2 = n >> 1;
            float ab = bias[c2], gb = bias[FFI + c2];
            float a0 = acc[nf][0] + ab, g0 = acc[nf][1] + gb;
            float a1 = acc[nf][2] + ab, g1 = acc[nf][3] + gb;
            Cb[(size_t)m * (N / 2) + c2]       = __float2bfloat16(a0 * gelu_exact(g0));
            Cb[(size_t)(m + 8) * (N / 2) + c2] = __float2bfloat16(a1 * gelu_exact(g1));
            continue;
        }
        float b0 = bias ? bias[n] : 0.f;
        float b1 = bias ? bias[n + 1] : 0.f;
        float v0 = acc[nf][0] + b0;
        float v1 = acc[nf][1] + b1;
        float v2 = acc[nf][2] + b0;
        float v3 = acc[nf][3] + b1;
        if (EPI == 2) {
            C[(size_t)n * M + m]           = v0 + R[(size_t)n * M + m];
            C[(size_t)(n + 1) * M + m]     = v1 + R[(size_t)(n + 1) * M + m];
            C[(size_t)n * M + m + 8]       = v2 + R[(size_t)n * M + m + 8];
            C[(size_t)(n + 1) * M + m + 8] = v3 + R[(size_t)(n + 1) * M + m + 8];
        } else if (EPI == 3) {
            *(uint32_t*)&Cb[(size_t)m * N + n]       = bf2pk(v0, v1);
            *(uint32_t*)&Cb[(size_t)(m + 8) * N + n] = bf2pk(v2, v3);
        } else {
            if (EPI == 1 || EPI == 4) {
                float2 r0 = *(const float2*)&R[(size_t)m * N + n];
                float2 r1 = *(const float2*)&R[(size_t)(m + 8) * N + n];
                v0 += r0.x; v1 += r0.y; v2 += r1.x; v3 += r1.y;
            }
            *(float2*)&C[(size_t)m * N + n]       = make_float2(v0, v1);
            *(float2*)&C[(size_t)(m + 8) * N + n] = make_float2(v2, v3);
            if (EPI == 4) {
                *(uint32_t*)&Cb[(size_t)m * N + n]       = bf2pk(v0, v1);
                *(uint32_t*)&Cb[(size_t)(m + 8) * N + n] = bf2pk(v2, v3);
            }
        }
    }
}

// ---------------- bf16 flash self-attention, cp.async 2-stage, ldmatrix -------------
// grid (32, 8), 256 threads = 8 warps; warp w owns query rows [w*16, w*16+16)
__global__ void __launch_bounds__(256) flash_bf16_kernel(
    const bf16* __restrict__ QKV, bf16* __restrict__ O)
{
    __shared__ __align__(16) bf16 Ks[2][64][40];
    __shared__ __align__(16) bf16 Vs[2][64][40];
    __shared__ __align__(16) bf16 Ps[128][72];
    int h = blockIdx.y;
    int q0 = blockIdx.x * 128;
    int tid = threadIdx.x, wid = tid >> 5, lane = tid & 31;
    int g = lane >> 2, t = lane & 3;
    const float sclog = 0.15811388300841897f * LOG2E;   // scale folded into exp2

    uint32_t ksb = smem_u32(&Ks[0][0][0]);
    uint32_t vsb = smem_u32(&Vs[0][0][0]);
    uint32_t psb = smem_u32(&Ps[0][0]);
    const int KSS = 64 * 40 * 2, VSS = 64 * 40 * 2;

    // ldmatrix lane bases (bytes)
    uint32_t k16Base = (uint32_t)((lane & 7) + ((lane & 16) ? 8 : 0)) * 80
                       + ((lane & 8) ? 16 : 0);
    uint32_t k8Base  = (uint32_t)lane * 80 + 64;
    uint32_t pBase   = psb + (uint32_t)(wid * 16 + (lane & 15)) * 144 + (lane >> 4) * 16;

    // Q fragments: 2 full k16 + 1 k8 tail
    uint32_t qa[2][4], qa2[2];
    {
        const bf16* qb = QKV + (size_t)(q0 + wid * 16) * 960 + h * 40;
        #pragma unroll
        for (int kk = 0; kk < 2; kk++) {
            int d = kk * 16 + 2 * t;
            qa[kk][0] = *(const uint32_t*)(qb + (size_t)g * 960 + d);
            qa[kk][1] = *(const uint32_t*)(qb + (size_t)(g + 8) * 960 + d);
            qa[kk][2] = *(const uint32_t*)(qb + (size_t)g * 960 + d + 8);
            qa[kk][3] = *(const uint32_t*)(qb + (size_t)(g + 8) * 960 + d + 8);
        }
        qa2[0] = *(const uint32_t*)(qb + (size_t)g * 960 + 32 + 2 * t);
        qa2[1] = *(const uint32_t*)(qb + (size_t)(g + 8) * 960 + 32 + 2 * t);
    }

    // issue tile 0
    {
        for (int idx = tid; idx < 640; idx += 256) {
            int r = idx / 10, c = (idx % 10) * 4;
            cp8(ksb + r * 80 + c * 2, QKV + (size_t)r * 960 + 320 + h * 40 + c);
            cp8(vsb + r * 80 + c * 2, QKV + (size_t)r * 960 + 640 + h * 40 + c);
        }
        CP_COMMIT();
    }

    float o[5][4];
    #pragma unroll
    for (int nf = 0; nf < 5; nf++)
        #pragma unroll
        for (int r = 0; r < 4; r++) o[nf][r] = 0.f;
    float mA = -1e30f, mB = -1e30f, lA = 0.f, lB = 0.f;

    for (int it = 0; it < 64; it++) {
        int buf = it & 1;
        if (it < 63) {
            int k0 = (it + 1) * 64;
            uint32_t kd = ksb + (buf ^ 1) * KSS;
            uint32_t vd = vsb + (buf ^ 1) * VSS;
            for (int idx = tid; idx < 640; idx += 256) {
                int r = idx / 10, c = (idx % 10) * 4;
                cp8(kd + r * 80 + c * 2, QKV + (size_t)(k0 + r) * 960 + 320 + h * 40 + c);
                cp8(vd + r * 80 + c * 2, QKV + (size_t)(k0 + r) * 960 + 640 + h * 40 + c);
            }
            CP_COMMIT();
            CP_WAIT1();
        } else {
            CP_WAIT0();
        }
        __syncthreads();

        // S = Q K^T  (2x k16 + 1x k8, no padding)
        float s[8][4];
        #pragma unroll
        for (int nf = 0; nf < 8; nf++)
            #pragma unroll
            for (int r = 0; r < 4; r++) s[nf][r] = 0.f;
        uint32_t kbuf = ksb + buf * KSS;
        #pragma unroll
        for (int kk = 0; kk < 2; kk++) {
            #pragma unroll
            for (int nfp = 0; nfp < 4; nfp++) {
                uint32_t b4[4];
                ldmatrix_x4(b4[0], b4[1], b4[2], b4[3],
                            kbuf + k16Base + nfp * 1280 + kk * 32);
                mma_bf16(s[2 * nfp],     qa[kk], b4 + 0);
                mma_bf16(s[2 * nfp + 1], qa[kk], b4 + 2);
            }
        }
        #pragma unroll
        for (int half = 0; half < 2; half++) {
            uint32_t b4[4];
            ldmatrix_x4(b4[0], b4[1], b4[2], b4[3], kbuf + k8Base + half * 2560);
            mma_bf16_k8(s[half * 4 + 0], qa2, b4[0]);
            mma_bf16_k8(s[half * 4 + 1], qa2, b4[1]);
            mma_bf16_k8(s[half * 4 + 2], qa2, b4[2]);
            mma_bf16_k8(s[half * 4 + 3], qa2, b4[3]);
        }

        // online softmax (s unscaled; scale folded into sclog)
        float mtA = mA, mtB = mB;
        #pragma unroll
        for (int nf = 0; nf < 8; nf++) {
            mtA = fmaxf(mtA, fmaxf(s[nf][0], s[nf][1]));
            mtB = fmaxf(mtB, fmaxf(s[nf][2], s[nf][3]));
        }
        mtA = fmaxf(mtA, __shfl_xor_sync(0xffffffffu, mtA, 1));
        mtA = fmaxf(mtA, __shfl_xor_sync(0xffffffffu, mtA, 2));
        mtB = fmaxf(mtB, __shfl_xor_sync(0xffffffffu, mtB, 1));
        mtB = fmaxf(mtB, __shfl_xor_sync(0xffffffffu, mtB, 2));
        float corrA = exp2f((mA - mtA) * sclog);
        float corrB = exp2f((mB - mtB) * sclog);
        mA = mtA; mB = mtB;
        lA *= corrA; lB *= corrB;
        #pragma unroll
        for (int nf = 0; nf < 5; nf++) {
            o[nf][0] *= corrA; o[nf][1] *= corrA;
            o[nf][2] *= corrB; o[nf][3] *= corrB;
        }
        int pr = wid * 16 + g;
        #pragma unroll
        for (int nf = 0; nf < 8; nf++) {
            float p0 = exp2f((s[nf][0] - mA) * sclog);
            float p1 = exp2f((s[nf][1] - mA) * sclog);
            float p2 = exp2f((s[nf][2] - mB) * sclog);
            float p3 = exp2f((s[nf][3] - mB) * sclog);
            lA += p0 + p1; lB += p2 + p3;
            *(uint32_t*)&Ps[pr][nf * 8 + 2 * t]     = bf2pk(p0, p1);
            *(uint32_t*)&Ps[pr + 8][nf * 8 + 2 * t] = bf2pk(p2, p3);
        }
        __syncwarp();

        // O += P V  (P A-frags via ldmatrix.x4; V B-frags via ldmatrix.x2.trans)
        uint32_t vbase = vsb + buf * VSS;
        #pragma unroll
        for (int kk = 0; kk < 4; kk++) {
            uint32_t pa[4];
            ldmatrix_x4(pa[0], pa[1], pa[2], pa[3], pBase + kk * 32);
            uint32_t rowaddr = vbase + (kk * 16 + (lane & 15)) * 80;
            #pragma unroll
            for (int nf = 0; nf < 5; nf++) {
                uint32_t bb[2];
                ldmatrix_x2_trans(bb[0], bb[1], rowaddr + nf * 16);
                mma_bf16(o[nf], pa, bb);
            }
        }
        __syncthreads();
    }

    lA += __shfl_xor_sync(0xffffffffu, lA, 1);
    lA += __shfl_xor_sync(0xffffffffu, lA, 2);
    lB += __shfl_xor_sync(0xffffffffu, lB, 1);
    lB += __shfl_xor_sync(0xffffffffu, lB, 2);
    float iA = 1.f / lA, iB = 1.f / lB;
    bf16* ob = O + (size_t)(q0 + wid * 16 + g) * D + h * 40;
    #pragma unroll
    for (int nf = 0; nf < 5; nf++) {
        *(uint32_t*)(ob + nf * 8 + 2 * t) = bf2pk(o[nf][0] * iA, o[nf][1] * iA);
        *(uint32_t*)(ob + (size_t)8 * D + nf * 8 + 2 * t) = bf2pk(o[nf][2] * iB, o[nf][3] * iB);
    }
}

// ---------------- cross attention (scalar; Q bf16, 77 keys; KV merged [96][640]) ----
__global__ void __launch_bounds__(128) cross_attn_kernel(
    const bf16* __restrict__ Q, const float* __restrict__ KV, bf16* __restrict__ O)
{
    const float scale = 0.15811388300841897f;
    int h = blockIdx.y;
    int qrow = blockIdx.x * 128 + threadIdx.x;
    int tid = threadIdx.x;

    __shared__ __align__(16) float Ks[CTX_N][40];
    __shared__ __align__(16) float Vs[CTX_N][40];
    for (int i = tid; i < CTX_N * 10; i += 128) {
        int r = i / 10, c = (i % 10) * 4;
        *(float4*)&Ks[r][c] = *(const float4*)(KV + (size_t)r * 640 + h * DH + c);
        *(float4*)&Vs[r][c] = *(const float4*)(KV + (size_t)r * 640 + 320 + h * DH + c);
    }
    __syncthreads();

    float4 q4[10], a4[10];
    const bf16* qp = Q + (size_t)qrow * D + h * DH;
    #pragma unroll
    for (int dd = 0; dd < 10; dd++) {
        __nv_bfloat162 b0 = *(const __nv_bfloat162*)(qp + dd * 4);
        __nv_bfloat162 b1 = *(const __nv_bfloat162*)(qp + dd * 4 + 2);
        q4[dd] = make_float4(__low2float(b0) * scale, __high2float(b0) * scale,
                             __low2float(b1) * scale, __high2float(b1) * scale);
        a4[dd] = make_float4(0.f, 0.f, 0.f, 0.f);
    }
    float m = -1e30f, l = 0.f;
    for (int j = 0; j < CTX_N; j++) {
        float s = 0.f;
        #pragma unroll
        for (int dd = 0; dd < 10; dd++) {
            float4 kk = *(const float4*)&Ks[j][dd * 4];
            s += q4[dd].x * kk.x + q4[dd].y * kk.y + q4[dd].z * kk.z + q4[dd].w * kk.w;
        }
        float mt = fmaxf(m, s);
        float corr = __expf(m - mt);
        float p = __expf(s - mt);
        m = mt;
        l = l * corr + p;
        #pragma unroll
        for (int dd = 0; dd < 10; dd++) {
            float4 vv = *(const float4*)&Vs[j][dd * 4];
            a4[dd].x = a4[dd].x * corr + p * vv.x;
            a4[dd].y = a4[dd].y * corr + p * vv.y;
            a4[dd].z = a4[dd].z * corr + p * vv.z;
            a4[dd].w = a4[dd].w * corr + p * vv.w;
        }
    }
    float inv = 1.f / l;
    bf16* op = O + (size_t)qrow * D + h * DH;
    #pragma unroll
    for (int dd = 0; dd < 10; dd++) {
        *(uint32_t*)(op + dd * 4)     = bf2pk(a4[dd].x * inv, a4[dd].y * inv);
        *(uint32_t*)(op + dd * 4 + 2) = bf2pk(a4[dd].z * inv, a4[dd].w * inv);
    }
}

// ---------------- launch ----------------
extern "C" void kernel_launch(void* const* d_in, const int* in_sizes, int n_in,
                              void* d_out, int out_size) {
    const float* x      = (const float*)d_in[0];
    const float* ctx    = (const float*)d_in[1];
    const float* gn_w   = (const float*)d_in[2];
    const float* gn_b   = (const float*)d_in[3];
    const float* pin_w  = (const float*)d_in[4];
    const float* pin_b  = (const float*)d_in[5];
    const float* ln1_w  = (const float*)d_in[6];
    const float* ln1_b  = (const float*)d_in[7];
    const float* q1     = (const float*)d_in[8];
    const float* k1     = (const float*)d_in[9];
    const float* v1     = (const float*)d_in[10];
    const float* o1_w   = (const float*)d_in[11];
    const float* o1_b   = (const float*)d_in[12];
    const float* ln2_w  = (const float*)d_in[13];
    const float* ln2_b  = (const float*)d_in[14];
    const float* q2     = (const float*)d_in[15];
    const float* k2     = (const float*)d_in[16];
    const float* v2     = (const float*)d_in[17];
    const float* o2_w   = (const float*)d_in[18];
    const float* o2_b   = (const float*)d_in[19];
    const float* ln3_w  = (const float*)d_in[20];
    const float* ln3_b  = (const float*)d_in[21];
    const float* ff1_w  = (const float*)d_in[22];
    const float* ff1_b  = (const float*)d_in[23];
    const float* ff2_w  = (const float*)d_in[24];
    const float* ff2_b  = (const float*)d_in[25];
    const float* pout_w = (const float*)d_in[26];
    const float* pout_b = (const float*)d_in[27];
    float* out = (float*)d_out;

    float *p_h, *p_h2, *p_kvc;
    bf16 *p_lnb, *p_qkvb, *p_attnb, *p_q2b, *p_h2b, *p_ffgb, *p_ctxb;
    bf16 *p_wqkv, *p_wo1, *p_wq2, *p_wo2, *p_wff1, *p_wff2, *p_wpin, *p_wpout, *p_wkv2;
    cudaGetSymbolAddress((void**)&p_h,    g_h);
    cudaGetSymbolAddress((void**)&p_h2,   g_h2);
    cudaGetSymbolAddress((void**)&p_kvc,  g_kvc);
    cudaGetSymbolAddress((void**)&p_lnb,  g_lnb);
    cudaGetSymbolAddress((void**)&p_qkvb, g_qkvb);
    cudaGetSymbolAddress((void**)&p_attnb,g_attnb);
    cudaGetSymbolAddress((void**)&p_q2b,  g_q2b);
    cudaGetSymbolAddress((void**)&p_h2b,  g_h2b);
    cudaGetSymbolAddress((void**)&p_ffgb, g_ffgb);
    cudaGetSymbolAddress((void**)&p_ctxb, g_ctxb);
    cudaGetSymbolAddress((void**)&p_wqkv, g_wqkv);
    cudaGetSymbolAddress((void**)&p_wo1,  g_wo1);
    cudaGetSymbolAddress((void**)&p_wq2,  g_wq2);
    cudaGetSymbolAddress((void**)&p_wo2,  g_wo2);
    cudaGetSymbolAddress((void**)&p_wff1, g_wff1);
    cudaGetSymbolAddress((void**)&p_wff2, g_wff2);
    cudaGetSymbolAddress((void**)&p_wpin, g_wpin);
    cudaGetSymbolAddress((void**)&p_wpout,g_wpout);
    cudaGetSymbolAddress((void**)&p_wkv2, g_wkv2);

    dim3 gD(D / 64, N_TOK / 32);            // (5, 128)

    // weight prep (+ ctx conversion) + GroupNorm
    prep_weights_kernel<<<2768, 256>>>(q1, k1, v1, o1_w, q2, o2_w, ff1_w, ff2_w,
                                       pin_w, pout_w, k2, v2, ctx);
    gn_stats_kernel<<<GROUPS, 256>>>(x);
    gn_apply_t_kernel<<<dim3(32, 10), 256>>>(x, gn_w, gn_b, p_lnb);
    gemm_bf16_kernel<0><<<gD, 128>>>(p_lnb, p_wpin, pin_b, nullptr, p_h, nullptr, N_TOK, D, D);

    // self-attention
    layernorm_kernel<<<N_TOK, 128>>>(p_h, ln1_w, ln1_b, p_lnb);
    gemm_bf16_kernel<3><<<dim3(3 * D / 64, N_TOK / 32), 128>>>(p_lnb, p_wqkv, nullptr, nullptr, nullptr, p_qkvb, N_TOK, 3 * D, D);
    flash_bf16_kernel<<<dim3(N_TOK / 128, HEADS), 256>>>(p_qkvb, p_attnb);
    gemm_bf16_kernel<1><<<gD, 128>>>(p_attnb, p_wo1, o1_b, p_h, p_h2, nullptr, N_TOK, D, D);

    // cross-attention
    layernorm_kernel<<<N_TOK, 128>>>(p_h2, ln2_w, ln2_b, p_lnb);
    gemm_bf16_kernel<3><<<gD, 128>>>(p_lnb, p_wq2, nullptr, nullptr, nullptr, p_q2b, N_TOK, D, D);
    gemm_bf16_kernel<0><<<dim3(2 * D / 64, CTX_M / 32), 128>>>(p_ctxb, p_wkv2, nullptr, nullptr, p_kvc, nullptr, CTX_M, 2 * D, CTX_D);
    cross_attn_kernel<<<dim3(N_TOK / 128, HEADS), 128>>>(p_q2b, p_kvc, p_attnb);
    gemm_bf16_kernel<1><<<gD, 128>>>(p_attnb, p_wo2, o2_b, p_h2, p_h, nullptr, N_TOK, D, D);

    // GEGLU FF (fused into ff1 epilogue via interleaved weights)
    layernorm_kernel<<<N_TOK, 128>>>(p_h, ln3_w, ln3_b, p_lnb);
    gemm_bf16_kernel<5><<<dim3(2 * FFI / 64, N_TOK / 32), 128>>>(p_lnb, p_wff1, ff1_b, nullptr, nullptr, p_ffgb, N_TOK, 2 * FFI, D);
    gemm_bf16_kernel<4><<<gD, 128>>>(p_ffgb, p_wff2, ff2_b, p_h, p_h2, p_h2b, N_TOK, D, FFI);

    // proj_out + residual (transposed store back to [C][HW])
    gemm_bf16_kernel<2><<<gD, 128>>>(p_h2b, p_wpout, pout_b, x, out, nullptr, N_TOK, D, D);
}